// round 9
// baseline (speedup 1.0000x reference)
#include <cuda_runtime.h>
#include <math.h>

#define NN 10000
#define EE 160000
#define BB 64
#define DD 128
#define MM 32
#define EINN 321
#define H1 642
#define KK 5
#define FH 768
#define F2 256
#define FASTRIDE 644

// permuted column index: fragment pair (k, k+4) contiguous
#define PERM(k) (((k)&3)*18 + ((k)>>2))
#define RS 72   // row stride (mod 32 == 8 -> conflict-free with qc*18)

// ---------------- scratch (zero-initialized device globals) ----------------
__device__ float d_feats[NN*DD];
__device__ float d_eap[EE*RS];          // permuted tf32 edge attrs (sin/cos only)
__device__ float d_dcol[EE];            // fp32 squared distance per edge
__device__ float d_deg[NN];
__device__ float d_FA[NN*FASTRIDE + 256];
__device__ float d_FB[NN*FASTRIDE + 256];
__device__ float d_msum[NN*MM];
__device__ float d_xcat[NN*160];
__device__ float d_fcat[NN*FH];
__device__ float d_f1[NN*F2];
__device__ float d_f2[NN*F2];
__device__ float d_gsum[BB*F2];
__device__ float d_gcnt[BB];
__device__ float d_w1p[KK*11*64*RS];    // pre-permuted edge W1 chunks
__device__ float d_w2p[KK*11*32*RS];    // pre-permuted edge W2 chunks
__device__ float d_wfabp[KK*2*11*2*64*RS]; // pre-permuted FA/FB weights
__device__ float d_wf0p[4*12*64*RS];    // pre-permuted fW0
__device__ float d_wf1p[4*4*64*RS];     // pre-permuted fW1
__device__ float d_wf2p[4*4*64*RS];     // pre-permuted fW2

__device__ __forceinline__ float siluf(float x){
  return __fdividef(x, 1.f+__expf(-x));
}

__device__ __forceinline__ float tf32r(float x){
  float r; asm("cvt.rna.tf32.f32 %0,%1;" : "=f"(r) : "f"(x)); return r;
}
__device__ __forceinline__ void mma8(float4 &c, unsigned a0,unsigned a1,unsigned a2,unsigned a3,
                                     unsigned b0,unsigned b1){
  asm("mma.sync.aligned.m16n8k8.row.col.f32.tf32.tf32.f32 "
      "{%0,%1,%2,%3},{%4,%5,%6,%7},{%8,%9},{%0,%1,%2,%3};"
      : "+f"(c.x),"+f"(c.y),"+f"(c.z),"+f"(c.w)
      : "r"(a0),"r"(a1),"r"(a2),"r"(a3),"r"(b0),"r"(b1));
}

// ---------------- init / zero kernels ----------------
__global__ void k_zero_init(){
  int i = blockIdx.x*256+threadIdx.x;
  if(i<NN) d_deg[i]=0.f;
  if(i<BB*F2) d_gsum[i]=0.f;
  if(i<BB) d_gcnt[i]=0.f;
}
__global__ void k_zero_msum(){
  int i = blockIdx.x*256+threadIdx.x;
  d_msum[i]=0.f;
}
__global__ void k_feats(const float* __restrict__ emb, const int* __restrict__ atomids){
  int n=blockIdx.x; int c=threadIdx.x;
  float v=emb[atomids[n]*DD+c];
  d_feats[n*DD+c]=v;
  d_fcat[(size_t)n*FH+c]=v;
}
__global__ void k_deg(const int* __restrict__ eidx){
  int e=blockIdx.x*256+threadIdx.x;
  atomicAdd(&d_deg[eidx[EE+e]],1.f);
}
__global__ void k_ea(const float* __restrict__ coords, const int* __restrict__ eidx){
  int e=blockIdx.x*256+threadIdx.x;
  int s=eidx[e], t2=eidx[EE+e];
  float dx=coords[3*s]-coords[3*t2];
  float dy=coords[3*s+1]-coords[3*t2+1];
  float dz=coords[3*s+2]-coords[3*t2+2];
  float d=dx*dx+dy*dy+dz*dz;
  float* o=&d_eap[(size_t)e*RS];
  float x=d;
  #pragma unroll
  for(int i=0;i<32;i++){
    float sv,cv; __sincosf(x,&sv,&cv);
    o[PERM(i)]=tf32r(sv); o[PERM(32+i)]=tf32r(cv);
    x*=0.5f;
  }
  d_dcol[e]=d;
}

// ---------------- one-shot weight permutes ----------------
__global__ void k_wprep(const float* __restrict__ keW1, const float* __restrict__ keW2){
  int i = blockIdx.x*256+threadIdx.x;
  const int W1TOT = KK*11*64*64;
  const int W2TOT = KK*11*32*64;
  if(i < W1TOT){
    int kk=i&63; int n=(i>>6)&63; int ch=(i>>12)%11; int k=i/(64*64*11);
    int j=ch*64+n;
    float v = (j<H1)? tf32r(keW1[(size_t)k*EINN*H1 + (size_t)(256+kk)*H1 + j]) : 0.f;
    d_w1p[(size_t)(((k*11+ch)*64)+n)*RS + PERM(kk)] = v;
  } else if(i < W1TOT+W2TOT){
    int m=i-W1TOT;
    int kk=m&63; int n=(m>>6)&31; int ch=(m>>11)%11; int k=m/(32*64*11);
    int j=ch*64+kk;
    float v = (j<H1)? tf32r(keW2[(size_t)k*H1*MM + (size_t)j*MM + n]) : 0.f;
    d_w2p[(size_t)(((k*11+ch)*32)+n)*RS + PERM(kk)] = v;
  }
}

// FA/FB weights: keW1[k][part*128 + kc*64 + kk][ch*64+n]
__global__ void k_wprep_fab(const float* __restrict__ keW1){
  int i = blockIdx.x*256+threadIdx.x;   // total KK*2*11*2*64*64 = 901120
  int kk=i&63; int i2=i>>6;
  int n=i2&63; i2>>=6;
  int kc=i2&1; i2>>=1;
  int ch=i2%11; i2/=11;
  int part=i2&1; int k=i2>>1;
  int p = part*128 + kc*64 + kk;
  int j = ch*64 + n;
  float v = (j<H1)? tf32r(keW1[(size_t)k*EINN*H1 + (size_t)p*H1 + j]) : 0.f;
  d_wfabp[(size_t)((((k*2+part)*11+ch)*2+kc)*64 + n)*RS + PERM(kk)] = v;
}

// head weights: fW0 [768x256] (cc 4, kc 12), fW1/fW2 [256x256] (cc 4, kc 4)
__global__ void k_wprep_fnn(const float* __restrict__ fW0,
                            const float* __restrict__ fW1,
                            const float* __restrict__ fW2){
  int i = blockIdx.x*256+threadIdx.x;   // total 196608 + 65536 + 65536 = 327680
  if(i < 196608){
    int kk=i&63; int n=(i>>6)&63; int r=i>>12;   // 0..47
    int kc=r%12, cc=r/12;
    d_wf0p[(size_t)((cc*12+kc)*64+n)*RS + PERM(kk)] =
      tf32r(fW0[(size_t)(kc*64+kk)*F2 + cc*64+n]);
  } else if(i < 262144){
    int j=i-196608;
    int kk=j&63; int n=(j>>6)&63; int r=j>>12;   // 0..15
    int kc=r&3, cc=r>>2;
    d_wf1p[(size_t)((cc*4+kc)*64+n)*RS + PERM(kk)] =
      tf32r(fW1[(size_t)(kc*64+kk)*F2 + cc*64+n]);
  } else {
    int j=i-262144;
    int kk=j&63; int n=(j>>6)&63; int r=j>>12;
    int kc=r&3, cc=r>>2;
    d_wf2p[(size_t)((cc*4+kc)*64+n)*RS + PERM(kk)] =
      tf32r(fW2[(size_t)(kc*64+kk)*F2 + cc*64+n]);
  }
}

// ---------------- per-layer: FA/FB = feats @ W1[part] via tf32 MMA ----------------
// grid (11, 79, 2), 256 thr; block = 128 nodes x 64 cols, K=128 (2 chunks)
__global__ void __launch_bounds__(256,2) k_fab_mma(int k){
  extern __shared__ float sm[];
  float* s_f = sm;              // 2 planes of 128*72
  float* s_b = sm + 2*128*RS;   // 2 tiles of 64*72
  int tid=threadIdx.x;
  int ch=blockIdx.x, nb=blockIdx.y, part=blockIdx.z;
  int n0 = nb*128;
  // stage A (feats, permuted tf32)
  #pragma unroll
  for(int t=0;t<16;t++){
    int lin = tid + t*256;            // float4 index over [128][32]
    int r = lin>>5, c4 = (lin&31)*4;
    int n = n0 + r;
    float4 v = (n<NN)? *(const float4*)(d_feats + (size_t)n*DD + c4) : make_float4(0,0,0,0);
    int kc = c4>>6, cc = c4&63;
    float* dst = s_f + kc*(128*RS) + r*RS + (cc>>2);
    dst[0]=tf32r(v.x); dst[18]=tf32r(v.y); dst[36]=tf32r(v.z); dst[54]=tf32r(v.w);
  }
  // stage B (both K-chunks contiguous)
  {
    const float4* src = (const float4*)(d_wfabp + (size_t)(((k*2+part)*11+ch)*2)*(64*RS));
    float4* dst = (float4*)s_b;
    #pragma unroll
    for(int t=0;t<9;t++){ int i=tid+t*256; if(i<2304) dst[i]=src[i]; }
  }
  __syncthreads();
  int w=tid>>5, l=tid&31, qr=l>>2, qc=l&3;
  int ra=w*16+qr, rb=ra+8, aoff=qc*18;
  float4 c1[8];
  #pragma unroll
  for(int t=0;t<8;t++) c1[t]=make_float4(0,0,0,0);
  #pragma unroll
  for(int kc=0;kc<2;kc++){
    float* sa = s_f + kc*(128*RS);
    float* sb = s_b + kc*(64*RS);
    #pragma unroll
    for(int ks=0;ks<8;ks++){
      float2 A0=*(float2*)(sa+ra*RS+aoff+2*ks);
      float2 A1=*(float2*)(sa+rb*RS+aoff+2*ks);
      unsigned a0=__float_as_uint(A0.x), a2=__float_as_uint(A0.y);
      unsigned a1=__float_as_uint(A1.x), a3=__float_as_uint(A1.y);
      #pragma unroll
      for(int nt=0;nt<8;nt++){
        float2 Bv=*(float2*)(sb+(nt*8+qr)*RS+aoff+2*ks);
        mma8(c1[nt],a0,a1,a2,a3,__float_as_uint(Bv.x),__float_as_uint(Bv.y));
      }
    }
  }
  float* OUT = part? d_FB : d_FA;
  int na=n0+ra, nb2=n0+rb;
  #pragma unroll
  for(int nt=0;nt<8;nt++){
    int col = ch*64 + nt*8 + 2*qc;
    if(col<643){
      if(na<NN)  *(float2*)(OUT+(size_t)na*FASTRIDE+col)=make_float2(c1[nt].x,c1[nt].y);
      if(nb2<NN) *(float2*)(OUT+(size_t)nb2*FASTRIDE+col)=make_float2(c1[nt].z,c1[nt].w);
    }
  }
}

// ---------------- head MLP via tf32 MMA ----------------
// grid (2, 79), 256 thr; block = 128 nodes x 128 cols
// stage 0: silu(d_fcat) @ fW0 -> d_f1 (KC=12); stage 1: d_f1 @ fW1 -> d_f2; stage 2: d_f2 @ fW2 -> d_f1
__global__ void __launch_bounds__(256,2) k_fnn_mma(const float* __restrict__ bias, int stage){
  const float* Wp = (stage==0)? d_wf0p : ((stage==1)? d_wf1p : d_wf2p);
  const float* in = (stage==0)? d_fcat : ((stage==1)? d_f1 : d_f2);
  float* out      = (stage==1)? d_f2 : d_f1;
  int KC          = (stage==0)? 12 : 4;
  int dosilu      = (stage==0);
  extern __shared__ float sm[];
  float* s_a = sm;              // 128*72
  float* s_b = sm + 128*RS;     // 2 tiles of 64*72
  int tid=threadIdx.x;
  int n0 = blockIdx.y*128;
  int cc0 = blockIdx.x*2;
  int w=tid>>5, l=tid&31, qr=l>>2, qc=l&3;
  int ra=w*16+qr, rb=ra+8, aoff=qc*18;
  int INST = KC*64;
  float4 c1[16];
  #pragma unroll
  for(int t=0;t<16;t++) c1[t]=make_float4(0,0,0,0);
  for(int kc=0;kc<KC;kc++){
    __syncthreads();
    // stage A chunk
    #pragma unroll
    for(int t=0;t<8;t++){
      int lin=tid+t*256;             // float4 over [128][16]
      int r=lin>>4, c4=(lin&15)*4;
      int n=n0+r;
      float4 v = (n<NN)? *(const float4*)(in + (size_t)n*INST + kc*64 + c4) : make_float4(0,0,0,0);
      if(dosilu){ v.x=siluf(v.x); v.y=siluf(v.y); v.z=siluf(v.z); v.w=siluf(v.w); }
      float* dst = s_a + r*RS + (c4>>2);
      dst[0]=tf32r(v.x); dst[18]=tf32r(v.y); dst[36]=tf32r(v.z); dst[54]=tf32r(v.w);
    }
    // stage B (two 64-col tiles)
    {
      const float4* s0=(const float4*)(Wp + (size_t)(cc0*KC+kc)*(64*RS));
      const float4* s1=(const float4*)(Wp + (size_t)((cc0+1)*KC+kc)*(64*RS));
      float4* d0=(float4*)s_b;
      float4* d1=(float4*)(s_b+64*RS);
      #pragma unroll
      for(int t=0;t<5;t++){ int i=tid+t*256; if(i<1152){ d0[i]=s0[i]; d1[i]=s1[i]; } }
    }
    __syncthreads();
    #pragma unroll
    for(int ks=0;ks<8;ks++){
      float2 A0=*(float2*)(s_a+ra*RS+aoff+2*ks);
      float2 A1=*(float2*)(s_a+rb*RS+aoff+2*ks);
      unsigned a0=__float_as_uint(A0.x), a2=__float_as_uint(A0.y);
      unsigned a1=__float_as_uint(A1.x), a3=__float_as_uint(A1.y);
      #pragma unroll
      for(int nt=0;nt<16;nt++){
        float* sb = s_b + (nt>>3)*(64*RS);
        float2 Bv=*(float2*)(sb+((nt&7)*8+qr)*RS+aoff+2*ks);
        mma8(c1[nt],a0,a1,a2,a3,__float_as_uint(Bv.x),__float_as_uint(Bv.y));
      }
    }
  }
  int na=n0+ra, nb2=n0+rb;
  #pragma unroll
  for(int nt=0;nt<16;nt++){
    int col = cc0*64 + nt*8 + 2*qc;
    float b0=__ldg(&bias[col]), b1=__ldg(&bias[col+1]);
    if(na<NN)  *(float2*)(out+(size_t)na*F2+col)=make_float2(siluf(c1[nt].x+b0),siluf(c1[nt].y+b1));
    if(nb2<NN) *(float2*)(out+(size_t)nb2*F2+col)=make_float2(siluf(c1[nt].z+b0),siluf(c1[nt].w+b1));
  }
}

// ---------------- per-layer: fused edge MLP via tf32 MMA + LN + scatter ----------------
// grid 1250, 256 thr (8 warps); block = 128 edges
__global__ void __launch_bounds__(256,2) k_edge(const int* __restrict__ eidx,
   const float* __restrict__ keW1,const float* __restrict__ keb1,
   const float* __restrict__ keb2,
   const float* __restrict__ keng,const float* __restrict__ kenb,int k){
  extern __shared__ float sm[];
  float* s_ea = sm;                    // 128*RS
  float* s_w1 = s_ea + 128*RS;         // 64*RS
  float* s_h  = s_w1 + 64*RS;          // 128*RS
  float* s_w2 = s_h  + 128*RS;         // 32*RS
  float* s_w1d= s_w2 + 32*RS;          // 64  (d-row of W1 chunk)
  float* s_d  = s_w1d + 64;            // 128 (d per edge)
  float* s_b1 = s_d + 128;             // 64
  float* s_b2 = s_b1 + 64;             // 32
  float* s_g  = s_b2 + 32;             // 32
  float* s_bt = s_g + 32;              // 32
  int* s_dst = (int*)(s_bt+32);        // 128
  int* s_src = s_dst + 128;            // 128
  int tid=threadIdx.x;
  int e0=blockIdx.x*128;
  {
    const float4* src=(const float4*)(d_eap + (size_t)e0*RS);
    float4* dst=(float4*)s_ea;
    #pragma unroll
    for(int i=0;i<9;i++) dst[tid+256*i]=src[tid+256*i];
  }
  if(tid<128){ s_dst[tid]=eidx[EE+e0+tid]; s_src[tid]=eidx[e0+tid];
               s_d[tid]=d_dcol[e0+tid]; }
  if(tid>=128 && tid<160){ int c=tid-128; s_b2[c]=keb2[k*MM+c]; s_g[c]=keng[k*MM+c]; s_bt[c]=kenb[k*MM+c]; }
  const float* W1c = keW1 + (size_t)k*EINN*H1 + (size_t)256*H1;
  const float* B1  = keb1 + (size_t)k*H1;

  int w=tid>>5, l=tid&31, qr=l>>2, qc=l&3;
  int ra=w*16+qr, rb=ra+8;
  int aoff=qc*18;

  float4 c2[4];
  #pragma unroll
  for(int t=0;t<4;t++) c2[t]=make_float4(0.f,0.f,0.f,0.f);

  for(int ch=0; ch<11; ch++){
    int jc0=ch*64;
    __syncthreads();
    {
      const float4* w1src=(const float4*)(d_w1p + (size_t)((k*11+ch)*64)*RS);
      float4* w1dst=(float4*)s_w1;
      #pragma unroll
      for(int i=0;i<4;i++) w1dst[tid+256*i]=w1src[tid+256*i];
      if(tid<128) w1dst[tid+1024]=w1src[tid+1024];
      const float4* w2src=(const float4*)(d_w2p + (size_t)((k*11+ch)*32)*RS);
      float4* w2dst=(float4*)s_w2;
      #pragma unroll
      for(int i=0;i<2;i++) w2dst[tid+256*i]=w2src[tid+256*i];
      if(tid<64) w2dst[tid+512]=w2src[tid+512];
      if(tid<64){ int j=jc0+tid; s_b1[tid]=(j<H1)?B1[j]:0.f;
                  s_w1d[tid]=(j<H1)? W1c[(size_t)64*H1+j] : 0.f; }
    }
    __syncthreads();

    float4 c1[8];
    #pragma unroll
    for(int t=0;t<8;t++) c1[t]=make_float4(0.f,0.f,0.f,0.f);
    #pragma unroll
    for(int ks=0;ks<8;ks++){
      float2 A0=*(float2*)(s_ea+ra*RS+aoff+2*ks);
      float2 A1=*(float2*)(s_ea+rb*RS+aoff+2*ks);
      unsigned a0=__float_as_uint(A0.x), a2=__float_as_uint(A0.y);
      unsigned a1=__float_as_uint(A1.x), a3=__float_as_uint(A1.y);
      #pragma unroll
      for(int nt=0;nt<8;nt++){
        float2 Bv=*(float2*)(s_w1+(nt*8+qr)*RS+aoff+2*ks);
        mma8(c1[nt],a0,a1,a2,a3,__float_as_uint(Bv.x),__float_as_uint(Bv.y));
      }
    }
    {
      int nda=s_dst[ra], nsa=s_src[ra], ndb=s_dst[rb], nsb=s_src[rb];
      float da=s_d[ra], db=s_d[rb];
      const float* FAa=d_FA+(size_t)nda*FASTRIDE+jc0;
      const float* FBa=d_FB+(size_t)nsa*FASTRIDE+jc0;
      const float* FAb=d_FA+(size_t)ndb*FASTRIDE+jc0;
      const float* FBb=d_FB+(size_t)nsb*FASTRIDE+jc0;
      #pragma unroll
      for(int nt=0;nt<8;nt++){
        int col0=nt*8+2*qc;
        float2 faa=*(const float2*)(FAa+col0);
        float2 fba=*(const float2*)(FBa+col0);
        float2 fab=*(const float2*)(FAb+col0);
        float2 fbb=*(const float2*)(FBb+col0);
        float b0=s_b1[col0], b1f=s_b1[col0+1];
        float w0=s_w1d[col0], w1v=s_w1d[col0+1];
        int p0=((col0&3)*18) + (col0>>2);
        s_h[ra*RS+p0]   =tf32r(siluf(c1[nt].x+b0 +da*w0 +faa.x+fba.x));
        s_h[ra*RS+p0+18]=tf32r(siluf(c1[nt].y+b1f+da*w1v+faa.y+fba.y));
        s_h[rb*RS+p0]   =tf32r(siluf(c1[nt].z+b0 +db*w0 +fab.x+fbb.x));
        s_h[rb*RS+p0+18]=tf32r(siluf(c1[nt].w+b1f+db*w1v+fab.y+fbb.y));
      }
    }
    __syncthreads();
    #pragma unroll
    for(int ks=0;ks<8;ks++){
      float2 A0=*(float2*)(s_h+ra*RS+aoff+2*ks);
      float2 A1=*(float2*)(s_h+rb*RS+aoff+2*ks);
      unsigned a0=__float_as_uint(A0.x), a2=__float_as_uint(A0.y);
      unsigned a1=__float_as_uint(A1.x), a3=__float_as_uint(A1.y);
      #pragma unroll
      for(int nt=0;nt<4;nt++){
        float2 Bv=*(float2*)(s_w2+(nt*8+qr)*RS+aoff+2*ks);
        mma8(c2[nt],a0,a1,a2,a3,__float_as_uint(Bv.x),__float_as_uint(Bv.y));
      }
    }
  }
  float va[8], vb[8];
  #pragma unroll
  for(int nt=0;nt<4;nt++){
    int col0=nt*8+2*qc;
    va[2*nt]  =siluf(c2[nt].x+s_b2[col0]);
    va[2*nt+1]=siluf(c2[nt].y+s_b2[col0+1]);
    vb[2*nt]  =siluf(c2[nt].z+s_b2[col0]);
    vb[2*nt+1]=siluf(c2[nt].w+s_b2[col0+1]);
  }
  float sa=0.f,ssa=0.f,sb=0.f,ssb=0.f;
  #pragma unroll
  for(int i=0;i<8;i++){ sa+=va[i]; ssa+=va[i]*va[i]; sb+=vb[i]; ssb+=vb[i]*vb[i]; }
  #pragma unroll
  for(int o=1;o<4;o<<=1){
    sa+=__shfl_xor_sync(0xffffffffu,sa,o); ssa+=__shfl_xor_sync(0xffffffffu,ssa,o);
    sb+=__shfl_xor_sync(0xffffffffu,sb,o); ssb+=__shfl_xor_sync(0xffffffffu,ssb,o);
  }
  float mua=sa*(1.f/MM), vara=ssa*(1.f/MM)-mua*mua, inva=rsqrtf(vara+1e-5f);
  float mub=sb*(1.f/MM), varb=ssb*(1.f/MM)-mub*mub, invb=rsqrtf(varb+1e-5f);
  float* pa=&d_msum[(size_t)s_dst[ra]*MM];
  float* pb=&d_msum[(size_t)s_dst[rb]*MM];
  #pragma unroll
  for(int nt=0;nt<4;nt++){
    int col0=nt*8+2*qc;
    atomicAdd(pa+col0,  (va[2*nt]  -mua)*inva*s_g[col0]  +s_bt[col0]);
    atomicAdd(pa+col0+1,(va[2*nt+1]-mua)*inva*s_g[col0+1]+s_bt[col0+1]);
    atomicAdd(pb+col0,  (vb[2*nt]  -mub)*invb*s_g[col0]  +s_bt[col0]);
    atomicAdd(pb+col0+1,(vb[2*nt+1]-mub)*invb*s_g[col0+1]+s_bt[col0+1]);
  }
}

// ---------------- per-layer: xcat = [LN(feats) | LN(msum/deg)] ----------------
__global__ void k_xcat(const float* __restrict__ keng,const float* __restrict__ kenb,
                       const float* __restrict__ kn1g,const float* __restrict__ kn1b,int k){
  int warp=threadIdx.x>>5, lane=threadIdx.x&31;
  int n=blockIdx.x*8+warp;
  const float* g1=kn1g+(size_t)k*128; const float* b1=kn1b+(size_t)k*128;
  float v[4],s=0.f,ss=0.f;
  #pragma unroll
  for(int i=0;i<4;i++){ float x=d_feats[(size_t)n*128+lane+32*i]; v[i]=x; s+=x; ss+=x*x; }
  #pragma unroll
  for(int o=16;o;o>>=1){ s+=__shfl_xor_sync(0xffffffffu,s,o); ss+=__shfl_xor_sync(0xffffffffu,ss,o); }
  float mu=s*(1.f/128), var=ss*(1.f/128)-mu*mu, inv=rsqrtf(var+1e-5f);
  #pragma unroll
  for(int i=0;i<4;i++){ int c=lane+32*i; d_xcat[(size_t)n*160+c]=(v[i]-mu)*inv*g1[c]+b1[c]; }
  float m=d_msum[(size_t)n*MM+lane]/fmaxf(d_deg[n],1.f);
  float s2=m, ss2=m*m;
  #pragma unroll
  for(int o=16;o;o>>=1){ s2+=__shfl_xor_sync(0xffffffffu,s2,o); ss2+=__shfl_xor_sync(0xffffffffu,ss2,o); }
  float mu2=s2*(1.f/MM), var2=ss2*(1.f/MM)-mu2*mu2, inv2=rsqrtf(var2+1e-5f);
  d_xcat[(size_t)n*160+128+lane]=(m-mu2)*inv2*keng[k*MM+lane]+kenb[k*MM+lane];
}

// ---------------- per-layer: fused node MLP + LN + residual (fp32 scalar) ----------------
__global__ void __launch_bounds__(256) k_node(const float* __restrict__ knW1,const float* __restrict__ knb1,
    const float* __restrict__ knW2,const float* __restrict__ knb2,
    const float* __restrict__ kn2g,const float* __restrict__ kn2b,int k){
  extern __shared__ float sm[];
  float* s_x=sm;            // 64*161=10304
  float* s_h=s_x+10304;     // 64*257=16448
  float* s_w=s_h+16448;     // 256*64=16384
  int tid=threadIdx.x;
  int n0=blockIdx.x*64;
  const float* W1=knW1+(size_t)k*160*256;
  const float* B1=knb1+(size_t)k*256;
  const float* W2=knW2+(size_t)k*256*128;
  const float* B2=knb2+(size_t)k*128;
  const float* G =kn2g+(size_t)k*128;
  const float* BT=kn2b+(size_t)k*128;
  for(int i=tid;i<64*160;i+=256){int r=i/160,c=i-r*160;int n=n0+r; s_x[r*161+c]= (n<NN)? d_xcat[(size_t)n*160+c]:0.f;}
  int r0=(tid>>4)*4, c0=(tid&15)*4;
  for(int oc=0;oc<4;oc++){
    __syncthreads();
    for(int i=tid;i<160*64;i+=256){int p=i>>6,c=i&63; s_w[i]=W1[(size_t)p*256+oc*64+c];}
    __syncthreads();
    float a4[4][4];
    #pragma unroll
    for(int i=0;i<4;i++){a4[i][0]=0;a4[i][1]=0;a4[i][2]=0;a4[i][3]=0;}
    for(int p=0;p<160;p++){
      float4 w=*(float4*)(s_w+p*64+c0);
      #pragma unroll
      for(int i=0;i<4;i++){ float a=s_x[(r0+i)*161+p];
        a4[i][0]+=a*w.x; a4[i][1]+=a*w.y; a4[i][2]+=a*w.z; a4[i][3]+=a*w.w; }
    }
    #pragma unroll
    for(int i=0;i<4;i++){
      #pragma unroll
      for(int j=0;j<4;j++){ int col=oc*64+c0+j;
        s_h[(r0+i)*257+col]=siluf(a4[i][j]+__ldg(&B1[col])); }
    }
  }
  __syncthreads();
  for(int oc=0;oc<2;oc++){
    if(oc) __syncthreads();
    for(int i=tid;i<256*64;i+=256){int p=i>>6,c=i&63; s_w[i]=W2[(size_t)p*128+oc*64+c];}
    __syncthreads();
    float a4[4][4];
    #pragma unroll
    for(int i=0;i<4;i++){a4[i][0]=0;a4[i][1]=0;a4[i][2]=0;a4[i][3]=0;}
    for(int p=0;p<256;p++){
      float4 w=*(float4*)(s_w+p*64+c0);
      #pragma unroll
      for(int i=0;i<4;i++){ float a=s_h[(r0+i)*257+p];
        a4[i][0]+=a*w.x; a4[i][1]+=a*w.y; a4[i][2]+=a*w.z; a4[i][3]+=a*w.w; }
    }
    #pragma unroll
    for(int i=0;i<4;i++){
      #pragma unroll
      for(int j=0;j<4;j++){ int col=oc*64+c0+j;
        s_x[(r0+i)*129+col]=a4[i][j]+__ldg(&B2[col]); }
    }
  }
  __syncthreads();
  int w=tid>>5, lane=tid&31;
  for(int rr=w; rr<64; rr+=8){
    int n=n0+rr;
    float v[4],s=0.f,ss=0.f;
    #pragma unroll
    for(int i=0;i<4;i++){ float x=s_x[rr*129+lane+32*i]; v[i]=x; s+=x; ss+=x*x; }
    #pragma unroll
    for(int o=16;o;o>>=1){ s+=__shfl_xor_sync(0xffffffffu,s,o); ss+=__shfl_xor_sync(0xffffffffu,ss,o); }
    float mu=s*(1.f/128), var=ss*(1.f/128)-mu*mu, inv=rsqrtf(var+1e-5f);
    if(n<NN){
      #pragma unroll
      for(int i=0;i<4;i++){ int c=lane+32*i;
        float nv=(v[i]-mu)*inv*G[c]+BT[c];
        float f=d_feats[(size_t)n*128+c]+nv;
        d_feats[(size_t)n*128+c]=f;
        d_fcat[(size_t)n*FH+(size_t)(k+1)*128+c]=f; }
    }
  }
}

__global__ void k_pool(const int* __restrict__ batch){
  int n=blockIdx.x; int c=threadIdx.x;
  int b=batch[n];
  atomicAdd(&d_gsum[b*F2+c], d_f1[(size_t)n*F2+c]);
  if(c==0) atomicAdd(&d_gcnt[b],1.f);
}

__global__ void k_final(const float* __restrict__ gW0,const float* __restrict__ gb0,
                        const float* __restrict__ gW1,const float* __restrict__ gb1,
                        const float* __restrict__ gW2,const float* __restrict__ gb2,
                        float* __restrict__ out){
  __shared__ float s_g[256], s_h[256], s_red[8];
  int b=blockIdx.x, t=threadIdx.x;
  float cnt=fmaxf(d_gcnt[b],1.f);
  s_g[t]=d_gsum[b*F2+t]/cnt;
  __syncthreads();
  float a=gb0[t];
  #pragma unroll 8
  for(int p=0;p<256;p++) a+=s_g[p]*gW0[p*256+t];
  s_h[t]=siluf(a);
  __syncthreads();
  a=gb1[t];
  #pragma unroll 8
  for(int p=0;p<256;p++) a+=s_h[p]*gW1[p*256+t];
  float h=siluf(a);
  float v=h*gW2[t];
  #pragma unroll
  for(int o=16;o;o>>=1) v+=__shfl_xor_sync(0xffffffffu,v,o);
  if((t&31)==0) s_red[t>>5]=v;
  __syncthreads();
  if(t==0){ float tot=0.f;
    #pragma unroll
    for(int i=0;i<8;i++) tot+=s_red[i];
    out[b]=tot+gb2[0]; }
}

// ---------------- host ----------------
extern "C" void kernel_launch(void* const* d_in, const int* in_sizes, int n_in,
                              void* d_out, int out_size){
  const float* coords =(const float*)d_in[0];
  const int*   atomids=(const int*)d_in[1];
  const int*   eidx   =(const int*)d_in[2];
  const int*   batch  =(const int*)d_in[3];
  int s = (in_sizes[4]==11*DD) ? 4 : 5;   // skip num_graphs scalar if present
  const float* emb =(const float*)d_in[s+0];
  const float* keW1=(const float*)d_in[s+1];
  const float* keb1=(const float*)d_in[s+2];
  const float* keW2=(const float*)d_in[s+3];
  const float* keb2=(const float*)d_in[s+4];
  const float* keng=(const float*)d_in[s+5];
  const float* kenb=(const float*)d_in[s+6];
  const float* kn1g=(const float*)d_in[s+7];
  const float* kn1b=(const float*)d_in[s+8];
  const float* knW1=(const float*)d_in[s+9];
  const float* knb1=(const float*)d_in[s+10];
  const float* knW2=(const float*)d_in[s+11];
  const float* knb2=(const float*)d_in[s+12];
  const float* kn2g=(const float*)d_in[s+13];
  const float* kn2b=(const float*)d_in[s+14];
  const float* fW0 =(const float*)d_in[s+15];
  const float* fb0 =(const float*)d_in[s+16];
  const float* fW1 =(const float*)d_in[s+17];
  const float* fb1 =(const float*)d_in[s+18];
  const float* fW2 =(const float*)d_in[s+19];
  const float* fb2 =(const float*)d_in[s+20];
  const float* gW0 =(const float*)d_in[s+21];
  const float* gb0 =(const float*)d_in[s+22];
  const float* gW1 =(const float*)d_in[s+23];
  const float* gb1 =(const float*)d_in[s+24];
  const float* gW2 =(const float*)d_in[s+25];
  const float* gb2 =(const float*)d_in[s+26];
  float* out=(float*)d_out;

  const int EDGE_SM = (352*RS + 64 + 128 + 64 + 96 + 256)*4;      // 103808
  const int NODE_SM = (10304+16448+16384)*4;                      // 172544
  const int FAB_SM  = (2*128*RS + 2*64*RS)*4;                     // 110592
  const int FNN_SM  = (128*RS + 2*64*RS)*4;                       // 73728
  cudaFuncSetAttribute(k_edge,    cudaFuncAttributeMaxDynamicSharedMemorySize, EDGE_SM);
  cudaFuncSetAttribute(k_node,    cudaFuncAttributeMaxDynamicSharedMemorySize, NODE_SM);
  cudaFuncSetAttribute(k_fab_mma, cudaFuncAttributeMaxDynamicSharedMemorySize, FAB_SM);
  cudaFuncSetAttribute(k_fnn_mma, cudaFuncAttributeMaxDynamicSharedMemorySize, FNN_SM);

  k_zero_init<<<65,256>>>();
  k_feats<<<NN,128>>>(emb,atomids);
  k_deg<<<EE/256,256>>>(eidx);
  k_ea<<<EE/256,256>>>(coords,eidx);
  k_wprep<<<1320,256>>>(keW1,keW2);
  k_wprep_fab<<<3520,256>>>(keW1);      // 901120 elems
  k_wprep_fnn<<<1280,256>>>(fW0,fW1,fW2); // 327680 elems
  for(int k=0;k<KK;k++){
    k_zero_msum<<<(NN*MM)/256,256>>>();
    k_fab_mma<<<dim3(11,79,2),256,FAB_SM>>>(k);
    k_edge<<<EE/128,256,EDGE_SM>>>(eidx,keW1,keb1,keb2,keng,kenb,k);
    k_xcat<<<NN/8,256>>>(keng,kenb,kn1g,kn1b,k);
    k_node<<<157,256,NODE_SM>>>(knW1,knb1,knW2,knb2,kn2g,kn2b,k);
  }
  k_fnn_mma<<<dim3(2,79),256,FNN_SM>>>(fb0, 0);
  k_fnn_mma<<<dim3(2,79),256,FNN_SM>>>(fb1, 1);
  k_fnn_mma<<<dim3(2,79),256,FNN_SM>>>(fb2, 2);
  k_pool<<<NN,256>>>(batch);
  k_final<<<BB,256>>>(gW0,gb0,gW1,gb1,gW2,gb2,out);
}

// round 11
// speedup vs baseline: 1.2008x; 1.2008x over previous
#include <cuda_runtime.h>
#include <stdint.h>
#include <math.h>

#define NN 10000
#define EE 160000
#define BB 64
#define DD 128
#define MM 32
#define EINN 321
#define H1 642
#define KK 5
#define FH 768
#define F2 256
#define FASTRIDE 644

#define PERM(k) (((k)&3)*18 + ((k)>>2))
#define RS 72

__device__ float d_feats[NN*DD];
__device__ float d_eap[EE*RS];
__device__ float d_dcol[EE];
__device__ float d_deg[NN];
__device__ float d_FA[NN*FASTRIDE + 256];
__device__ float d_FB[NN*FASTRIDE + 256];
__device__ float d_msum[NN*MM];
__device__ float d_xcat[NN*160];
__device__ float d_fcat[NN*FH];
__device__ float d_f1[NN*F2];
__device__ float d_f2[NN*F2];
__device__ float d_gsum[BB*F2];
__device__ float d_gcnt[BB];
__device__ float d_w1p[KK*11*64*RS];
__device__ float d_w2p[KK*11*32*RS];
__device__ float d_wfabp[KK*2*11*2*64*RS];
__device__ float d_wf0p[4*12*64*RS];
__device__ float d_wf1p[4*4*64*RS];
__device__ float d_wf2p[4*4*64*RS];

__device__ __forceinline__ float siluf(float x){
  return __fdividef(x, 1.f+__expf(-x));
}
__device__ __forceinline__ float tf32r(float x){
  float r; asm("cvt.rna.tf32.f32 %0,%1;" : "=f"(r) : "f"(x)); return r;
}
__device__ __forceinline__ void mma8(float4 &c, unsigned a0,unsigned a1,unsigned a2,unsigned a3,
                                     unsigned b0,unsigned b1){
  asm("mma.sync.aligned.m16n8k8.row.col.f32.tf32.tf32.f32 "
      "{%0,%1,%2,%3},{%4,%5,%6,%7},{%8,%9},{%0,%1,%2,%3};"
      : "+f"(c.x),"+f"(c.y),"+f"(c.z),"+f"(c.w)
      : "r"(a0),"r"(a1),"r"(a2),"r"(a3),"r"(b0),"r"(b1));
}
__device__ __forceinline__ uint32_t s2u(const void* p){
  uint32_t a; asm("{ .reg .u64 t; cvta.to.shared.u64 t, %1; cvt.u32.u64 %0, t; }" : "=r"(a) : "l"(p)); return a;
}
__device__ __forceinline__ void cpa(uint32_t s, const void* g){
  asm volatile("cp.async.cg.shared.global [%0], [%1], 16;"::"r"(s),"l"(g):"memory");
}
#define CPA_COMMIT() asm volatile("cp.async.commit_group;":::"memory")
#define CPA_WAIT0()  asm volatile("cp.async.wait_group 0;":::"memory")

__global__ void k_zero_init(){
  int i = blockIdx.x*256+threadIdx.x;
  if(i<NN) d_deg[i]=0.f;
  if(i<BB*F2) d_gsum[i]=0.f;
  if(i<BB) d_gcnt[i]=0.f;
}
__global__ void k_feats(const float* __restrict__ emb, const int* __restrict__ atomids){
  int n=blockIdx.x; int c=threadIdx.x;
  float v=emb[atomids[n]*DD+c];
  d_feats[n*DD+c]=v;
  d_fcat[(size_t)n*FH+c]=v;
}
__global__ void k_deg(const int* __restrict__ eidx){
  int e=blockIdx.x*256+threadIdx.x;
  atomicAdd(&d_deg[eidx[EE+e]],1.f);
}
__global__ void k_ea(const float* __restrict__ coords, const int* __restrict__ eidx){
  int e=blockIdx.x*256+threadIdx.x;
  int s=eidx[e], t2=eidx[EE+e];
  float dx=coords[3*s]-coords[3*t2];
  float dy=coords[3*s+1]-coords[3*t2+1];
  float dz=coords[3*s+2]-coords[3*t2+2];
  float d=dx*dx+dy*dy+dz*dz;
  float* o=&d_eap[(size_t)e*RS];
  float x=d;
  #pragma unroll
  for(int i=0;i<32;i++){
    float sv,cv; __sincosf(x,&sv,&cv);
    o[PERM(i)]=tf32r(sv); o[PERM(32+i)]=tf32r(cv);
    x*=0.5f;
  }
  d_dcol[e]=d;
}

__global__ void k_wprep(const float* __restrict__ keW1, const float* __restrict__ keW2){
  int i = blockIdx.x*256+threadIdx.x;
  const int W1TOT = KK*11*64*64;
  const int W2TOT = KK*11*32*64;
  if(i < W1TOT){
    int kk=i&63; int n=(i>>6)&63; int ch=(i>>12)%11; int k=i/(64*64*11);
    int j=ch*64+n;
    float v = (j<H1)? tf32r(keW1[(size_t)k*EINN*H1 + (size_t)(256+kk)*H1 + j]) : 0.f;
    d_w1p[(size_t)(((k*11+ch)*64)+n)*RS + PERM(kk)] = v;
  } else if(i < W1TOT+W2TOT){
    int m=i-W1TOT;
    int kk=m&63; int n=(m>>6)&31; int ch=(m>>11)%11; int k=m/(32*64*11);
    int j=ch*64+kk;
    float v = (j<H1)? tf32r(keW2[(size_t)k*H1*MM + (size_t)j*MM + n]) : 0.f;
    d_w2p[(size_t)(((k*11+ch)*32)+n)*RS + PERM(kk)] = v;
  }
}
__global__ void k_wprep_fab(const float* __restrict__ keW1){
  int i = blockIdx.x*256+threadIdx.x;
  int kk=i&63; int i2=i>>6;
  int n=i2&63; i2>>=6;
  int kc=i2&1; i2>>=1;
  int ch=i2%11; i2/=11;
  int part=i2&1; int k=i2>>1;
  int p = part*128 + kc*64 + kk;
  int j = ch*64 + n;
  float v = (j<H1)? tf32r(keW1[(size_t)k*EINN*H1 + (size_t)p*H1 + j]) : 0.f;
  d_wfabp[(size_t)((((k*2+part)*11+ch)*2+kc)*64 + n)*RS + PERM(kk)] = v;
}
__global__ void k_wprep_fnn(const float* __restrict__ fW0,
                            const float* __restrict__ fW1,
                            const float* __restrict__ fW2){
  int i = blockIdx.x*256+threadIdx.x;
  if(i < 196608){
    int kk=i&63; int n=(i>>6)&63; int r=i>>12;
    int kc=r%12, cc=r/12;
    d_wf0p[(size_t)((cc*12+kc)*64+n)*RS + PERM(kk)] =
      tf32r(fW0[(size_t)(kc*64+kk)*F2 + cc*64+n]);
  } else if(i < 262144){
    int j=i-196608;
    int kk=j&63; int n=(j>>6)&63; int r=j>>12;
    int kc=r&3, cc=r>>2;
    d_wf1p[(size_t)((cc*4+kc)*64+n)*RS + PERM(kk)] =
      tf32r(fW1[(size_t)(kc*64+kk)*F2 + cc*64+n]);
  } else {
    int j=i-262144;
    int kk=j&63; int n=(j>>6)&63; int r=j>>12;
    int kc=r&3, cc=r>>2;
    d_wf2p[(size_t)((cc*4+kc)*64+n)*RS + PERM(kk)] =
      tf32r(fW2[(size_t)(kc*64+kk)*F2 + cc*64+n]);
  }
}

// FA/FB via HMMA; also zeroes d_msum for the following k_edge
__global__ void __launch_bounds__(256,2) k_fab_mma(int k){
  extern __shared__ float sm[];
  float* s_f = sm;
  float* s_b = sm + 2*128*RS;
  int tid=threadIdx.x;
  { int gi=(blockIdx.x+11*(blockIdx.y+79*(int)blockIdx.z))*256+tid;
    if(gi<NN*MM) d_msum[gi]=0.f; }
  int ch=blockIdx.x, nb=blockIdx.y, part=blockIdx.z;
  int n0 = nb*128;
  #pragma unroll
  for(int t=0;t<16;t++){
    int lin = tid + t*256;
    int r = lin>>5, c4 = (lin&31)*4;
    int n = n0 + r;
    float4 v = (n<NN)? *(const float4*)(d_feats + (size_t)n*DD + c4) : make_float4(0,0,0,0);
    int kc = c4>>6, cc = c4&63;
    float* dst = s_f + kc*(128*RS) + r*RS + (cc>>2);
    dst[0]=tf32r(v.x); dst[18]=tf32r(v.y); dst[36]=tf32r(v.z); dst[54]=tf32r(v.w);
  }
  {
    const float4* src = (const float4*)(d_wfabp + (size_t)(((k*2+part)*11+ch)*2)*(64*RS));
    float4* dst = (float4*)s_b;
    #pragma unroll
    for(int t=0;t<9;t++){ int i=tid+t*256; if(i<2304) dst[i]=src[i]; }
  }
  __syncthreads();
  int w=tid>>5, l=tid&31, qr=l>>2, qc=l&3;
  int ra=w*16+qr, rb=ra+8, aoff=qc*18;
  float4 c1[8];
  #pragma unroll
  for(int t=0;t<8;t++) c1[t]=make_float4(0,0,0,0);
  #pragma unroll
  for(int kc=0;kc<2;kc++){
    float* sa = s_f + kc*(128*RS);
    float* sb = s_b + kc*(64*RS);
    #pragma unroll
    for(int ks=0;ks<8;ks++){
      float2 A0=*(float2*)(sa+ra*RS+aoff+2*ks);
      float2 A1=*(float2*)(sa+rb*RS+aoff+2*ks);
      unsigned a0=__float_as_uint(A0.x), a2=__float_as_uint(A0.y);
      unsigned a1=__float_as_uint(A1.x), a3=__float_as_uint(A1.y);
      #pragma unroll
      for(int nt=0;nt<8;nt++){
        float2 Bv=*(float2*)(sb+(nt*8+qr)*RS+aoff+2*ks);
        mma8(c1[nt],a0,a1,a2,a3,__float_as_uint(Bv.x),__float_as_uint(Bv.y));
      }
    }
  }
  float* OUT = part? d_FB : d_FA;
  int na=n0+ra, nb2=n0+rb;
  #pragma unroll
  for(int nt=0;nt<8;nt++){
    int col = ch*64 + nt*8 + 2*qc;
    if(col<643){
      if(na<NN)  *(float2*)(OUT+(size_t)na*FASTRIDE+col)=make_float2(c1[nt].x,c1[nt].y);
      if(nb2<NN) *(float2*)(OUT+(size_t)nb2*FASTRIDE+col)=make_float2(c1[nt].z,c1[nt].w);
    }
  }
}

__global__ void __launch_bounds__(256,2) k_fnn_mma(const float* __restrict__ bias, int stage){
  const float* Wp = (stage==0)? d_wf0p : ((stage==1)? d_wf1p : d_wf2p);
  const float* in = (stage==0)? d_fcat : ((stage==1)? d_f1 : d_f2);
  float* out      = (stage==1)? d_f2 : d_f1;
  int KC          = (stage==0)? 12 : 4;
  int dosilu      = (stage==0);
  extern __shared__ float sm[];
  float* s_a = sm;
  float* s_b = sm + 128*RS;
  int tid=threadIdx.x;
  int n0 = blockIdx.y*128;
  int cc0 = blockIdx.x*2;
  int w=tid>>5, l=tid&31, qr=l>>2, qc=l&3;
  int ra=w*16+qr, rb=ra+8, aoff=qc*18;
  int INST = KC*64;
  float4 c1[16];
  #pragma unroll
  for(int t=0;t<16;t++) c1[t]=make_float4(0,0,0,0);
  for(int kc=0;kc<KC;kc++){
    __syncthreads();
    #pragma unroll
    for(int t=0;t<8;t++){
      int lin=tid+t*256;
      int r=lin>>4, c4=(lin&15)*4;
      int n=n0+r;
      float4 v = (n<NN)? *(const float4*)(in + (size_t)n*INST + kc*64 + c4) : make_float4(0,0,0,0);
      if(dosilu){ v.x=siluf(v.x); v.y=siluf(v.y); v.z=siluf(v.z); v.w=siluf(v.w); }
      float* dst = s_a + r*RS + (c4>>2);
      dst[0]=tf32r(v.x); dst[18]=tf32r(v.y); dst[36]=tf32r(v.z); dst[54]=tf32r(v.w);
    }
    {
      const float4* s0=(const float4*)(Wp + (size_t)(cc0*KC+kc)*(64*RS));
      const float4* s1=(const float4*)(Wp + (size_t)((cc0+1)*KC+kc)*(64*RS));
      float4* d0=(float4*)s_b;
      float4* d1=(float4*)(s_b+64*RS);
      #pragma unroll
      for(int t=0;t<5;t++){ int i=tid+t*256; if(i<1152){ d0[i]=s0[i]; d1[i]=s1[i]; } }
    }
    __syncthreads();
    #pragma unroll
    for(int ks=0;ks<8;ks++){
      float2 A0=*(float2*)(s_a+ra*RS+aoff+2*ks);
      float2 A1=*(float2*)(s_a+rb*RS+aoff+2*ks);
      unsigned a0=__float_as_uint(A0.x), a2=__float_as_uint(A0.y);
      unsigned a1=__float_as_uint(A1.x), a3=__float_as_uint(A1.y);
      #pragma unroll
      for(int nt=0;nt<16;nt++){
        float* sb = s_b + (nt>>3)*(64*RS);
        float2 Bv=*(float2*)(sb+((nt&7)*8+qr)*RS+aoff+2*ks);
        mma8(c1[nt],a0,a1,a2,a3,__float_as_uint(Bv.x),__float_as_uint(Bv.y));
      }
    }
  }
  int na=n0+ra, nb2=n0+rb;
  #pragma unroll
  for(int nt=0;nt<16;nt++){
    int col = cc0*64 + nt*8 + 2*qc;
    float b0=__ldg(&bias[col]), b1=__ldg(&bias[col+1]);
    if(na<NN)  *(float2*)(out+(size_t)na*F2+col)=make_float2(siluf(c1[nt].x+b0),siluf(c1[nt].y+b1));
    if(nb2<NN) *(float2*)(out+(size_t)nb2*F2+col)=make_float2(siluf(c1[nt].z+b0),siluf(c1[nt].w+b1));
  }
}

// ---------- edge MLP: regs-A, cp.async double-buffered weights, 1 sync/chunk ----------
__global__ void __launch_bounds__(256,2) k_edge(const int* __restrict__ eidx,
   const float* __restrict__ keW1,const float* __restrict__ keb1,
   const float* __restrict__ keb2,
   const float* __restrict__ keng,const float* __restrict__ kenb,int k){
  extern __shared__ float sm[];
  float* s_h  = sm;                    // 128*72 = 9216
  float* s_w1 = sm + 9216;             // 2 x 4608
  float* s_w2 = sm + 18432;            // 2 x 2304
  float* s_w1d= sm + 23040;            // 2 x 64
  float* s_b1 = sm + 23168;            // 2 x 64
  float* s_b2 = sm + 23296;
  float* s_g  = sm + 23328;
  float* s_bt = sm + 23360;
  int tid=threadIdx.x, w=tid>>5, l=tid&31, qr=l>>2, qc=l&3;
  int e0=blockIdx.x*128;
  int ra=w*16+qr, rb=ra+8, aoff=qc*18;
  uint32_t sbu=s2u(sm);
  const float* W1c = keW1 + (size_t)k*EINN*H1 + (size_t)256*H1;
  const float* B1  = keb1 + (size_t)k*H1;
  float2 eA[8], eB[8];
  {
    const float* pA=d_eap+(size_t)(e0+ra)*RS+aoff;
    const float* pB=d_eap+(size_t)(e0+rb)*RS+aoff;
    #pragma unroll
    for(int ks=0;ks<8;ks++){ eA[ks]=*(const float2*)(pA+2*ks); eB[ks]=*(const float2*)(pB+2*ks); }
  }
  int nda=eidx[EE+e0+ra], nsa=eidx[e0+ra];
  int ndb=eidx[EE+e0+rb], nsb=eidx[e0+rb];
  float da=d_dcol[e0+ra], db=d_dcol[e0+rb];
  if(tid<32){ s_b2[tid]=keb2[k*MM+tid]; s_g[tid]=keng[k*MM+tid]; s_bt[tid]=kenb[k*MM+tid]; }

  auto stage=[&](int ch,int buf){
    const float4* w1s=(const float4*)(d_w1p + (size_t)((k*11+ch)*64)*RS);
    uint32_t w1a = sbu + (9216+buf*4608)*4;
    #pragma unroll
    for(int i=0;i<4;i++) cpa(w1a+(tid+256*i)*16, w1s+tid+256*i);
    if(tid<128) cpa(w1a+(1024+tid)*16, w1s+1024+tid);
    const float4* w2s=(const float4*)(d_w2p + (size_t)((k*11+ch)*32)*RS);
    uint32_t w2a = sbu + (18432+buf*2304)*4;
    #pragma unroll
    for(int i=0;i<2;i++) cpa(w2a+(tid+256*i)*16, w2s+tid+256*i);
    if(tid<64){
      cpa(w2a+(512+tid)*16, w2s+512+tid);
      int j=ch*64+tid;
      s_b1[buf*64+tid]=(j<H1)?B1[j]:0.f;
      s_w1d[buf*64+tid]=(j<H1)? W1c[(size_t)64*H1+j] : 0.f;
    }
  };
  stage(0,0); CPA_COMMIT();

  float4 c2[4];
  #pragma unroll
  for(int t=0;t<4;t++) c2[t]=make_float4(0.f,0.f,0.f,0.f);

  for(int ch=0; ch<11; ch++){
    int buf=ch&1;
    CPA_WAIT0();
    __syncthreads();
    if(ch<10){ stage(ch+1,1-buf); CPA_COMMIT(); }
    float* w1b = s_w1 + buf*4608;
    float* w2b = s_w2 + buf*2304;
    float* b1b = s_b1 + buf*64;
    float* wdb = s_w1d + buf*64;
    int jc0=ch*64;
    float4 c1[8];
    #pragma unroll
    for(int t=0;t<8;t++) c1[t]=make_float4(0.f,0.f,0.f,0.f);
    #pragma unroll
    for(int ks=0;ks<8;ks++){
      unsigned a0=__float_as_uint(eA[ks].x), a2=__float_as_uint(eA[ks].y);
      unsigned a1=__float_as_uint(eB[ks].x), a3=__float_as_uint(eB[ks].y);
      #pragma unroll
      for(int nt=0;nt<8;nt++){
        float2 Bv=*(float2*)(w1b+(nt*8+qr)*RS+aoff+2*ks);
        mma8(c1[nt],a0,a1,a2,a3,__float_as_uint(Bv.x),__float_as_uint(Bv.y));
      }
    }
    {
      const float* FAa=d_FA+(size_t)nda*FASTRIDE+jc0;
      const float* FBa=d_FB+(size_t)nsa*FASTRIDE+jc0;
      const float* FAb=d_FA+(size_t)ndb*FASTRIDE+jc0;
      const float* FBb=d_FB+(size_t)nsb*FASTRIDE+jc0;
      #pragma unroll
      for(int nt=0;nt<8;nt++){
        int col0=nt*8+2*qc;
        float2 faa=*(const float2*)(FAa+col0);
        float2 fba=*(const float2*)(FBa+col0);
        float2 fab=*(const float2*)(FAb+col0);
        float2 fbb=*(const float2*)(FBb+col0);
        float b0=b1b[col0], b1f=b1b[col0+1];
        float w0=wdb[col0], w1v=wdb[col0+1];
        int p0=((col0&3)*18) + (col0>>2);
        s_h[ra*RS+p0]   =tf32r(siluf(c1[nt].x+b0 +da*w0 +faa.x+fba.x));
        s_h[ra*RS+p0+18]=tf32r(siluf(c1[nt].y+b1f+da*w1v+faa.y+fba.y));
        s_h[rb*RS+p0]   =tf32r(siluf(c1[nt].z+b0 +db*w0 +fab.x+fbb.x));
        s_h[rb*RS+p0+18]=tf32r(siluf(c1[nt].w+b1f+db*w1v+fab.y+fbb.y));
      }
    }
    __syncwarp();
    #pragma unroll
    for(int ks=0;ks<8;ks++){
      float2 A0=*(float2*)(s_h+ra*RS+aoff+2*ks);
      float2 A1=*(float2*)(s_h+rb*RS+aoff+2*ks);
      unsigned a0=__float_as_uint(A0.x), a2=__float_as_uint(A0.y);
      unsigned a1=__float_as_uint(A1.x), a3=__float_as_uint(A1.y);
      #pragma unroll
      for(int nt=0;nt<4;nt++){
        float2 Bv=*(float2*)(w2b+(nt*8+qr)*RS+aoff+2*ks);
        mma8(c2[nt],a0,a1,a2,a3,__float_as_uint(Bv.x),__float_as_uint(Bv.y));
      }
    }
  }
  float va[8], vb[8];
  #pragma unroll
  for(int nt=0;nt<4;nt++){
    int col0=nt*8+2*qc;
    va[2*nt]  =siluf(c2[nt].x+s_b2[col0]);
    va[2*nt+1]=siluf(c2[nt].y+s_b2[col0+1]);
    vb[2*nt]  =siluf(c2[nt].z+s_b2[col0]);
    vb[2*nt+1]=siluf(c2[nt].w+s_b2[col0+1]);
  }
  float sa=0.f,ssa=0.f,sb=0.f,ssb=0.f;
  #pragma unroll
  for(int i=0;i<8;i++){ sa+=va[i]; ssa+=va[i]*va[i]; sb+=vb[i]; ssb+=vb[i]*vb[i]; }
  #pragma unroll
  for(int o=1;o<4;o<<=1){
    sa+=__shfl_xor_sync(0xffffffffu,sa,o); ssa+=__shfl_xor_sync(0xffffffffu,ssa,o);
    sb+=__shfl_xor_sync(0xffffffffu,sb,o); ssb+=__shfl_xor_sync(0xffffffffu,ssb,o);
  }
  float mua=sa*(1.f/MM), vara=ssa*(1.f/MM)-mua*mua, inva=rsqrtf(vara+1e-5f);
  float mub=sb*(1.f/MM), varb=ssb*(1.f/MM)-mub*mub, invb=rsqrtf(varb+1e-5f);
  float* pa=&d_msum[(size_t)nda*MM];
  float* pb=&d_msum[(size_t)ndb*MM];
  #pragma unroll
  for(int nt=0;nt<4;nt++){
    int col0=nt*8+2*qc;
    atomicAdd(pa+col0,  (va[2*nt]  -mua)*inva*s_g[col0]  +s_bt[col0]);
    atomicAdd(pa+col0+1,(va[2*nt+1]-mua)*inva*s_g[col0+1]+s_bt[col0+1]);
    atomicAdd(pb+col0,  (vb[2*nt]  -mub)*invb*s_g[col0]  +s_bt[col0]);
    atomicAdd(pb+col0+1,(vb[2*nt+1]-mub)*invb*s_g[col0+1]+s_bt[col0+1]);
  }
}

__global__ void k_xcat(const float* __restrict__ keng,const float* __restrict__ kenb,
                       const float* __restrict__ kn1g,const float* __restrict__ kn1b,int k){
  int warp=threadIdx.x>>5, lane=threadIdx.x&31;
  int n=blockIdx.x*8+warp;
  const float* g1=kn1g+(size_t)k*128; const float* b1=kn1b+(size_t)k*128;
  float v[4],s=0.f,ss=0.f;
  #pragma unroll
  for(int i=0;i<4;i++){ float x=d_feats[(size_t)n*128+lane+32*i]; v[i]=x; s+=x; ss+=x*x; }
  #pragma unroll
  for(int o=16;o;o>>=1){ s+=__shfl_xor_sync(0xffffffffu,s,o); ss+=__shfl_xor_sync(0xffffffffu,ss,o); }
  float mu=s*(1.f/128), var=ss*(1.f/128)-mu*mu, inv=rsqrtf(var+1e-5f);
  #pragma unroll
  for(int i=0;i<4;i++){ int c=lane+32*i; d_xcat[(size_t)n*160+c]=(v[i]-mu)*inv*g1[c]+b1[c]; }
  float m=d_msum[(size_t)n*MM+lane]/fmaxf(d_deg[n],1.f);
  float s2=m, ss2=m*m;
  #pragma unroll
  for(int o=16;o;o>>=1){ s2+=__shfl_xor_sync(0xffffffffu,s2,o); ss2+=__shfl_xor_sync(0xffffffffu,ss2,o); }
  float mu2=s2*(1.f/MM), var2=ss2*(1.f/MM)-mu2*mu2, inv2=rsqrtf(var2+1e-5f);
  d_xcat[(size_t)n*160+128+lane]=(m-mu2)*inv2*keng[k*MM+lane]+kenb[k*MM+lane];
}

__global__ void __launch_bounds__(256) k_node(const float* __restrict__ knW1,const float* __restrict__ knb1,
    const float* __restrict__ knW2,const float* __restrict__ knb2,
    const float* __restrict__ kn2g,const float* __restrict__ kn2b,int k){
  extern __shared__ float sm[];
  float* s_x=sm;
  float* s_h=s_x+10304;
  float* s_w=s_h+16448;
  int tid=threadIdx.x;
  int n0=blockIdx.x*64;
  const float* W1=knW1+(size_t)k*160*256;
  const float* B1=knb1+(size_t)k*256;
  const float* W2=knW2+(size_t)k*256*128;
  const float* B2=knb2+(size_t)k*128;
  const float* G =kn2g+(size_t)k*128;
  const float* BT=kn2b+(size_t)k*128;
  for(int i=tid;i<64*160;i+=256){int r=i/160,c=i-r*160;int n=n0+r; s_x[r*161+c]= (n<NN)? d_xcat[(size_t)n*160+c]:0.f;}
  int r0=(tid>>4)*4, c0=(tid&15)*4;
  for(int oc=0;oc<4;oc++){
    __syncthreads();
    for(int i=tid;i<160*64;i+=256){int p=i>>6,c=i&63; s_w[i]=W1[(size_t)p*256+oc*64+c];}
    __syncthreads();
    float a4[4][4];
    #pragma unroll
    for(int i=0;i<4;i++){a4[i][0]=0;a4[i][1]=0;a4[i][2]=0;a4[i][3]=0;}
    for(int p=0;p<160;p++){
      float4 w=*(float4*)(s_w+p*64+c0);
      #pragma unroll
      for(int i=0;i<4;i++){ float a=s_x[(r0+i)*161+p];
        a4[i][0]+=a*w.x; a4[i][1]+=a*w.y; a4[i][2]+=a*w.z; a4[i][3]+=a*w.w; }
    }
    #pragma unroll
    for(int i=0;i<4;i++){
      #pragma unroll
      for(int j=0;j<4;j++){ int col=oc*64+c0+j;
        s_h[(r0+i)*257+col]=siluf(a4[i][j]+__ldg(&B1[col])); }
    }
  }
  __syncthreads();
  for(int oc=0;oc<2;oc++){
    if(oc) __syncthreads();
    for(int i=tid;i<256*64;i+=256){int p=i>>6,c=i&63; s_w[i]=W2[(size_t)p*128+oc*64+c];}
    __syncthreads();
    float a4[4][4];
    #pragma unroll
    for(int i=0;i<4;i++){a4[i][0]=0;a4[i][1]=0;a4[i][2]=0;a4[i][3]=0;}
    for(int p=0;p<256;p++){
      float4 w=*(float4*)(s_w+p*64+c0);
      #pragma unroll
      for(int i=0;i<4;i++){ float a=s_h[(r0+i)*257+p];
        a4[i][0]+=a*w.x; a4[i][1]+=a*w.y; a4[i][2]+=a*w.z; a4[i][3]+=a*w.w; }
    }
    #pragma unroll
    for(int i=0;i<4;i++){
      #pragma unroll
      for(int j=0;j<4;j++){ int col=oc*64+c0+j;
        s_x[(r0+i)*129+col]=a4[i][j]+__ldg(&B2[col]); }
    }
  }
  __syncthreads();
  int w=tid>>5, lane=tid&31;
  for(int rr=w; rr<64; rr+=8){
    int n=n0+rr;
    float v[4],s=0.f,ss=0.f;
    #pragma unroll
    for(int i=0;i<4;i++){ float x=s_x[rr*129+lane+32*i]; v[i]=x; s+=x; ss+=x*x; }
    #pragma unroll
    for(int o=16;o;o>>=1){ s+=__shfl_xor_sync(0xffffffffu,s,o); ss+=__shfl_xor_sync(0xffffffffu,ss,o); }
    float mu=s*(1.f/128), var=ss*(1.f/128)-mu*mu, inv=rsqrtf(var+1e-5f);
    if(n<NN){
      #pragma unroll
      for(int i=0;i<4;i++){ int c=lane+32*i;
        float nv=(v[i]-mu)*inv*G[c]+BT[c];
        float f=d_feats[(size_t)n*128+c]+nv;
        d_feats[(size_t)n*128+c]=f;
        d_fcat[(size_t)n*FH+(size_t)(k+1)*128+c]=f; }
    }
  }
}

__global__ void k_pool(const int* __restrict__ batch){
  int n=blockIdx.x; int c=threadIdx.x;
  int b=batch[n];
  atomicAdd(&d_gsum[b*F2+c], d_f1[(size_t)n*F2+c]);
  if(c==0) atomicAdd(&d_gcnt[b],1.f);
}

__global__ void k_final(const float* __restrict__ gW0,const float* __restrict__ gb0,
                        const float* __restrict__ gW1,const float* __restrict__ gb1,
                        const float* __restrict__ gW2,const float* __restrict__ gb2,
                        float* __restrict__ out){
  __shared__ float s_g[256], s_h[256], s_red[8];
  int b=blockIdx.x, t=threadIdx.x;
  float cnt=fmaxf(d_gcnt[b],1.f);
  s_g[t]=d_gsum[b*F2+t]/cnt;
  __syncthreads();
  float a=gb0[t];
  #pragma unroll 8
  for(int p=0;p<256;p++) a+=s_g[p]*gW0[p*256+t];
  s_h[t]=siluf(a);
  __syncthreads();
  a=gb1[t];
  #pragma unroll 8
  for(int p=0;p<256;p++) a+=s_h[p]*gW1[p*256+t];
  float h=siluf(a);
  float v=h*gW2[t];
  #pragma unroll
  for(int o=16;o;o>>=1) v+=__shfl_xor_sync(0xffffffffu,v,o);
  if((t&31)==0) s_red[t>>5]=v;
  __syncthreads();
  if(t==0){ float tot=0.f;
    #pragma unroll
    for(int i=0;i<8;i++) tot+=s_red[i];
    out[b]=tot+gb2[0]; }
}

extern "C" void kernel_launch(void* const* d_in, const int* in_sizes, int n_in,
                              void* d_out, int out_size){
  const float* coords =(const float*)d_in[0];
  const int*   atomids=(const int*)d_in[1];
  const int*   eidx   =(const int*)d_in[2];
  const int*   batch  =(const int*)d_in[3];
  int s = (in_sizes[4]==11*DD) ? 4 : 5;
  const float* emb =(const float*)d_in[s+0];
  const float* keW1=(const float*)d_in[s+1];
  const float* keb1=(const float*)d_in[s+2];
  const float* keW2=(const float*)d_in[s+3];
  const float* keb2=(const float*)d_in[s+4];
  const float* keng=(const float*)d_in[s+5];
  const float* kenb=(const float*)d_in[s+6];
  const float* kn1g=(const float*)d_in[s+7];
  const float* kn1b=(const float*)d_in[s+8];
  const float* knW1=(const float*)d_in[s+9];
  const float* knb1=(const float*)d_in[s+10];
  const float* knW2=(const float*)d_in[s+11];
  const float* knb2=(const float*)d_in[s+12];
  const float* kn2g=(const float*)d_in[s+13];
  const float* kn2b=(const float*)d_in[s+14];
  const float* fW0 =(const float*)d_in[s+15];
  const float* fb0 =(const float*)d_in[s+16];
  const float* fW1 =(const float*)d_in[s+17];
  const float* fb1 =(const float*)d_in[s+18];
  const float* fW2 =(const float*)d_in[s+19];
  const float* fb2 =(const float*)d_in[s+20];
  const float* gW0 =(const float*)d_in[s+21];
  const float* gb0 =(const float*)d_in[s+22];
  const float* gW1 =(const float*)d_in[s+23];
  const float* gb1 =(const float*)d_in[s+24];
  const float* gW2 =(const float*)d_in[s+25];
  const float* gb2 =(const float*)d_in[s+26];
  float* out=(float*)d_out;

  const int EDGE_SM = 23392*4;                 // 93568
  const int NODE_SM = (10304+16448+16384)*4;   // 172544
  const int FAB_SM  = (2*128*RS + 2*64*RS)*4;  // 110592
  const int FNN_SM  = (128*RS + 2*64*RS)*4;    // 73728
  cudaFuncSetAttribute(k_edge,    cudaFuncAttributeMaxDynamicSharedMemorySize, EDGE_SM);
  cudaFuncSetAttribute(k_node,    cudaFuncAttributeMaxDynamicSharedMemorySize, NODE_SM);
  cudaFuncSetAttribute(k_fab_mma, cudaFuncAttributeMaxDynamicSharedMemorySize, FAB_SM);
  cudaFuncSetAttribute(k_fnn_mma, cudaFuncAttributeMaxDynamicSharedMemorySize, FNN_SM);

  k_zero_init<<<65,256>>>();
  k_feats<<<NN,128>>>(emb,atomids);
  k_deg<<<EE/256,256>>>(eidx);
  k_ea<<<EE/256,256>>>(coords,eidx);
  k_wprep<<<1320,256>>>(keW1,keW2);
  k_wprep_fab<<<3520,256>>>(keW1);
  k_wprep_fnn<<<1280,256>>>(fW0,fW1,fW2);
  for(int k=0;k<KK;k++){
    k_fab_mma<<<dim3(11,79,2),256,FAB_SM>>>(k);
    k_edge<<<EE/128,256,EDGE_SM>>>(eidx,keW1,keb1,keb2,keng,kenb,k);
    k_xcat<<<NN/8,256>>>(keng,kenb,kn1g,kn1b,k);
    k_node<<<157,256,NODE_SM>>>(knW1,knb1,knW2,knb2,kn2g,kn2b,k);
  }
  k_fnn_mma<<<dim3(2,79),256,FNN_SM>>>(fb0, 0);
  k_fnn_mma<<<dim3(2,79),256,FNN_SM>>>(fb1, 1);
  k_fnn_mma<<<dim3(2,79),256,FNN_SM>>>(fb2, 2);
  k_pool<<<NN,256>>>(batch);
  k_final<<<BB,256>>>(gW0,gb0,gW1,gb1,gW2,gb2,out);
}

// round 13
// speedup vs baseline: 1.2532x; 1.0436x over previous
#include <cuda_runtime.h>
#include <stdint.h>
#include <math.h>

#define NN 10000
#define EE 160000
#define BB 64
#define DD 128
#define MM 32
#define EINN 321
#define H1 642
#define KK 5
#define FH 768
#define F2 256
#define FASTRIDE 644

#define PERM(k) (((k)&3)*18 + ((k)>>2))
#define RS 72

__device__ float d_feats[NN*DD];
__device__ float d_eap[EE*RS];
__device__ float d_dcol[EE];
__device__ float d_deg[NN];
__device__ float d_FA[NN*FASTRIDE + 256];
__device__ float d_FB[NN*FASTRIDE + 256];
__device__ float d_msum[NN*MM];
__device__ float d_xcat[NN*160];
__device__ float d_fcat[NN*FH];
__device__ float d_f1[NN*F2];
__device__ float d_f2[NN*F2];
__device__ float d_gsum[BB*F2];
__device__ float d_gcnt[BB];
__device__ float d_w1p[KK*11*64*RS];
__device__ float d_w2p[KK*11*32*RS];
__device__ float d_wfabp[KK*2*11*2*64*RS];
__device__ float d_wf0p[4*12*64*RS];
__device__ float d_wf1p[4*4*64*RS];
__device__ float d_wf2p[4*4*64*RS];

__device__ __forceinline__ float siluf(float x){
  return __fdividef(x, 1.f+__expf(-x));
}
__device__ __forceinline__ float tf32r(float x){
  float r; asm("cvt.rna.tf32.f32 %0,%1;" : "=f"(r) : "f"(x)); return r;
}
__device__ __forceinline__ void mma8(float4 &c, unsigned a0,unsigned a1,unsigned a2,unsigned a3,
                                     unsigned b0,unsigned b1){
  asm("mma.sync.aligned.m16n8k8.row.col.f32.tf32.tf32.f32 "
      "{%0,%1,%2,%3},{%4,%5,%6,%7},{%8,%9},{%0,%1,%2,%3};"
      : "+f"(c.x),"+f"(c.y),"+f"(c.z),"+f"(c.w)
      : "r"(a0),"r"(a1),"r"(a2),"r"(a3),"r"(b0),"r"(b1));
}
__device__ __forceinline__ uint32_t s2u(const void* p){
  uint32_t a; asm("{ .reg .u64 t; cvta.to.shared.u64 t, %1; cvt.u32.u64 %0, t; }" : "=r"(a) : "l"(p)); return a;
}
__device__ __forceinline__ void cpa(uint32_t s, const void* g){
  asm volatile("cp.async.cg.shared.global [%0], [%1], 16;"::"r"(s),"l"(g):"memory");
}
#define CPA_COMMIT() asm volatile("cp.async.commit_group;":::"memory")
#define CPA_WAIT0()  asm volatile("cp.async.wait_group 0;":::"memory")

__global__ void k_zero_init(){
  int i = blockIdx.x*256+threadIdx.x;
  if(i<NN) d_deg[i]=0.f;
  if(i<BB*F2) d_gsum[i]=0.f;
  if(i<BB) d_gcnt[i]=0.f;
}
__global__ void k_feats(const float* __restrict__ emb, const int* __restrict__ atomids){
  int n=blockIdx.x; int c=threadIdx.x;
  float v=emb[atomids[n]*DD+c];
  d_feats[n*DD+c]=v;
  d_fcat[(size_t)n*FH+c]=v;
}
__global__ void k_deg(const int* __restrict__ eidx){
  int e=blockIdx.x*256+threadIdx.x;
  atomicAdd(&d_deg[eidx[EE+e]],1.f);
}
__global__ void k_ea(const float* __restrict__ coords, const int* __restrict__ eidx){
  int e=blockIdx.x*256+threadIdx.x;
  int s=eidx[e], t2=eidx[EE+e];
  float dx=coords[3*s]-coords[3*t2];
  float dy=coords[3*s+1]-coords[3*t2+1];
  float dz=coords[3*s+2]-coords[3*t2+2];
  float d=dx*dx+dy*dy+dz*dz;
  float* o=&d_eap[(size_t)e*RS];
  float x=d;
  #pragma unroll
  for(int i=0;i<32;i++){
    float sv,cv; __sincosf(x,&sv,&cv);
    o[PERM(i)]=tf32r(sv); o[PERM(32+i)]=tf32r(cv);
    x*=0.5f;
  }
  d_dcol[e]=d;
}

__global__ void k_wprep(const float* __restrict__ keW1, const float* __restrict__ keW2){
  int i = blockIdx.x*256+threadIdx.x;
  const int W1TOT = KK*11*64*64;
  const int W2TOT = KK*11*32*64;
  if(i < W1TOT){
    int kk=i&63; int n=(i>>6)&63; int ch=(i>>12)%11; int k=i/(64*64*11);
    int j=ch*64+n;
    float v = (j<H1)? tf32r(keW1[(size_t)k*EINN*H1 + (size_t)(256+kk)*H1 + j]) : 0.f;
    d_w1p[(size_t)(((k*11+ch)*64)+n)*RS + PERM(kk)] = v;
  } else if(i < W1TOT+W2TOT){
    int m=i-W1TOT;
    int kk=m&63; int n=(m>>6)&31; int ch=(m>>11)%11; int k=m/(32*64*11);
    int j=ch*64+kk;
    float v = (j<H1)? tf32r(keW2[(size_t)k*H1*MM + (size_t)j*MM + n]) : 0.f;
    d_w2p[(size_t)(((k*11+ch)*32)+n)*RS + PERM(kk)] = v;
  }
}
__global__ void k_wprep_fab(const float* __restrict__ keW1){
  int i = blockIdx.x*256+threadIdx.x;
  int kk=i&63; int i2=i>>6;
  int n=i2&63; i2>>=6;
  int kc=i2&1; i2>>=1;
  int ch=i2%11; i2/=11;
  int part=i2&1; int k=i2>>1;
  int p = part*128 + kc*64 + kk;
  int j = ch*64 + n;
  float v = (j<H1)? tf32r(keW1[(size_t)k*EINN*H1 + (size_t)p*H1 + j]) : 0.f;
  d_wfabp[(size_t)((((k*2+part)*11+ch)*2+kc)*64 + n)*RS + PERM(kk)] = v;
}
__global__ void k_wprep_fnn(const float* __restrict__ fW0,
                            const float* __restrict__ fW1,
                            const float* __restrict__ fW2){
  int i = blockIdx.x*256+threadIdx.x;
  if(i < 196608){
    int kk=i&63; int n=(i>>6)&63; int r=i>>12;
    int kc=r%12, cc=r/12;
    d_wf0p[(size_t)((cc*12+kc)*64+n)*RS + PERM(kk)] =
      tf32r(fW0[(size_t)(kc*64+kk)*F2 + cc*64+n]);
  } else if(i < 262144){
    int j=i-196608;
    int kk=j&63; int n=(j>>6)&63; int r=j>>12;
    int kc=r&3, cc=r>>2;
    d_wf1p[(size_t)((cc*4+kc)*64+n)*RS + PERM(kk)] =
      tf32r(fW1[(size_t)(kc*64+kk)*F2 + cc*64+n]);
  } else {
    int j=i-262144;
    int kk=j&63; int n=(j>>6)&63; int r=j>>12;
    int kc=r&3, cc=r>>2;
    d_wf2p[(size_t)((cc*4+kc)*64+n)*RS + PERM(kk)] =
      tf32r(fW2[(size_t)(kc*64+kk)*F2 + cc*64+n]);
  }
}

// FA/FB via HMMA; also zeroes d_msum
__global__ void __launch_bounds__(256,2) k_fab_mma(int k){
  extern __shared__ float sm[];
  float* s_f = sm;
  float* s_b = sm + 2*128*RS;
  int tid=threadIdx.x;
  { int gi=(blockIdx.x+11*(blockIdx.y+79*(int)blockIdx.z))*256+tid;
    if(gi<NN*MM) d_msum[gi]=0.f; }
  int ch=blockIdx.x, nb=blockIdx.y, part=blockIdx.z;
  int n0 = nb*128;
  #pragma unroll
  for(int t=0;t<16;t++){
    int lin = tid + t*256;
    int r = lin>>5, c4 = (lin&31)*4;
    int n = n0 + r;
    float4 v = (n<NN)? *(const float4*)(d_feats + (size_t)n*DD + c4) : make_float4(0,0,0,0);
    int kc = c4>>6, cc = c4&63;
    float* dst = s_f + kc*(128*RS) + r*RS + (cc>>2);
    dst[0]=tf32r(v.x); dst[18]=tf32r(v.y); dst[36]=tf32r(v.z); dst[54]=tf32r(v.w);
  }
  {
    const float4* src = (const float4*)(d_wfabp + (size_t)(((k*2+part)*11+ch)*2)*(64*RS));
    float4* dst = (float4*)s_b;
    #pragma unroll
    for(int t=0;t<9;t++){ int i=tid+t*256; if(i<2304) dst[i]=src[i]; }
  }
  __syncthreads();
  int w=tid>>5, l=tid&31, qr=l>>2, qc=l&3;
  int ra=w*16+qr, rb=ra+8, aoff=qc*18;
  float4 c1[8];
  #pragma unroll
  for(int t=0;t<8;t++) c1[t]=make_float4(0,0,0,0);
  #pragma unroll
  for(int kc=0;kc<2;kc++){
    float* sa = s_f + kc*(128*RS);
    float* sb = s_b + kc*(64*RS);
    #pragma unroll
    for(int ks=0;ks<8;ks++){
      float2 A0=*(float2*)(sa+ra*RS+aoff+2*ks);
      float2 A1=*(float2*)(sa+rb*RS+aoff+2*ks);
      unsigned a0=__float_as_uint(A0.x), a2=__float_as_uint(A0.y);
      unsigned a1=__float_as_uint(A1.x), a3=__float_as_uint(A1.y);
      #pragma unroll
      for(int nt=0;nt<8;nt++){
        float2 Bv=*(float2*)(sb+(nt*8+qr)*RS+aoff+2*ks);
        mma8(c1[nt],a0,a1,a2,a3,__float_as_uint(Bv.x),__float_as_uint(Bv.y));
      }
    }
  }
  float* OUT = part? d_FB : d_FA;
  int na=n0+ra, nb2=n0+rb;
  #pragma unroll
  for(int nt=0;nt<8;nt++){
    int col = ch*64 + nt*8 + 2*qc;
    if(col<643){
      if(na<NN)  *(float2*)(OUT+(size_t)na*FASTRIDE+col)=make_float2(c1[nt].x,c1[nt].y);
      if(nb2<NN) *(float2*)(OUT+(size_t)nb2*FASTRIDE+col)=make_float2(c1[nt].z,c1[nt].w);
    }
  }
}

__global__ void __launch_bounds__(256,2) k_fnn_mma(const float* __restrict__ bias, int stage){
  const float* Wp = (stage==0)? d_wf0p : ((stage==1)? d_wf1p : d_wf2p);
  const float* in = (stage==0)? d_fcat : ((stage==1)? d_f1 : d_f2);
  float* out      = (stage==1)? d_f2 : d_f1;
  int KC          = (stage==0)? 12 : 4;
  int dosilu      = (stage==0);
  extern __shared__ float sm[];
  float* s_a = sm;
  float* s_b = sm + 128*RS;
  int tid=threadIdx.x;
  int n0 = blockIdx.y*128;
  int cc0 = blockIdx.x*2;
  int w=tid>>5, l=tid&31, qr=l>>2, qc=l&3;
  int ra=w*16+qr, rb=ra+8, aoff=qc*18;
  int INST = KC*64;
  float4 c1[16];
  #pragma unroll
  for(int t=0;t<16;t++) c1[t]=make_float4(0,0,0,0);
  for(int kc=0;kc<KC;kc++){
    __syncthreads();
    #pragma unroll
    for(int t=0;t<8;t++){
      int lin=tid+t*256;
      int r=lin>>4, c4=(lin&15)*4;
      int n=n0+r;
      float4 v = (n<NN)? *(const float4*)(in + (size_t)n*INST + kc*64 + c4) : make_float4(0,0,0,0);
      if(dosilu){ v.x=siluf(v.x); v.y=siluf(v.y); v.z=siluf(v.z); v.w=siluf(v.w); }
      float* dst = s_a + r*RS + (c4>>2);
      dst[0]=tf32r(v.x); dst[18]=tf32r(v.y); dst[36]=tf32r(v.z); dst[54]=tf32r(v.w);
    }
    {
      const float4* s0=(const float4*)(Wp + (size_t)(cc0*KC+kc)*(64*RS));
      const float4* s1=(const float4*)(Wp + (size_t)((cc0+1)*KC+kc)*(64*RS));
      float4* d0=(float4*)s_b;
      float4* d1=(float4*)(s_b+64*RS);
      #pragma unroll
      for(int t=0;t<5;t++){ int i=tid+t*256; if(i<1152){ d0[i]=s0[i]; d1[i]=s1[i]; } }
    }
    __syncthreads();
    #pragma unroll
    for(int ks=0;ks<8;ks++){
      float2 A0=*(float2*)(s_a+ra*RS+aoff+2*ks);
      float2 A1=*(float2*)(s_a+rb*RS+aoff+2*ks);
      unsigned a0=__float_as_uint(A0.x), a2=__float_as_uint(A0.y);
      unsigned a1=__float_as_uint(A1.x), a3=__float_as_uint(A1.y);
      #pragma unroll
      for(int nt=0;nt<16;nt++){
        float* sb = s_b + (nt>>3)*(64*RS);
        float2 Bv=*(float2*)(sb+((nt&7)*8+qr)*RS+aoff+2*ks);
        mma8(c1[nt],a0,a1,a2,a3,__float_as_uint(Bv.x),__float_as_uint(Bv.y));
      }
    }
  }
  int na=n0+ra, nb2=n0+rb;
  #pragma unroll
  for(int nt=0;nt<16;nt++){
    int col = cc0*64 + nt*8 + 2*qc;
    float b0=__ldg(&bias[col]), b1=__ldg(&bias[col+1]);
    if(na<NN)  *(float2*)(out+(size_t)na*F2+col)=make_float2(siluf(c1[nt].x+b0),siluf(c1[nt].y+b1));
    if(nb2<NN) *(float2*)(out+(size_t)nb2*F2+col)=make_float2(siluf(c1[nt].z+b0),siluf(c1[nt].w+b1));
  }
}

// ---------- edge MLP: 10 MMA chunks + scalar tail for cols 640/641 ----------
__global__ void __launch_bounds__(256,2) k_edge(const int* __restrict__ eidx,
   const float* __restrict__ keW1,const float* __restrict__ keb1,
   const float* __restrict__ keW2r,const float* __restrict__ keb2,
   const float* __restrict__ keng,const float* __restrict__ kenb,int k){
  extern __shared__ float sm[];
  float* s_h  = sm;                    // 128*72
  float* s_w1 = sm + 9216;             // 2 x 4608
  float* s_w2 = sm + 18432;            // 2 x 2304
  float* s_w1d= sm + 23040;            // 2 x 64
  float* s_b1 = sm + 23168;            // 2 x 64
  float* s_b2 = sm + 23296;
  float* s_g  = sm + 23328;
  float* s_bt = sm + 23360;
  float* s_w1t= sm + 23392;            // 128
  float* s_w2t= sm + 23520;            // 64
  float* s_sc = sm + 23584;            // 4
  int tid=threadIdx.x, w=tid>>5, l=tid&31, qr=l>>2, qc=l&3;
  int e0=blockIdx.x*128;
  int ra=w*16+qr, rb=ra+8, aoff=qc*18;
  uint32_t sbu=s2u(sm);
  const float* W1c = keW1 + (size_t)k*EINN*H1 + (size_t)256*H1;
  const float* B1  = keb1 + (size_t)k*H1;
  float2 eA[8], eB[8];
  {
    const float* pA=d_eap+(size_t)(e0+ra)*RS+aoff;
    const float* pB=d_eap+(size_t)(e0+rb)*RS+aoff;
    #pragma unroll
    for(int ks=0;ks<8;ks++){ eA[ks]=*(const float2*)(pA+2*ks); eB[ks]=*(const float2*)(pB+2*ks); }
  }
  int nda=eidx[EE+e0+ra], nsa=eidx[e0+ra];
  int ndb=eidx[EE+e0+rb], nsb=eidx[e0+rb];
  float da=d_dcol[e0+ra], db=d_dcol[e0+rb];
  if(tid<32){ s_b2[tid]=keb2[k*MM+tid]; s_g[tid]=keng[k*MM+tid]; s_bt[tid]=kenb[k*MM+tid]; }
  if(tid<128){ int kk=tid>>1, j=tid&1; s_w1t[tid]=W1c[(size_t)kk*H1+640+j]; }
  else if(tid<192){ int m=tid-128; int j=m>>5, n=m&31;
    s_w2t[m]=keW2r[(size_t)k*H1*MM + (size_t)(640+j)*MM + n]; }
  else if(tid<196){ int m=tid-192;
    s_sc[m] = (m<2)? B1[640+m] : W1c[(size_t)64*H1+640+(m-2)]; }

  auto stage=[&](int ch,int buf){
    const float4* w1s=(const float4*)(d_w1p + (size_t)((k*11+ch)*64)*RS);
    uint32_t w1a = sbu + (9216+buf*4608)*4;
    #pragma unroll
    for(int i=0;i<4;i++) cpa(w1a+(tid+256*i)*16, w1s+tid+256*i);
    if(tid<128) cpa(w1a+(1024+tid)*16, w1s+1024+tid);
    const float4* w2s=(const float4*)(d_w2p + (size_t)((k*11+ch)*32)*RS);
    uint32_t w2a = sbu + (18432+buf*2304)*4;
    #pragma unroll
    for(int i=0;i<2;i++) cpa(w2a+(tid+256*i)*16, w2s+tid+256*i);
    if(tid<64){
      cpa(w2a+(512+tid)*16, w2s+512+tid);
      int j=ch*64+tid;
      s_b1[buf*64+tid]=B1[j];
      s_w1d[buf*64+tid]=W1c[(size_t)64*H1+j];
    }
  };
  stage(0,0); CPA_COMMIT();

  float4 c2[4];
  #pragma unroll
  for(int t=0;t<4;t++) c2[t]=make_float4(0.f,0.f,0.f,0.f);

  for(int ch=0; ch<10; ch++){
    int buf=ch&1;
    CPA_WAIT0();
    __syncthreads();
    if(ch<9){ stage(ch+1,1-buf); CPA_COMMIT(); }
    float* w1b = s_w1 + buf*4608;
    float* w2b = s_w2 + buf*2304;
    float* b1b = s_b1 + buf*64;
    float* wdb = s_w1d + buf*64;
    int jc0=ch*64;
    float4 c1[8];
    #pragma unroll
    for(int t=0;t<8;t++) c1[t]=make_float4(0.f,0.f,0.f,0.f);
    #pragma unroll
    for(int ks=0;ks<8;ks++){
      unsigned a0=__float_as_uint(eA[ks].x), a2=__float_as_uint(eA[ks].y);
      unsigned a1=__float_as_uint(eB[ks].x), a3=__float_as_uint(eB[ks].y);
      #pragma unroll
      for(int nt=0;nt<8;nt++){
        float2 Bv=*(float2*)(w1b+(nt*8+qr)*RS+aoff+2*ks);
        mma8(c1[nt],a0,a1,a2,a3,__float_as_uint(Bv.x),__float_as_uint(Bv.y));
      }
    }
    {
      const float* FAa=d_FA+(size_t)nda*FASTRIDE+jc0;
      const float* FBa=d_FB+(size_t)nsa*FASTRIDE+jc0;
      const float* FAb=d_FA+(size_t)ndb*FASTRIDE+jc0;
      const float* FBb=d_FB+(size_t)nsb*FASTRIDE+jc0;
      #pragma unroll
      for(int nt=0;nt<8;nt++){
        int col0=nt*8+2*qc;
        float2 faa=*(const float2*)(FAa+col0);
        float2 fba=*(const float2*)(FBa+col0);
        float2 fab=*(const float2*)(FAb+col0);
        float2 fbb=*(const float2*)(FBb+col0);
        float b0=b1b[col0], b1f=b1b[col0+1];
        float w0=wdb[col0], w1v=wdb[col0+1];
        int p0=((col0&3)*18) + (col0>>2);
        s_h[ra*RS+p0]   =tf32r(siluf(c1[nt].x+b0 +da*w0 +faa.x+fba.x));
        s_h[ra*RS+p0+18]=tf32r(siluf(c1[nt].y+b1f+da*w1v+faa.y+fba.y));
        s_h[rb*RS+p0]   =tf32r(siluf(c1[nt].z+b0 +db*w0 +fab.x+fbb.x));
        s_h[rb*RS+p0+18]=tf32r(siluf(c1[nt].w+b1f+db*w1v+fab.y+fbb.y));
      }
    }
    __syncwarp();
    #pragma unroll
    for(int ks=0;ks<8;ks++){
      float2 A0=*(float2*)(s_h+ra*RS+aoff+2*ks);
      float2 A1=*(float2*)(s_h+rb*RS+aoff+2*ks);
      unsigned a0=__float_as_uint(A0.x), a2=__float_as_uint(A0.y);
      unsigned a1=__float_as_uint(A1.x), a3=__float_as_uint(A1.y);
      #pragma unroll
      for(int nt=0;nt<4;nt++){
        float2 Bv=*(float2*)(w2b+(nt*8+qr)*RS+aoff+2*ks);
        mma8(c2[nt],a0,a1,a2,a3,__float_as_uint(Bv.x),__float_as_uint(Bv.y));
      }
    }
  }
  // scalar tail: H1 cols 640, 641
  {
    float p0a=0,p1a=0,p0b=0,p1b=0;
    #pragma unroll
    for(int ks=0;ks<8;ks++){
      int k1=8*ks+qc, k2=k1+4;
      p0a+=eA[ks].x*s_w1t[2*k1]  +eA[ks].y*s_w1t[2*k2];
      p1a+=eA[ks].x*s_w1t[2*k1+1]+eA[ks].y*s_w1t[2*k2+1];
      p0b+=eB[ks].x*s_w1t[2*k1]  +eB[ks].y*s_w1t[2*k2];
      p1b+=eB[ks].x*s_w1t[2*k1+1]+eB[ks].y*s_w1t[2*k2+1];
    }
    #pragma unroll
    for(int o=1;o<4;o<<=1){
      p0a+=__shfl_xor_sync(0xffffffffu,p0a,o); p1a+=__shfl_xor_sync(0xffffffffu,p1a,o);
      p0b+=__shfl_xor_sync(0xffffffffu,p0b,o); p1b+=__shfl_xor_sync(0xffffffffu,p1b,o);
    }
    float h0a=siluf(p0a+s_sc[0]+da*s_sc[2]+d_FA[(size_t)nda*FASTRIDE+640]+d_FB[(size_t)nsa*FASTRIDE+640]);
    float h1a=siluf(p1a+s_sc[1]+da*s_sc[3]+d_FA[(size_t)nda*FASTRIDE+641]+d_FB[(size_t)nsa*FASTRIDE+641]);
    float h0b=siluf(p0b+s_sc[0]+db*s_sc[2]+d_FA[(size_t)ndb*FASTRIDE+640]+d_FB[(size_t)nsb*FASTRIDE+640]);
    float h1b=siluf(p1b+s_sc[1]+db*s_sc[3]+d_FA[(size_t)ndb*FASTRIDE+641]+d_FB[(size_t)nsb*FASTRIDE+641]);
    #pragma unroll
    for(int nt=0;nt<4;nt++){
      int col0=nt*8+2*qc;
      c2[nt].x += h0a*s_w2t[col0]  +h1a*s_w2t[32+col0];
      c2[nt].y += h0a*s_w2t[col0+1]+h1a*s_w2t[32+col0+1];
      c2[nt].z += h0b*s_w2t[col0]  +h1b*s_w2t[32+col0];
      c2[nt].w += h0b*s_w2t[col0+1]+h1b*s_w2t[32+col0+1];
    }
  }
  float va[8], vb[8];
  #pragma unroll
  for(int nt=0;nt<4;nt++){
    int col0=nt*8+2*qc;
    va[2*nt]  =siluf(c2[nt].x+s_b2[col0]);
    va[2*nt+1]=siluf(c2[nt].y+s_b2[col0+1]);
    vb[2*nt]  =siluf(c2[nt].z+s_b2[col0]);
    vb[2*nt+1]=siluf(c2[nt].w+s_b2[col0+1]);
  }
  float sa=0.f,ssa=0.f,sb=0.f,ssb=0.f;
  #pragma unroll
  for(int i=0;i<8;i++){ sa+=va[i]; ssa+=va[i]*va[i]; sb+=vb[i]; ssb+=vb[i]*vb[i]; }
  #pragma unroll
  for(int o=1;o<4;o<<=1){
    sa+=__shfl_xor_sync(0xffffffffu,sa,o); ssa+=__shfl_xor_sync(0xffffffffu,ssa,o);
    sb+=__shfl_xor_sync(0xffffffffu,sb,o); ssb+=__shfl_xor_sync(0xffffffffu,ssb,o);
  }
  float mua=sa*(1.f/MM), vara=ssa*(1.f/MM)-mua*mua, inva=rsqrtf(vara+1e-5f);
  float mub=sb*(1.f/MM), varb=ssb*(1.f/MM)-mub*mub, invb=rsqrtf(varb+1e-5f);
  float* pa=&d_msum[(size_t)nda*MM];
  float* pb=&d_msum[(size_t)ndb*MM];
  #pragma unroll
  for(int nt=0;nt<4;nt++){
    int col0=nt*8+2*qc;
    atomicAdd(pa+col0,  (va[2*nt]  -mua)*inva*s_g[col0]  +s_bt[col0]);
    atomicAdd(pa+col0+1,(va[2*nt+1]-mua)*inva*s_g[col0+1]+s_bt[col0+1]);
    atomicAdd(pb+col0,  (vb[2*nt]  -mub)*invb*s_g[col0]  +s_bt[col0]);
    atomicAdd(pb+col0+1,(vb[2*nt+1]-mub)*invb*s_g[col0+1]+s_bt[col0+1]);
  }
}

__global__ void k_xcat(const float* __restrict__ keng,const float* __restrict__ kenb,
                       const float* __restrict__ kn1g,const float* __restrict__ kn1b,int k){
  int warp=threadIdx.x>>5, lane=threadIdx.x&31;
  int n=blockIdx.x*8+warp;
  const float* g1=kn1g+(size_t)k*128; const float* b1=kn1b+(size_t)k*128;
  float v[4],s=0.f,ss=0.f;
  #pragma unroll
  for(int i=0;i<4;i++){ float x=d_feats[(size_t)n*128+lane+32*i]; v[i]=x; s+=x; ss+=x*x; }
  #pragma unroll
  for(int o=16;o;o>>=1){ s+=__shfl_xor_sync(0xffffffffu,s,o); ss+=__shfl_xor_sync(0xffffffffu,ss,o); }
  float mu=s*(1.f/128), var=ss*(1.f/128)-mu*mu, inv=rsqrtf(var+1e-5f);
  #pragma unroll
  for(int i=0;i<4;i++){ int c=lane+32*i; d_xcat[(size_t)n*160+c]=(v[i]-mu)*inv*g1[c]+b1[c]; }
  float m=d_msum[(size_t)n*MM+lane]/fmaxf(d_deg[n],1.f);
  float s2=m, ss2=m*m;
  #pragma unroll
  for(int o=16;o;o>>=1){ s2+=__shfl_xor_sync(0xffffffffu,s2,o); ss2+=__shfl_xor_sync(0xffffffffu,ss2,o); }
  float mu2=s2*(1.f/MM), var2=ss2*(1.f/MM)-mu2*mu2, inv2=rsqrtf(var2+1e-5f);
  d_xcat[(size_t)n*160+128+lane]=(m-mu2)*inv2*keng[k*MM+lane]+kenb[k*MM+lane];
}

__global__ void __launch_bounds__(256) k_node(const float* __restrict__ knW1,const float* __restrict__ knb1,
    const float* __restrict__ knW2,const float* __restrict__ knb2,
    const float* __restrict__ kn2g,const float* __restrict__ kn2b,int k){
  extern __shared__ float sm[];
  float* s_x=sm;
  float* s_h=s_x+10304;
  float* s_w=s_h+16448;
  int tid=threadIdx.x;
  int n0=blockIdx.x*64;
  const float* W1=knW1+(size_t)k*160*256;
  const float* B1=knb1+(size_t)k*256;
  const float* W2=knW2+(size_t)k*256*128;
  const float* B2=knb2+(size_t)k*128;
  const float* G =kn2g+(size_t)k*128;
  const float* BT=kn2b+(size_t)k*128;
  for(int i=tid;i<64*160;i+=256){int r=i/160,c=i-r*160;int n=n0+r; s_x[r*161+c]= (n<NN)? d_xcat[(size_t)n*160+c]:0.f;}
  int r0=(tid>>4)*4, c0=(tid&15)*4;
  for(int oc=0;oc<4;oc++){
    __syncthreads();
    for(int i=tid;i<160*64;i+=256){int p=i>>6,c=i&63; s_w[i]=W1[(size_t)p*256+oc*64+c];}
    __syncthreads();
    float a4[4][4];
    #pragma unroll
    for(int i=0;i<4;i++){a4[i][0]=0;a4[i][1]=0;a4[i][2]=0;a4[i][3]=0;}
    for(int p=0;p<160;p++){
      float4 w=*(float4*)(s_w+p*64+c0);
      #pragma unroll
      for(int i=0;i<4;i++){ float a=s_x[(r0+i)*161+p];
        a4[i][0]+=a*w.x; a4[i][1]+=a*w.y; a4[i][2]+=a*w.z; a4[i][3]+=a*w.w; }
    }
    #pragma unroll
    for(int i=0;i<4;i++){
      #pragma unroll
      for(int j=0;j<4;j++){ int col=oc*64+c0+j;
        s_h[(r0+i)*257+col]=siluf(a4[i][j]+__ldg(&B1[col])); }
    }
  }
  __syncthreads();
  for(int oc=0;oc<2;oc++){
    if(oc) __syncthreads();
    for(int i=tid;i<256*64;i+=256){int p=i>>6,c=i&63; s_w[i]=W2[(size_t)p*128+oc*64+c];}
    __syncthreads();
    float a4[4][4];
    #pragma unroll
    for(int i=0;i<4;i++){a4[i][0]=0;a4[i][1]=0;a4[i][2]=0;a4[i][3]=0;}
    for(int p=0;p<256;p++){
      float4 w=*(float4*)(s_w+p*64+c0);
      #pragma unroll
      for(int i=0;i<4;i++){ float a=s_h[(r0+i)*257+p];
        a4[i][0]+=a*w.x; a4[i][1]+=a*w.y; a4[i][2]+=a*w.z; a4[i][3]+=a*w.w; }
    }
    #pragma unroll
    for(int i=0;i<4;i++){
      #pragma unroll
      for(int j=0;j<4;j++){ int col=oc*64+c0+j;
        s_x[(r0+i)*129+col]=a4[i][j]+__ldg(&B2[col]); }
    }
  }
  __syncthreads();
  int w=tid>>5, lane=tid&31;
  for(int rr=w; rr<64; rr+=8){
    int n=n0+rr;
    float v[4],s=0.f,ss=0.f;
    #pragma unroll
    for(int i=0;i<4;i++){ float x=s_x[rr*129+lane+32*i]; v[i]=x; s+=x; ss+=x*x; }
    #pragma unroll
    for(int o=16;o;o>>=1){ s+=__shfl_xor_sync(0xffffffffu,s,o); ss+=__shfl_xor_sync(0xffffffffu,ss,o); }
    float mu=s*(1.f/128), var=ss*(1.f/128)-mu*mu, inv=rsqrtf(var+1e-5f);
    if(n<NN){
      #pragma unroll
      for(int i=0;i<4;i++){ int c=lane+32*i;
        float nv=(v[i]-mu)*inv*G[c]+BT[c];
        float f=d_feats[(size_t)n*128+c]+nv;
        d_feats[(size_t)n*128+c]=f;
        d_fcat[(size_t)n*FH+(size_t)(k+1)*128+c]=f; }
    }
  }
}

__global__ void k_pool(const int* __restrict__ batch){
  int n=blockIdx.x; int c=threadIdx.x;
  int b=batch[n];
  atomicAdd(&d_gsum[b*F2+c], d_f1[(size_t)n*F2+c]);
  if(c==0) atomicAdd(&d_gcnt[b],1.f);
}

__global__ void k_final(const float* __restrict__ gW0,const float* __restrict__ gb0,
                        const float* __restrict__ gW1,const float* __restrict__ gb1,
                        const float* __restrict__ gW2,const float* __restrict__ gb2,
                        float* __restrict__ out){
  __shared__ float s_g[256], s_h[256], s_red[8];
  int b=blockIdx.x, t=threadIdx.x;
  float cnt=fmaxf(d_gcnt[b],1.f);
  s_g[t]=d_gsum[b*F2+t]/cnt;
  __syncthreads();
  float a=gb0[t];
  #pragma unroll 8
  for(int p=0;p<256;p++) a+=s_g[p]*gW0[p*256+t];
  s_h[t]=siluf(a);
  __syncthreads();
  a=gb1[t];
  #pragma unroll 8
  for(int p=0;p<256;p++) a+=s_h[p]*gW1[p*256+t];
  float h=siluf(a);
  float v=h*gW2[t];
  #pragma unroll
  for(int o=16;o;o>>=1) v+=__shfl_xor_sync(0xffffffffu,v,o);
  if((t&31)==0) s_red[t>>5]=v;
  __syncthreads();
  if(t==0){ float tot=0.f;
    #pragma unroll
    for(int i=0;i<8;i++) tot+=s_red[i];
    out[b]=tot+gb2[0]; }
}

extern "C" void kernel_launch(void* const* d_in, const int* in_sizes, int n_in,
                              void* d_out, int out_size){
  const float* coords =(const float*)d_in[0];
  const int*   atomids=(const int*)d_in[1];
  const int*   eidx   =(const int*)d_in[2];
  const int*   batch  =(const int*)d_in[3];
  int s = (in_sizes[4]==11*DD) ? 4 : 5;
  const float* emb =(const float*)d_in[s+0];
  const float* keW1=(const float*)d_in[s+1];
  const float* keb1=(const float*)d_in[s+2];
  const float* keW2=(const float*)d_in[s+3];
  const float* keb2=(const float*)d_in[s+4];
  const float* keng=(const float*)d_in[s+5];
  const float* kenb=(const float*)d_in[s+6];
  const float* kn1g=(const float*)d_in[s+7];
  const float* kn1b=(const float*)d_in[s+8];
  const float* knW1=(const float*)d_in[s+9];
  const float* knb1=(const float*)d_in[s+10];
  const float* knW2=(const float*)d_in[s+11];
  const float* knb2=(const float*)d_in[s+12];
  const float* kn2g=(const float*)d_in[s+13];
  const float* kn2b=(const float*)d_in[s+14];
  const float* fW0 =(const float*)d_in[s+15];
  const float* fb0 =(const float*)d_in[s+16];
  const float* fW1 =(const float*)d_in[s+17];
  const float* fb1 =(const float*)d_in[s+18];
  const float* fW2 =(const float*)d_in[s+19];
  const float* fb2 =(const float*)d_in[s+20];
  const float* gW0 =(const float*)d_in[s+21];
  const float* gb0 =(const float*)d_in[s+22];
  const float* gW1 =(const float*)d_in[s+23];
  const float* gb1 =(const float*)d_in[s+24];
  const float* gW2 =(const float*)d_in[s+25];
  const float* gb2 =(const float*)d_in[s+26];
  float* out=(float*)d_out;

  const int EDGE_SM = 23592*4;                 // 94368
  const int NODE_SM = (10304+16448+16384)*4;   // 172544
  const int FAB_SM  = (2*128*RS + 2*64*RS)*4;  // 110592
  const int FNN_SM  = (128*RS + 2*64*RS)*4;    // 73728
  cudaFuncSetAttribute(k_edge,    cudaFuncAttributeMaxDynamicSharedMemorySize, EDGE_SM);
  cudaFuncSetAttribute(k_node,    cudaFuncAttributeMaxDynamicSharedMemorySize, NODE_SM);
  cudaFuncSetAttribute(k_fab_mma, cudaFuncAttributeMaxDynamicSharedMemorySize, FAB_SM);
  cudaFuncSetAttribute(k_fnn_mma, cudaFuncAttributeMaxDynamicSharedMemorySize, FNN_SM);

  k_zero_init<<<65,256>>>();
  k_feats<<<NN,128>>>(emb,atomids);
  k_deg<<<EE/256,256>>>(eidx);
  k_ea<<<EE/256,256>>>(coords,eidx);
  k_wprep<<<1320,256>>>(keW1,keW2);
  k_wprep_fab<<<3520,256>>>(keW1);
  k_wprep_fnn<<<1280,256>>>(fW0,fW1,fW2);
  for(int k=0;k<KK;k++){
    k_fab_mma<<<dim3(11,79,2),256,FAB_SM>>>(k);
    k_edge<<<EE/128,256,EDGE_SM>>>(eidx,keW1,keb1,keW2,keb2,keng,kenb,k);
    k_xcat<<<NN/8,256>>>(keng,kenb,kn1g,kn1b,k);
    k_node<<<157,256,NODE_SM>>>(knW1,knb1,knW2,knb2,kn2g,kn2b,k);
  }
  k_fnn_mma<<<dim3(2,79),256,FNN_SM>>>(fb0, 0);
  k_fnn_mma<<<dim3(2,79),256,FNN_SM>>>(fb1, 1);
  k_fnn_mma<<<dim3(2,79),256,FNN_SM>>>(fb2, 2);
  k_pool<<<NN,256>>>(batch);
  k_final<<<BB,256>>>(gW0,gb0,gW1,gb1,gW2,gb2,out);
}

// round 14
// speedup vs baseline: 1.2542x; 1.0008x over previous
#include <cuda_runtime.h>
#include <stdint.h>
#include <math.h>

#define NN 10000
#define EE 160000
#define BB 64
#define DD 128
#define MM 32
#define EINN 321
#define H1 642
#define KK 5
#define FH 768
#define F2 256
#define FASTRIDE 644

#define PERM(k) (((k)&3)*18 + ((k)>>2))
#define RS 72

__device__ float d_feats[NN*DD];
__device__ float d_eap[EE*RS];
__device__ float d_dcol[EE];
__device__ float d_deg[NN];
__device__ float d_FA[NN*FASTRIDE + 256];
__device__ float d_FB[NN*FASTRIDE + 256];
__device__ float d_msum[NN*MM];
__device__ float d_xcat[NN*160];
__device__ float d_fcat[NN*FH];
__device__ float d_f1[NN*F2];
__device__ float d_f2[NN*F2];
__device__ float d_gsum[BB*F2];
__device__ float d_gcnt[BB];
__device__ float d_w1p[KK*11*64*RS];
__device__ float d_w2p[KK*11*32*RS];
__device__ float d_wfabp[KK*2*12*2*64*RS];
__device__ float d_wf0p[4*12*64*RS];
__device__ float d_wf1p[4*4*64*RS];
__device__ float d_wf2p[4*4*64*RS];

__device__ __forceinline__ float siluf(float x){
  return __fdividef(x, 1.f+__expf(-x));
}
__device__ __forceinline__ float tf32r(float x){
  float r; asm("cvt.rna.tf32.f32 %0,%1;" : "=f"(r) : "f"(x)); return r;
}
__device__ __forceinline__ void mma8(float4 &c, unsigned a0,unsigned a1,unsigned a2,unsigned a3,
                                     unsigned b0,unsigned b1){
  asm("mma.sync.aligned.m16n8k8.row.col.f32.tf32.tf32.f32 "
      "{%0,%1,%2,%3},{%4,%5,%6,%7},{%8,%9},{%0,%1,%2,%3};"
      : "+f"(c.x),"+f"(c.y),"+f"(c.z),"+f"(c.w)
      : "r"(a0),"r"(a1),"r"(a2),"r"(a3),"r"(b0),"r"(b1));
}
__device__ __forceinline__ uint32_t s2u(const void* p){
  uint32_t a; asm("{ .reg .u64 t; cvta.to.shared.u64 t, %1; cvt.u32.u64 %0, t; }" : "=r"(a) : "l"(p)); return a;
}
__device__ __forceinline__ void cpa(uint32_t s, const void* g){
  asm volatile("cp.async.cg.shared.global [%0], [%1], 16;"::"r"(s),"l"(g):"memory");
}
#define CPA_COMMIT() asm volatile("cp.async.commit_group;":::"memory")
#define CPA_WAIT0()  asm volatile("cp.async.wait_group 0;":::"memory")

__global__ void k_zero_init(){
  int i = blockIdx.x*256+threadIdx.x;
  if(i<NN) d_deg[i]=0.f;
  if(i<BB*F2) d_gsum[i]=0.f;
  if(i<BB) d_gcnt[i]=0.f;
}
__global__ void k_feats(const float* __restrict__ emb, const int* __restrict__ atomids){
  int n=blockIdx.x; int c=threadIdx.x;
  float v=emb[atomids[n]*DD+c];
  d_feats[n*DD+c]=v;
  d_fcat[(size_t)n*FH+c]=v;
}
__global__ void k_deg(const int* __restrict__ eidx){
  int e=blockIdx.x*256+threadIdx.x;
  atomicAdd(&d_deg[eidx[EE+e]],1.f);
}
__global__ void k_ea(const float* __restrict__ coords, const int* __restrict__ eidx){
  int e=blockIdx.x*256+threadIdx.x;
  int s=eidx[e], t2=eidx[EE+e];
  float dx=coords[3*s]-coords[3*t2];
  float dy=coords[3*s+1]-coords[3*t2+1];
  float dz=coords[3*s+2]-coords[3*t2+2];
  float d=dx*dx+dy*dy+dz*dz;
  float* o=&d_eap[(size_t)e*RS];
  #pragma unroll
  for(int i=0;i<32;i++){
    float sc=__uint_as_float((unsigned)(127-i)<<23);   // 2^-i
    float x=d*sc;
    float sv,cv; __sincosf(x,&sv,&cv);
    o[PERM(i)]=tf32r(sv); o[PERM(32+i)]=tf32r(cv);
  }
  d_dcol[e]=d;
}

__global__ void k_wprep(const float* __restrict__ keW1, const float* __restrict__ keW2){
  int i = blockIdx.x*256+threadIdx.x;
  const int W1TOT = KK*11*64*64;
  const int W2TOT = KK*11*32*64;
  if(i < W1TOT){
    int kk=i&63; int n=(i>>6)&63; int ch=(i>>12)%11; int k=i/(64*64*11);
    int j=ch*64+n;
    float v = (j<H1)? tf32r(keW1[(size_t)k*EINN*H1 + (size_t)(256+kk)*H1 + j]) : 0.f;
    d_w1p[(size_t)(((k*11+ch)*64)+n)*RS + PERM(kk)] = v;
  } else if(i < W1TOT+W2TOT){
    int m=i-W1TOT;
    int kk=m&63; int n=(m>>6)&31; int ch=(m>>11)%11; int k=m/(32*64*11);
    int j=ch*64+kk;
    float v = (j<H1)? tf32r(keW2[(size_t)k*H1*MM + (size_t)j*MM + n]) : 0.f;
    d_w2p[(size_t)(((k*11+ch)*32)+n)*RS + PERM(kk)] = v;
  }
}
// FA/FB weights in gemm128 layout: [k][part][cc=12][kc=2][64n][RS]
__global__ void k_wprep_fab(const float* __restrict__ keW1){
  int i = blockIdx.x*256+threadIdx.x;   // total KK*2*12*2*64*64 = 983040
  int kk=i&63; int i2=i>>6;
  int n=i2&63; i2>>=6;
  int kc=i2&1; i2>>=1;
  int cc=i2%12; i2/=12;
  int part=i2&1; int k=i2>>1;
  int p = part*128 + kc*64 + kk;
  int col = cc*64 + n;
  float v = (col<H1)? tf32r(keW1[(size_t)k*EINN*H1 + (size_t)p*H1 + col]) : 0.f;
  d_wfabp[(size_t)((((k*2+part)*12+cc)*2+kc)*64 + n)*RS + PERM(kk)] = v;
}
__global__ void k_wprep_fnn(const float* __restrict__ fW0,
                            const float* __restrict__ fW1,
                            const float* __restrict__ fW2){
  int i = blockIdx.x*256+threadIdx.x;
  if(i < 196608){
    int kk=i&63; int n=(i>>6)&63; int r=i>>12;
    int kc=r%12, cc=r/12;
    d_wf0p[(size_t)((cc*12+kc)*64+n)*RS + PERM(kk)] =
      tf32r(fW0[(size_t)(kc*64+kk)*F2 + cc*64+n]);
  } else if(i < 262144){
    int j=i-196608;
    int kk=j&63; int n=(j>>6)&63; int r=j>>12;
    int kc=r&3, cc=r>>2;
    d_wf1p[(size_t)((cc*4+kc)*64+n)*RS + PERM(kk)] =
      tf32r(fW1[(size_t)(kc*64+kk)*F2 + cc*64+n]);
  } else {
    int j=i-262144;
    int kk=j&63; int n=(j>>6)&63; int r=j>>12;
    int kc=r&3, cc=r>>2;
    d_wf2p[(size_t)((cc*4+kc)*64+n)*RS + PERM(kk)] =
      tf32r(fW2[(size_t)(kc*64+kk)*F2 + cc*64+n]);
  }
}

// generic 128-row x 128-col tf32 MMA GEMM body
__device__ __forceinline__ void gemm128(const float* Wp, const float* in, int INST, int KC,
                                        int insilu, int n0, int cc0, float4* c1, float* sm){
  float* s_a = sm;
  float* s_b = sm + 128*RS;
  int tid=threadIdx.x;
  int w=tid>>5, l=tid&31, qr=l>>2, qc=l&3;
  int ra=w*16+qr, rb=ra+8, aoff=qc*18;
  for(int kc=0;kc<KC;kc++){
    __syncthreads();
    #pragma unroll
    for(int t=0;t<8;t++){
      int lin=tid+t*256;
      int r=lin>>4, c4=(lin&15)*4;
      int n=n0+r;
      float4 v = (n<NN)? *(const float4*)(in + (size_t)n*INST + kc*64 + c4) : make_float4(0,0,0,0);
      if(insilu){ v.x=siluf(v.x); v.y=siluf(v.y); v.z=siluf(v.z); v.w=siluf(v.w); }
      float* dst = s_a + r*RS + (c4>>2);
      dst[0]=tf32r(v.x); dst[18]=tf32r(v.y); dst[36]=tf32r(v.z); dst[54]=tf32r(v.w);
    }
    {
      const float4* s0=(const float4*)(Wp + (size_t)(cc0*KC+kc)*(64*RS));
      const float4* s1=(const float4*)(Wp + (size_t)((cc0+1)*KC+kc)*(64*RS));
      float4* d0=(float4*)s_b;
      float4* d1=(float4*)(s_b+64*RS);
      #pragma unroll
      for(int t=0;t<5;t++){ int i=tid+t*256; if(i<1152){ d0[i]=s0[i]; d1[i]=s1[i]; } }
    }
    __syncthreads();
    #pragma unroll
    for(int ks=0;ks<8;ks++){
      float2 A0=*(float2*)(s_a+ra*RS+aoff+2*ks);
      float2 A1=*(float2*)(s_a+rb*RS+aoff+2*ks);
      unsigned a0=__float_as_uint(A0.x), a2=__float_as_uint(A0.y);
      unsigned a1=__float_as_uint(A1.x), a3=__float_as_uint(A1.y);
      #pragma unroll
      for(int nt=0;nt<16;nt++){
        float* sb = s_b + (nt>>3)*(64*RS);
        float2 Bv=*(float2*)(sb+((nt&7)*8+qr)*RS+aoff+2*ks);
        mma8(c1[nt],a0,a1,a2,a3,__float_as_uint(Bv.x),__float_as_uint(Bv.y));
      }
    }
  }
}

// FA/FB via gemm128: grid (6,79,2); also zeroes d_msum
__global__ void __launch_bounds__(256,2) k_fab_mma(int k){
  extern __shared__ float sm[];
  int tid=threadIdx.x;
  for(int gi=(blockIdx.x+6*(blockIdx.y+79*(int)blockIdx.z))*256+tid; gi<NN*MM; gi+=948*256)
    d_msum[gi]=0.f;
  int part=blockIdx.z;
  int n0=blockIdx.y*128, cc0=blockIdx.x*2;
  const float* Wp = d_wfabp + (size_t)(k*2+part)*(12*2*64*RS);
  float4 c1[16];
  #pragma unroll
  for(int t=0;t<16;t++) c1[t]=make_float4(0,0,0,0);
  gemm128(Wp, d_feats, 128, 2, 0, n0, cc0, c1, sm);
  float* OUT = part? d_FB : d_FA;
  int w=tid>>5, l=tid&31, qr=l>>2, qc=l&3;
  int na=n0+w*16+qr, nb2=na+8;
  #pragma unroll
  for(int nt=0;nt<16;nt++){
    int col = cc0*64 + nt*8 + 2*qc;
    if(col<642){
      if(na<NN)  *(float2*)(OUT+(size_t)na*FASTRIDE+col)=make_float2(c1[nt].x,c1[nt].y);
      if(nb2<NN) *(float2*)(OUT+(size_t)nb2*FASTRIDE+col)=make_float2(c1[nt].z,c1[nt].w);
    }
  }
}

__global__ void __launch_bounds__(256,2) k_fnn_mma(const float* __restrict__ bias, int stage){
  const float* Wp = (stage==0)? d_wf0p : ((stage==1)? d_wf1p : d_wf2p);
  const float* in = (stage==0)? d_fcat : ((stage==1)? d_f1 : d_f2);
  float* out      = (stage==1)? d_f2 : d_f1;
  int KC          = (stage==0)? 12 : 4;
  extern __shared__ float sm[];
  int n0 = blockIdx.y*128, cc0 = blockIdx.x*2;
  float4 c1[16];
  #pragma unroll
  for(int t=0;t<16;t++) c1[t]=make_float4(0,0,0,0);
  gemm128(Wp, in, KC*64, KC, stage==0, n0, cc0, c1, sm);
  int tid=threadIdx.x, w=tid>>5, l=tid&31, qr=l>>2, qc=l&3;
  int na=n0+w*16+qr, nb2=na+8;
  #pragma unroll
  for(int nt=0;nt<16;nt++){
    int col = cc0*64 + nt*8 + 2*qc;
    float b0=__ldg(&bias[col]), b1=__ldg(&bias[col+1]);
    if(na<NN)  *(float2*)(out+(size_t)na*F2+col)=make_float2(siluf(c1[nt].x+b0),siluf(c1[nt].y+b1));
    if(nb2<NN) *(float2*)(out+(size_t)nb2*F2+col)=make_float2(siluf(c1[nt].z+b0),siluf(c1[nt].w+b1));
  }
}

// ---------- edge MLP: 10 MMA chunks + scalar tail for cols 640/641 ----------
__global__ void __launch_bounds__(256,2) k_edge(const int* __restrict__ eidx,
   const float* __restrict__ keW1,const float* __restrict__ keb1,
   const float* __restrict__ keW2r,const float* __restrict__ keb2,
   const float* __restrict__ keng,const float* __restrict__ kenb,int k){
  extern __shared__ float sm[];
  float* s_h  = sm;                    // 128*72
  float* s_w1 = sm + 9216;             // 2 x 4608
  float* s_w2 = sm + 18432;            // 2 x 2304
  float* s_w1d= sm + 23040;            // 2 x 64
  float* s_b1 = sm + 23168;            // 2 x 64
  float* s_b2 = sm + 23296;
  float* s_g  = sm + 23328;
  float* s_bt = sm + 23360;
  float* s_w1t= sm + 23392;            // 128
  float* s_w2t= sm + 23520;            // 64
  float* s_sc = sm + 23584;            // 4
  int tid=threadIdx.x, w=tid>>5, l=tid&31, qr=l>>2, qc=l&3;
  int e0=blockIdx.x*128;
  int ra=w*16+qr, rb=ra+8, aoff=qc*18;
  uint32_t sbu=s2u(sm);
  const float* W1c = keW1 + (size_t)k*EINN*H1 + (size_t)256*H1;
  const float* B1  = keb1 + (size_t)k*H1;
  float2 eA[8], eB[8];
  {
    const float* pA=d_eap+(size_t)(e0+ra)*RS+aoff;
    const float* pB=d_eap+(size_t)(e0+rb)*RS+aoff;
    #pragma unroll
    for(int ks=0;ks<8;ks++){ eA[ks]=*(const float2*)(pA+2*ks); eB[ks]=*(const float2*)(pB+2*ks); }
  }
  int nda=eidx[EE+e0+ra], nsa=eidx[e0+ra];
  int ndb=eidx[EE+e0+rb], nsb=eidx[e0+rb];
  float da=d_dcol[e0+ra], db=d_dcol[e0+rb];
  if(tid<32){ s_b2[tid]=keb2[k*MM+tid]; s_g[tid]=keng[k*MM+tid]; s_bt[tid]=kenb[k*MM+tid]; }
  if(tid<128){ int kk=tid>>1, j=tid&1; s_w1t[tid]=W1c[(size_t)kk*H1+640+j]; }
  else if(tid<192){ int m=tid-128; int j=m>>5, n=m&31;
    s_w2t[m]=keW2r[(size_t)k*H1*MM + (size_t)(640+j)*MM + n]; }
  else if(tid<196){ int m=tid-192;
    s_sc[m] = (m<2)? B1[640+m] : W1c[(size_t)64*H1+640+(m-2)]; }

  auto stage=[&](int ch,int buf){
    const float4* w1s=(const float4*)(d_w1p + (size_t)((k*11+ch)*64)*RS);
    uint32_t w1a = sbu + (9216+buf*4608)*4;
    #pragma unroll
    for(int i=0;i<4;i++) cpa(w1a+(tid+256*i)*16, w1s+tid+256*i);
    if(tid<128) cpa(w1a+(1024+tid)*16, w1s+1024+tid);
    const float4* w2s=(const float4*)(d_w2p + (size_t)((k*11+ch)*32)*RS);
    uint32_t w2a = sbu + (18432+buf*2304)*4;
    #pragma unroll
    for(int i=0;i<2;i++) cpa(w2a+(tid+256*i)*16, w2s+tid+256*i);
    if(tid<64){
      cpa(w2a+(512+tid)*16, w2s+512+tid);
      int j=ch*64+tid;
      s_b1[buf*64+tid]=B1[j];
      s_w1d[buf*64+tid]=W1c[(size_t)64*H1+j];
    }
  };
  stage(0,0); CPA_COMMIT();

  float4 c2[4];
  #pragma unroll
  for(int t=0;t<4;t++) c2[t]=make_float4(0.f,0.f,0.f,0.f);

  for(int ch=0; ch<10; ch++){
    int buf=ch&1;
    CPA_WAIT0();
    __syncthreads();
    if(ch<9){ stage(ch+1,1-buf); CPA_COMMIT(); }
    float* w1b = s_w1 + buf*4608;
    float* w2b = s_w2 + buf*2304;
    float* b1b = s_b1 + buf*64;
    float* wdb = s_w1d + buf*64;
    int jc0=ch*64;
    float4 c1[8];
    #pragma unroll
    for(int t=0;t<8;t++) c1[t]=make_float4(0.f,0.f,0.f,0.f);
    #pragma unroll
    for(int ks=0;ks<8;ks++){
      unsigned a0=__float_as_uint(eA[ks].x), a2=__float_as_uint(eA[ks].y);
      unsigned a1=__float_as_uint(eB[ks].x), a3=__float_as_uint(eB[ks].y);
      #pragma unroll
      for(int nt=0;nt<8;nt++){
        float2 Bv=*(float2*)(w1b+(nt*8+qr)*RS+aoff+2*ks);
        mma8(c1[nt],a0,a1,a2,a3,__float_as_uint(Bv.x),__float_as_uint(Bv.y));
      }
    }
    {
      const float* FAa=d_FA+(size_t)nda*FASTRIDE+jc0;
      const float* FBa=d_FB+(size_t)nsa*FASTRIDE+jc0;
      const float* FAb=d_FA+(size_t)ndb*FASTRIDE+jc0;
      const float* FBb=d_FB+(size_t)nsb*FASTRIDE+jc0;
      #pragma unroll
      for(int nt=0;nt<8;nt++){
        int col0=nt*8+2*qc;
        float2 faa=*(const float2*)(FAa+col0);
        float2 fba=*(const float2*)(FBa+col0);
        float2 fab=*(const float2*)(FAb+col0);
        float2 fbb=*(const float2*)(FBb+col0);
        float b0=b1b[col0], b1f=b1b[col0+1];
        float w0=wdb[col0], w1v=wdb[col0+1];
        int p0=((col0&3)*18) + (col0>>2);
        s_h[ra*RS+p0]   =tf32r(siluf(c1[nt].x+b0 +da*w0 +faa.x+fba.x));
        s_h[ra*RS+p0+18]=tf32r(siluf(c1[nt].y+b1f+da*w1v+faa.y+fba.y));
        s_h[rb*RS+p0]   =tf32r(siluf(c1[nt].z+b0 +db*w0 +fab.x+fbb.x));
        s_h[rb*RS+p0+18]=tf32r(siluf(c1[nt].w+b1f+db*w1v+fab.y+fbb.y));
      }
    }
    __syncwarp();
    #pragma unroll
    for(int ks=0;ks<8;ks++){
      float2 A0=*(float2*)(s_h+ra*RS+aoff+2*ks);
      float2 A1=*(float2*)(s_h+rb*RS+aoff+2*ks);
      unsigned a0=__float_as_uint(A0.x), a2=__float_as_uint(A0.y);
      unsigned a1=__float_as_uint(A1.x), a3=__float_as_uint(A1.y);
      #pragma unroll
      for(int nt=0;nt<4;nt++){
        float2 Bv=*(float2*)(w2b+(nt*8+qr)*RS+aoff+2*ks);
        mma8(c2[nt],a0,a1,a2,a3,__float_as_uint(Bv.x),__float_as_uint(Bv.y));
      }
    }
  }
  // scalar tail: H1 cols 640, 641
  {
    float p0a=0,p1a=0,p0b=0,p1b=0;
    #pragma unroll
    for(int ks=0;ks<8;ks++){
      int k1=8*ks+qc, k2=k1+4;
      p0a+=eA[ks].x*s_w1t[2*k1]  +eA[ks].y*s_w1t[2*k2];
      p1a+=eA[ks].x*s_w1t[2*k1+1]+eA[ks].y*s_w1t[2*k2+1];
      p0b+=eB[ks].x*s_w1t[2*k1]  +eB[ks].y*s_w1t[2*k2];
      p1b+=eB[ks].x*s_w1t[2*k1+1]+eB[ks].y*s_w1t[2*k2+1];
    }
    #pragma unroll
    for(int o=1;o<4;o<<=1){
      p0a+=__shfl_xor_sync(0xffffffffu,p0a,o); p1a+=__shfl_xor_sync(0xffffffffu,p1a,o);
      p0b+=__shfl_xor_sync(0xffffffffu,p0b,o); p1b+=__shfl_xor_sync(0xffffffffu,p1b,o);
    }
    float h0a=siluf(p0a+s_sc[0]+da*s_sc[2]+d_FA[(size_t)nda*FASTRIDE+640]+d_FB[(size_t)nsa*FASTRIDE+640]);
    float h1a=siluf(p1a+s_sc[1]+da*s_sc[3]+d_FA[(size_t)nda*FASTRIDE+641]+d_FB[(size_t)nsa*FASTRIDE+641]);
    float h0b=siluf(p0b+s_sc[0]+db*s_sc[2]+d_FA[(size_t)ndb*FASTRIDE+640]+d_FB[(size_t)nsb*FASTRIDE+640]);
    float h1b=siluf(p1b+s_sc[1]+db*s_sc[3]+d_FA[(size_t)ndb*FASTRIDE+641]+d_FB[(size_t)nsb*FASTRIDE+641]);
    #pragma unroll
    for(int nt=0;nt<4;nt++){
      int col0=nt*8+2*qc;
      c2[nt].x += h0a*s_w2t[col0]  +h1a*s_w2t[32+col0];
      c2[nt].y += h0a*s_w2t[col0+1]+h1a*s_w2t[32+col0+1];
      c2[nt].z += h0b*s_w2t[col0]  +h1b*s_w2t[32+col0];
      c2[nt].w += h0b*s_w2t[col0+1]+h1b*s_w2t[32+col0+1];
    }
  }
  float va[8], vb[8];
  #pragma unroll
  for(int nt=0;nt<4;nt++){
    int col0=nt*8+2*qc;
    va[2*nt]  =siluf(c2[nt].x+s_b2[col0]);
    va[2*nt+1]=siluf(c2[nt].y+s_b2[col0+1]);
    vb[2*nt]  =siluf(c2[nt].z+s_b2[col0]);
    vb[2*nt+1]=siluf(c2[nt].w+s_b2[col0+1]);
  }
  float sa=0.f,ssa=0.f,sb=0.f,ssb=0.f;
  #pragma unroll
  for(int i=0;i<8;i++){ sa+=va[i]; ssa+=va[i]*va[i]; sb+=vb[i]; ssb+=vb[i]*vb[i]; }
  #pragma unroll
  for(int o=1;o<4;o<<=1){
    sa+=__shfl_xor_sync(0xffffffffu,sa,o); ssa+=__shfl_xor_sync(0xffffffffu,ssa,o);
    sb+=__shfl_xor_sync(0xffffffffu,sb,o); ssb+=__shfl_xor_sync(0xffffffffu,ssb,o);
  }
  float mua=sa*(1.f/MM), vara=ssa*(1.f/MM)-mua*mua, inva=rsqrtf(vara+1e-5f);
  float mub=sb*(1.f/MM), varb=ssb*(1.f/MM)-mub*mub, invb=rsqrtf(varb+1e-5f);
  float* pa=&d_msum[(size_t)nda*MM];
  float* pb=&d_msum[(size_t)ndb*MM];
  #pragma unroll
  for(int nt=0;nt<4;nt++){
    int col0=nt*8+2*qc;
    atomicAdd(pa+col0,  (va[2*nt]  -mua)*inva*s_g[col0]  +s_bt[col0]);
    atomicAdd(pa+col0+1,(va[2*nt+1]-mua)*inva*s_g[col0+1]+s_bt[col0+1]);
    atomicAdd(pb+col0,  (vb[2*nt]  -mub)*invb*s_g[col0]  +s_bt[col0]);
    atomicAdd(pb+col0+1,(vb[2*nt+1]-mub)*invb*s_g[col0+1]+s_bt[col0+1]);
  }
}

__global__ void k_xcat(const float* __restrict__ keng,const float* __restrict__ kenb,
                       const float* __restrict__ kn1g,const float* __restrict__ kn1b,int k){
  int warp=threadIdx.x>>5, lane=threadIdx.x&31;
  int n=blockIdx.x*8+warp;
  const float* g1=kn1g+(size_t)k*128; const float* b1=kn1b+(size_t)k*128;
  float v[4],s=0.f,ss=0.f;
  #pragma unroll
  for(int i=0;i<4;i++){ float x=d_feats[(size_t)n*128+lane+32*i]; v[i]=x; s+=x; ss+=x*x; }
  #pragma unroll
  for(int o=16;o;o>>=1){ s+=__shfl_xor_sync(0xffffffffu,s,o); ss+=__shfl_xor_sync(0xffffffffu,ss,o); }
  float mu=s*(1.f/128), var=ss*(1.f/128)-mu*mu, inv=rsqrtf(var+1e-5f);
  #pragma unroll
  for(int i=0;i<4;i++){ int c=lane+32*i; d_xcat[(size_t)n*160+c]=(v[i]-mu)*inv*g1[c]+b1[c]; }
  float m=d_msum[(size_t)n*MM+lane]/fmaxf(d_deg[n],1.f);
  float s2=m, ss2=m*m;
  #pragma unroll
  for(int o=16;o;o>>=1){ s2+=__shfl_xor_sync(0xffffffffu,s2,o); ss2+=__shfl_xor_sync(0xffffffffu,ss2,o); }
  float mu2=s2*(1.f/MM), var2=ss2*(1.f/MM)-mu2*mu2, inv2=rsqrtf(var2+1e-5f);
  d_xcat[(size_t)n*160+128+lane]=(m-mu2)*inv2*keng[k*MM+lane]+kenb[k*MM+lane];
}

__global__ void __launch_bounds__(256) k_node(const float* __restrict__ knW1,const float* __restrict__ knb1,
    const float* __restrict__ knW2,const float* __restrict__ knb2,
    const float* __restrict__ kn2g,const float* __restrict__ kn2b,int k){
  extern __shared__ float sm[];
  float* s_x=sm;
  float* s_h=s_x+10304;
  float* s_w=s_h+16448;
  int tid=threadIdx.x;
  int n0=blockIdx.x*64;
  const float* W1=knW1+(size_t)k*160*256;
  const float* B1=knb1+(size_t)k*256;
  const float* W2=knW2+(size_t)k*256*128;
  const float* B2=knb2+(size_t)k*128;
  const float* G =kn2g+(size_t)k*128;
  const float* BT=kn2b+(size_t)k*128;
  for(int i=tid;i<64*160;i+=256){int r=i/160,c=i-r*160;int n=n0+r; s_x[r*161+c]= (n<NN)? d_xcat[(size_t)n*160+c]:0.f;}
  int r0=(tid>>4)*4, c0=(tid&15)*4;
  for(int oc=0;oc<4;oc++){
    __syncthreads();
    for(int i=tid;i<160*64;i+=256){int p=i>>6,c=i&63; s_w[i]=W1[(size_t)p*256+oc*64+c];}
    __syncthreads();
    float a4[4][4];
    #pragma unroll
    for(int i=0;i<4;i++){a4[i][0]=0;a4[i][1]=0;a4[i][2]=0;a4[i][3]=0;}
    for(int p=0;p<160;p++){
      float4 w=*(float4*)(s_w+p*64+c0);
      #pragma unroll
      for(int i=0;i<4;i++){ float a=s_x[(r0+i)*161+p];
        a4[i][0]+=a*w.x; a4[i][1]+=a*w.y; a4[i][2]+=a*w.z; a4[i][3]+=a*w.w; }
    }
    #pragma unroll
    for(int i=0;i<4;i++){
      #pragma unroll
      for(int j=0;j<4;j++){ int col=oc*64+c0+j;
        s_h[(r0+i)*257+col]=siluf(a4[i][j]+__ldg(&B1[col])); }
    }
  }
  __syncthreads();
  for(int oc=0;oc<2;oc++){
    if(oc) __syncthreads();
    for(int i=tid;i<256*64;i+=256){int p=i>>6,c=i&63; s_w[i]=W2[(size_t)p*128+oc*64+c];}
    __syncthreads();
    float a4[4][4];
    #pragma unroll
    for(int i=0;i<4;i++){a4[i][0]=0;a4[i][1]=0;a4[i][2]=0;a4[i][3]=0;}
    for(int p=0;p<256;p++){
      float4 w=*(float4*)(s_w+p*64+c0);
      #pragma unroll
      for(int i=0;i<4;i++){ float a=s_h[(r0+i)*257+p];
        a4[i][0]+=a*w.x; a4[i][1]+=a*w.y; a4[i][2]+=a*w.z; a4[i][3]+=a*w.w; }
    }
    #pragma unroll
    for(int i=0;i<4;i++){
      #pragma unroll
      for(int j=0;j<4;j++){ int col=oc*64+c0+j;
        s_x[(r0+i)*129+col]=a4[i][j]+__ldg(&B2[col]); }
    }
  }
  __syncthreads();
  int w=tid>>5, lane=tid&31;
  for(int rr=w; rr<64; rr+=8){
    int n=n0+rr;
    float v[4],s=0.f,ss=0.f;
    #pragma unroll
    for(int i=0;i<4;i++){ float x=s_x[rr*129+lane+32*i]; v[i]=x; s+=x; ss+=x*x; }
    #pragma unroll
    for(int o=16;o;o>>=1){ s+=__shfl_xor_sync(0xffffffffu,s,o); ss+=__shfl_xor_sync(0xffffffffu,ss,o); }
    float mu=s*(1.f/128), var=ss*(1.f/128)-mu*mu, inv=rsqrtf(var+1e-5f);
    if(n<NN){
      #pragma unroll
      for(int i=0;i<4;i++){ int c=lane+32*i;
        float nv=(v[i]-mu)*inv*G[c]+BT[c];
        float f=d_feats[(size_t)n*128+c]+nv;
        d_feats[(size_t)n*128+c]=f;
        d_fcat[(size_t)n*FH+(size_t)(k+1)*128+c]=f; }
    }
  }
}

__global__ void k_pool(const int* __restrict__ batch){
  int n=blockIdx.x; int c=threadIdx.x;
  int b=batch[n];
  atomicAdd(&d_gsum[b*F2+c], d_f1[(size_t)n*F2+c]);
  if(c==0) atomicAdd(&d_gcnt[b],1.f);
}

__global__ void k_final(const float* __restrict__ gW0,const float* __restrict__ gb0,
                        const float* __restrict__ gW1,const float* __restrict__ gb1,
                        const float* __restrict__ gW2,const float* __restrict__ gb2,
                        float* __restrict__ out){
  __shared__ float s_g[256], s_h[256], s_red[8];
  int b=blockIdx.x, t=threadIdx.x;
  float cnt=fmaxf(d_gcnt[b],1.f);
  s_g[t]=d_gsum[b*F2+t]/cnt;
  __syncthreads();
  float a=gb0[t];
  #pragma unroll 8
  for(int p=0;p<256;p++) a+=s_g[p]*gW0[p*256+t];
  s_h[t]=siluf(a);
  __syncthreads();
  a=gb1[t];
  #pragma unroll 8
  for(int p=0;p<256;p++) a+=s_h[p]*gW1[p*256+t];
  float h=siluf(a);
  float v=h*gW2[t];
  #pragma unroll
  for(int o=16;o;o>>=1) v+=__shfl_xor_sync(0xffffffffu,v,o);
  if((t&31)==0) s_red[t>>5]=v;
  __syncthreads();
  if(t==0){ float tot=0.f;
    #pragma unroll
    for(int i=0;i<8;i++) tot+=s_red[i];
    out[b]=tot+gb2[0]; }
}

extern "C" void kernel_launch(void* const* d_in, const int* in_sizes, int n_in,
                              void* d_out, int out_size){
  const float* coords =(const float*)d_in[0];
  const int*   atomids=(const int*)d_in[1];
  const int*   eidx   =(const int*)d_in[2];
  const int*   batch  =(const int*)d_in[3];
  int s = (in_sizes[4]==11*DD) ? 4 : 5;
  const float* emb =(const float*)d_in[s+0];
  const float* keW1=(const float*)d_in[s+1];
  const float* keb1=(const float*)d_in[s+2];
  const float* keW2=(const float*)d_in[s+3];
  const float* keb2=(const float*)d_in[s+4];
  const float* keng=(const float*)d_in[s+5];
  const float* kenb=(const float*)d_in[s+6];
  const float* kn1g=(const float*)d_in[s+7];
  const float* kn1b=(const float*)d_in[s+8];
  const float* knW1=(const float*)d_in[s+9];
  const float* knb1=(const float*)d_in[s+10];
  const float* knW2=(const float*)d_in[s+11];
  const float* knb2=(const float*)d_in[s+12];
  const float* kn2g=(const float*)d_in[s+13];
  const float* kn2b=(const float*)d_in[s+14];
  const float* fW0 =(const float*)d_in[s+15];
  const float* fb0 =(const float*)d_in[s+16];
  const float* fW1 =(const float*)d_in[s+17];
  const float* fb1 =(const float*)d_in[s+18];
  const float* fW2 =(const float*)d_in[s+19];
  const float* fb2 =(const float*)d_in[s+20];
  const float* gW0 =(const float*)d_in[s+21];
  const float* gb0 =(const float*)d_in[s+22];
  const float* gW1 =(const float*)d_in[s+23];
  const float* gb1 =(const float*)d_in[s+24];
  const float* gW2 =(const float*)d_in[s+25];
  const float* gb2 =(const float*)d_in[s+26];
  float* out=(float*)d_out;

  const int EDGE_SM = 23592*4;                 // 94368
  const int NODE_SM = (10304+16448+16384)*4;   // 172544
  const int FNN_SM  = (128*RS + 2*64*RS)*4;    // 73728
  cudaFuncSetAttribute(k_edge,    cudaFuncAttributeMaxDynamicSharedMemorySize, EDGE_SM);
  cudaFuncSetAttribute(k_node,    cudaFuncAttributeMaxDynamicSharedMemorySize, NODE_SM);
  cudaFuncSetAttribute(k_fab_mma, cudaFuncAttributeMaxDynamicSharedMemorySize, FNN_SM);
  cudaFuncSetAttribute(k_fnn_mma, cudaFuncAttributeMaxDynamicSharedMemorySize, FNN_SM);

  k_zero_init<<<65,256>>>();
  k_feats<<<NN,128>>>(emb,atomids);
  k_deg<<<EE/256,256>>>(eidx);
  k_ea<<<EE/256,256>>>(coords,eidx);
  k_wprep<<<1320,256>>>(keW1,keW2);
  k_wprep_fab<<<3840,256>>>(keW1);
  k_wprep_fnn<<<1280,256>>>(fW0,fW1,fW2);
  for(int k=0;k<KK;k++){
    k_fab_mma<<<dim3(6,79,2),256,FNN_SM>>>(k);
    k_edge<<<EE/128,256,EDGE_SM>>>(eidx,keW1,keb1,keW2,keb2,keng,kenb,k);
    k_xcat<<<NN/8,256>>>(keng,kenb,kn1g,kn1b,k);
    k_node<<<157,256,NODE_SM>>>(knW1,knb1,knW2,knb2,kn2g,kn2b,k);
  }
  k_fnn_mma<<<dim3(2,79),256,FNN_SM>>>(fb0, 0);
  k_fnn_mma<<<dim3(2,79),256,FNN_SM>>>(fb1, 1);
  k_fnn_mma<<<dim3(2,79),256,FNN_SM>>>(fb2, 2);
  k_pool<<<NN,256>>>(batch);
  k_final<<<BB,256>>>(gW0,gb0,gW1,gb1,gW2,gb2,out);
}

// round 15
// speedup vs baseline: 1.2563x; 1.0016x over previous
#include <cuda_runtime.h>
#include <stdint.h>
#include <math.h>

#define NN 10000
#define EE 160000
#define BB 64
#define DD 128
#define MM 32
#define EINN 321
#define H1 642
#define KK 5
#define FH 768
#define F2 256
#define FASTRIDE 644

#define PERM(k) (((k)&3)*18 + ((k)>>2))
#define RS 72

__device__ float d_feats[NN*DD];
__device__ float d_eap[EE*RS];
__device__ float d_dcol[EE];
__device__ float d_deg[NN];
__device__ float d_FA[NN*FASTRIDE + 256];
__device__ float d_FB[NN*FASTRIDE + 256];
__device__ float d_msum[NN*MM];
__device__ float d_xcat[NN*160];
__device__ float d_fcat[NN*FH];
__device__ float d_f1[NN*F2];
__device__ float d_f2[NN*F2];
__device__ float d_gsum[BB*F2];
__device__ float d_gcnt[BB];
__device__ float d_w1p[KK*11*64*RS];
__device__ float d_w2p[KK*11*32*RS];
__device__ float d_wfabp[KK*2*12*2*64*RS];
__device__ float d_wf0p[4*12*64*RS];
__device__ float d_wf1p[4*4*64*RS];
__device__ float d_wf2p[4*4*64*RS];

__device__ __forceinline__ float siluf(float x){
  return __fdividef(x, 1.f+__expf(-x));
}
__device__ __forceinline__ float tf32r(float x){
  float r; asm("cvt.rna.tf32.f32 %0,%1;" : "=f"(r) : "f"(x)); return r;
}
__device__ __forceinline__ void mma8(float4 &c, unsigned a0,unsigned a1,unsigned a2,unsigned a3,
                                     unsigned b0,unsigned b1){
  asm("mma.sync.aligned.m16n8k8.row.col.f32.tf32.tf32.f32 "
      "{%0,%1,%2,%3},{%4,%5,%6,%7},{%8,%9},{%0,%1,%2,%3};"
      : "+f"(c.x),"+f"(c.y),"+f"(c.z),"+f"(c.w)
      : "r"(a0),"r"(a1),"r"(a2),"r"(a3),"r"(b0),"r"(b1));
}
__device__ __forceinline__ uint32_t s2u(const void* p){
  uint32_t a; asm("{ .reg .u64 t; cvta.to.shared.u64 t, %1; cvt.u32.u64 %0, t; }" : "=r"(a) : "l"(p)); return a;
}
__device__ __forceinline__ void cpa(uint32_t s, const void* g){
  asm volatile("cp.async.cg.shared.global [%0], [%1], 16;"::"r"(s),"l"(g):"memory");
}
#define CPA_COMMIT() asm volatile("cp.async.commit_group;":::"memory")
#define CPA_WAIT0()  asm volatile("cp.async.wait_group 0;":::"memory")

__global__ void k_zero_init(){
  int i = blockIdx.x*256+threadIdx.x;
  if(i<NN) d_deg[i]=0.f;
  if(i<BB*F2) d_gsum[i]=0.f;
  if(i<BB) d_gcnt[i]=0.f;
}
__global__ void k_feats(const float* __restrict__ emb, const int* __restrict__ atomids){
  int n=blockIdx.x; int c=threadIdx.x;
  float v=emb[atomids[n]*DD+c];
  d_feats[n*DD+c]=v;
  d_fcat[(size_t)n*FH+c]=v;
}
__global__ void k_deg(const int* __restrict__ eidx){
  int e=blockIdx.x*256+threadIdx.x;
  atomicAdd(&d_deg[eidx[EE+e]],1.f);
}
// edge attrs: compute into smem, coalesced copy out
__global__ void __launch_bounds__(256,2) k_ea(const float* __restrict__ coords, const int* __restrict__ eidx){
  extern __shared__ float s[];
  int tid=threadIdx.x;
  int e=blockIdx.x*256+tid;
  int si=eidx[e], t2=eidx[EE+e];
  float dx=coords[3*si]-coords[3*t2];
  float dy=coords[3*si+1]-coords[3*t2+1];
  float dz=coords[3*si+2]-coords[3*t2+2];
  float d=dx*dx+dy*dy+dz*dz;
  float* o=&s[tid*RS];
  #pragma unroll
  for(int i=0;i<32;i++){
    float sc=__uint_as_float((unsigned)(127-i)<<23);   // 2^-i
    float x=d*sc;
    float sv,cv; __sincosf(x,&sv,&cv);
    o[PERM(i)]=tf32r(sv); o[PERM(32+i)]=tf32r(cv);
  }
  d_dcol[e]=d;
  __syncthreads();
  float4* dst=(float4*)(d_eap + (size_t)blockIdx.x*256*RS);
  const float4* src=(const float4*)s;
  #pragma unroll
  for(int t=0;t<18;t++) dst[tid+256*t]=src[tid+256*t];
}

__global__ void k_wprep(const float* __restrict__ keW1, const float* __restrict__ keW2){
  int i = blockIdx.x*256+threadIdx.x;
  const int W1TOT = KK*11*64*64;
  const int W2TOT = KK*11*32*64;
  if(i < W1TOT){
    int kk=i&63; int n=(i>>6)&63; int ch=(i>>12)%11; int k=i/(64*64*11);
    int j=ch*64+n;
    float v = (j<H1)? tf32r(keW1[(size_t)k*EINN*H1 + (size_t)(256+kk)*H1 + j]) : 0.f;
    d_w1p[(size_t)(((k*11+ch)*64)+n)*RS + PERM(kk)] = v;
  } else if(i < W1TOT+W2TOT){
    int m=i-W1TOT;
    int kk=m&63; int n=(m>>6)&31; int ch=(m>>11)%11; int k=m/(32*64*11);
    int j=ch*64+kk;
    float v = (j<H1)? tf32r(keW2[(size_t)k*H1*MM + (size_t)j*MM + n]) : 0.f;
    d_w2p[(size_t)(((k*11+ch)*32)+n)*RS + PERM(kk)] = v;
  }
}
// FA/FB weights in gemm128 layout: [k][part][cc=12][kc=2][64n][RS]
__global__ void k_wprep_fab(const float* __restrict__ keW1){
  int i = blockIdx.x*256+threadIdx.x;
  int kk=i&63; int i2=i>>6;
  int n=i2&63; i2>>=6;
  int kc=i2&1; i2>>=1;
  int cc=i2%12; i2/=12;
  int part=i2&1; int k=i2>>1;
  int p = part*128 + kc*64 + kk;
  int col = cc*64 + n;
  float v = (col<H1)? tf32r(keW1[(size_t)k*EINN*H1 + (size_t)p*H1 + col]) : 0.f;
  d_wfabp[(size_t)((((k*2+part)*12+cc)*2+kc)*64 + n)*RS + PERM(kk)] = v;
}
__global__ void k_wprep_fnn(const float* __restrict__ fW0,
                            const float* __restrict__ fW1,
                            const float* __restrict__ fW2){
  int i = blockIdx.x*256+threadIdx.x;
  if(i < 196608){
    int kk=i&63; int n=(i>>6)&63; int r=i>>12;
    int kc=r%12, cc=r/12;
    d_wf0p[(size_t)((cc*12+kc)*64+n)*RS + PERM(kk)] =
      tf32r(fW0[(size_t)(kc*64+kk)*F2 + cc*64+n]);
  } else if(i < 262144){
    int j=i-196608;
    int kk=j&63; int n=(j>>6)&63; int r=j>>12;
    int kc=r&3, cc=r>>2;
    d_wf1p[(size_t)((cc*4+kc)*64+n)*RS + PERM(kk)] =
      tf32r(fW1[(size_t)(kc*64+kk)*F2 + cc*64+n]);
  } else {
    int j=i-262144;
    int kk=j&63; int n=(j>>6)&63; int r=j>>12;
    int kc=r&3, cc=r>>2;
    d_wf2p[(size_t)((cc*4+kc)*64+n)*RS + PERM(kk)] =
      tf32r(fW2[(size_t)(kc*64+kk)*F2 + cc*64+n]);
  }
}

// generic 128-row x 128-col tf32 MMA GEMM body
__device__ __forceinline__ void gemm128(const float* Wp, const float* in, int INST, int KC,
                                        int insilu, int n0, int cc0, float4* c1, float* sm){
  float* s_a = sm;
  float* s_b = sm + 128*RS;
  int tid=threadIdx.x;
  int w=tid>>5, l=tid&31, qr=l>>2, qc=l&3;
  int ra=w*16+qr, rb=ra+8, aoff=qc*18;
  for(int kc=0;kc<KC;kc++){
    __syncthreads();
    #pragma unroll
    for(int t=0;t<8;t++){
      int lin=tid+t*256;
      int r=lin>>4, c4=(lin&15)*4;
      int n=n0+r;
      float4 v = (n<NN)? *(const float4*)(in + (size_t)n*INST + kc*64 + c4) : make_float4(0,0,0,0);
      if(insilu){ v.x=siluf(v.x); v.y=siluf(v.y); v.z=siluf(v.z); v.w=siluf(v.w); }
      float* dst = s_a + r*RS + (c4>>2);
      dst[0]=tf32r(v.x); dst[18]=tf32r(v.y); dst[36]=tf32r(v.z); dst[54]=tf32r(v.w);
    }
    {
      const float4* s0=(const float4*)(Wp + (size_t)(cc0*KC+kc)*(64*RS));
      const float4* s1=(const float4*)(Wp + (size_t)((cc0+1)*KC+kc)*(64*RS));
      float4* d0=(float4*)s_b;
      float4* d1=(float4*)(s_b+64*RS);
      #pragma unroll
      for(int t=0;t<5;t++){ int i=tid+t*256; if(i<1152){ d0[i]=s0[i]; d1[i]=s1[i]; } }
    }
    __syncthreads();
    #pragma unroll
    for(int ks=0;ks<8;ks++){
      float2 A0=*(float2*)(s_a+ra*RS+aoff+2*ks);
      float2 A1=*(float2*)(s_a+rb*RS+aoff+2*ks);
      unsigned a0=__float_as_uint(A0.x), a2=__float_as_uint(A0.y);
      unsigned a1=__float_as_uint(A1.x), a3=__float_as_uint(A1.y);
      #pragma unroll
      for(int nt=0;nt<16;nt++){
        float* sb = s_b + (nt>>3)*(64*RS);
        float2 Bv=*(float2*)(sb+((nt&7)*8+qr)*RS+aoff+2*ks);
        mma8(c1[nt],a0,a1,a2,a3,__float_as_uint(Bv.x),__float_as_uint(Bv.y));
      }
    }
  }
}

// FA/FB via gemm128: grid (6,79,2); also zeroes d_msum
__global__ void __launch_bounds__(256,2) k_fab_mma(int k){
  extern __shared__ float sm[];
  int tid=threadIdx.x;
  for(int gi=(blockIdx.x+6*(blockIdx.y+79*(int)blockIdx.z))*256+tid; gi<NN*MM; gi+=948*256)
    d_msum[gi]=0.f;
  int part=blockIdx.z;
  int n0=blockIdx.y*128, cc0=blockIdx.x*2;
  const float* Wp = d_wfabp + (size_t)(k*2+part)*(12*2*64*RS);
  float4 c1[16];
  #pragma unroll
  for(int t=0;t<16;t++) c1[t]=make_float4(0,0,0,0);
  gemm128(Wp, d_feats, 128, 2, 0, n0, cc0, c1, sm);
  float* OUT = part? d_FB : d_FA;
  int w=tid>>5, l=tid&31, qr=l>>2, qc=l&3;
  int na=n0+w*16+qr, nb2=na+8;
  #pragma unroll
  for(int nt=0;nt<16;nt++){
    int col = cc0*64 + nt*8 + 2*qc;
    if(col<642){
      if(na<NN)  *(float2*)(OUT+(size_t)na*FASTRIDE+col)=make_float2(c1[nt].x,c1[nt].y);
      if(nb2<NN) *(float2*)(OUT+(size_t)nb2*FASTRIDE+col)=make_float2(c1[nt].z,c1[nt].w);
    }
  }
}

__global__ void __launch_bounds__(256,2) k_fnn_mma(const float* __restrict__ bias, int stage){
  const float* Wp = (stage==0)? d_wf0p : ((stage==1)? d_wf1p : d_wf2p);
  const float* in = (stage==0)? d_fcat : ((stage==1)? d_f1 : d_f2);
  float* out      = (stage==1)? d_f2 : d_f1;
  int KC          = (stage==0)? 12 : 4;
  extern __shared__ float sm[];
  int n0 = blockIdx.y*128, cc0 = blockIdx.x*2;
  float4 c1[16];
  #pragma unroll
  for(int t=0;t<16;t++) c1[t]=make_float4(0,0,0,0);
  gemm128(Wp, in, KC*64, KC, stage==0, n0, cc0, c1, sm);
  int tid=threadIdx.x, w=tid>>5, l=tid&31, qr=l>>2, qc=l&3;
  int na=n0+w*16+qr, nb2=na+8;
  #pragma unroll
  for(int nt=0;nt<16;nt++){
    int col = cc0*64 + nt*8 + 2*qc;
    float b0=__ldg(&bias[col]), b1=__ldg(&bias[col+1]);
    if(na<NN)  *(float2*)(out+(size_t)na*F2+col)=make_float2(siluf(c1[nt].x+b0),siluf(c1[nt].y+b1));
    if(nb2<NN) *(float2*)(out+(size_t)nb2*F2+col)=make_float2(siluf(c1[nt].z+b0),siluf(c1[nt].w+b1));
  }
}

// ---------- edge MLP: 10 MMA chunks + scalar tail for cols 640/641 ----------
__global__ void __launch_bounds__(256,2) k_edge(const int* __restrict__ eidx,
   const float* __restrict__ keW1,const float* __restrict__ keb1,
   const float* __restrict__ keW2r,const float* __restrict__ keb2,
   const float* __restrict__ keng,const float* __restrict__ kenb,int k){
  extern __shared__ float sm[];
  float* s_h  = sm;                    // 128*72
  float* s_w1 = sm + 9216;             // 2 x 4608
  float* s_w2 = sm + 18432;            // 2 x 2304
  float* s_w1d= sm + 23040;            // 2 x 64
  float* s_b1 = sm + 23168;            // 2 x 64
  float* s_b2 = sm + 23296;
  float* s_g  = sm + 23328;
  float* s_bt = sm + 23360;
  float* s_w1t= sm + 23392;            // 128
  float* s_w2t= sm + 23520;            // 64
  float* s_sc = sm + 23584;            // 4
  int tid=threadIdx.x, w=tid>>5, l=tid&31, qr=l>>2, qc=l&3;
  int e0=blockIdx.x*128;
  int ra=w*16+qr, rb=ra+8, aoff=qc*18;
  uint32_t sbu=s2u(sm);
  const float* W1c = keW1 + (size_t)k*EINN*H1 + (size_t)256*H1;
  const float* B1  = keb1 + (size_t)k*H1;
  float2 eA[8], eB[8];
  {
    const float* pA=d_eap+(size_t)(e0+ra)*RS+aoff;
    const float* pB=d_eap+(size_t)(e0+rb)*RS+aoff;
    #pragma unroll
    for(int ks=0;ks<8;ks++){ eA[ks]=*(const float2*)(pA+2*ks); eB[ks]=*(const float2*)(pB+2*ks); }
  }
  int nda=eidx[EE+e0+ra], nsa=eidx[e0+ra];
  int ndb=eidx[EE+e0+rb], nsb=eidx[e0+rb];
  float da=d_dcol[e0+ra], db=d_dcol[e0+rb];
  if(tid<32){ s_b2[tid]=keb2[k*MM+tid]; s_g[tid]=keng[k*MM+tid]; s_bt[tid]=kenb[k*MM+tid]; }
  if(tid<128){ int kk=tid>>1, j=tid&1; s_w1t[tid]=W1c[(size_t)kk*H1+640+j]; }
  else if(tid<192){ int m=tid-128; int j=m>>5, n=m&31;
    s_w2t[m]=keW2r[(size_t)k*H1*MM + (size_t)(640+j)*MM + n]; }
  else if(tid<196){ int m=tid-192;
    s_sc[m] = (m<2)? B1[640+m] : W1c[(size_t)64*H1+640+(m-2)]; }

  auto stage=[&](int ch,int buf){
    const float4* w1s=(const float4*)(d_w1p + (size_t)((k*11+ch)*64)*RS);
    uint32_t w1a = sbu + (9216+buf*4608)*4;
    #pragma unroll
    for(int i=0;i<4;i++) cpa(w1a+(tid+256*i)*16, w1s+tid+256*i);
    if(tid<128) cpa(w1a+(1024+tid)*16, w1s+1024+tid);
    const float4* w2s=(const float4*)(d_w2p + (size_t)((k*11+ch)*32)*RS);
    uint32_t w2a = sbu + (18432+buf*2304)*4;
    #pragma unroll
    for(int i=0;i<2;i++) cpa(w2a+(tid+256*i)*16, w2s+tid+256*i);
    if(tid<64){
      cpa(w2a+(512+tid)*16, w2s+512+tid);
      int j=ch*64+tid;
      s_b1[buf*64+tid]=B1[j];
      s_w1d[buf*64+tid]=W1c[(size_t)64*H1+j];
    }
  };
  stage(0,0); CPA_COMMIT();

  float4 c2[4];
  #pragma unroll
  for(int t=0;t<4;t++) c2[t]=make_float4(0.f,0.f,0.f,0.f);

  for(int ch=0; ch<10; ch++){
    int buf=ch&1;
    CPA_WAIT0();
    __syncthreads();
    if(ch<9){ stage(ch+1,1-buf); CPA_COMMIT(); }
    float* w1b = s_w1 + buf*4608;
    float* w2b = s_w2 + buf*2304;
    float* b1b = s_b1 + buf*64;
    float* wdb = s_w1d + buf*64;
    int jc0=ch*64;
    float4 c1[8];
    #pragma unroll
    for(int t=0;t<8;t++) c1[t]=make_float4(0.f,0.f,0.f,0.f);
    #pragma unroll
    for(int ks=0;ks<8;ks++){
      unsigned a0=__float_as_uint(eA[ks].x), a2=__float_as_uint(eA[ks].y);
      unsigned a1=__float_as_uint(eB[ks].x), a3=__float_as_uint(eB[ks].y);
      #pragma unroll
      for(int nt=0;nt<8;nt++){
        float2 Bv=*(float2*)(w1b+(nt*8+qr)*RS+aoff+2*ks);
        mma8(c1[nt],a0,a1,a2,a3,__float_as_uint(Bv.x),__float_as_uint(Bv.y));
      }
    }
    {
      const float* FAa=d_FA+(size_t)nda*FASTRIDE+jc0;
      const float* FBa=d_FB+(size_t)nsa*FASTRIDE+jc0;
      const float* FAb=d_FA+(size_t)ndb*FASTRIDE+jc0;
      const float* FBb=d_FB+(size_t)nsb*FASTRIDE+jc0;
      #pragma unroll
      for(int nt=0;nt<8;nt++){
        int col0=nt*8+2*qc;
        float2 faa=*(const float2*)(FAa+col0);
        float2 fba=*(const float2*)(FBa+col0);
        float2 fab=*(const float2*)(FAb+col0);
        float2 fbb=*(const float2*)(FBb+col0);
        float b0=b1b[col0], b1f=b1b[col0+1];
        float w0=wdb[col0], w1v=wdb[col0+1];
        int p0=((col0&3)*18) + (col0>>2);
        s_h[ra*RS+p0]   =tf32r(siluf(c1[nt].x+b0 +da*w0 +faa.x+fba.x));
        s_h[ra*RS+p0+18]=tf32r(siluf(c1[nt].y+b1f+da*w1v+faa.y+fba.y));
        s_h[rb*RS+p0]   =tf32r(siluf(c1[nt].z+b0 +db*w0 +fab.x+fbb.x));
        s_h[rb*RS+p0+18]=tf32r(siluf(c1[nt].w+b1f+db*w1v+fab.y+fbb.y));
      }
    }
    __syncwarp();
    #pragma unroll
    for(int ks=0;ks<8;ks++){
      float2 A0=*(float2*)(s_h+ra*RS+aoff+2*ks);
      float2 A1=*(float2*)(s_h+rb*RS+aoff+2*ks);
      unsigned a0=__float_as_uint(A0.x), a2=__float_as_uint(A0.y);
      unsigned a1=__float_as_uint(A1.x), a3=__float_as_uint(A1.y);
      #pragma unroll
      for(int nt=0;nt<4;nt++){
        float2 Bv=*(float2*)(w2b+(nt*8+qr)*RS+aoff+2*ks);
        mma8(c2[nt],a0,a1,a2,a3,__float_as_uint(Bv.x),__float_as_uint(Bv.y));
      }
    }
  }
  // scalar tail: H1 cols 640, 641
  {
    float p0a=0,p1a=0,p0b=0,p1b=0;
    #pragma unroll
    for(int ks=0;ks<8;ks++){
      int k1=8*ks+qc, k2=k1+4;
      p0a+=eA[ks].x*s_w1t[2*k1]  +eA[ks].y*s_w1t[2*k2];
      p1a+=eA[ks].x*s_w1t[2*k1+1]+eA[ks].y*s_w1t[2*k2+1];
      p0b+=eB[ks].x*s_w1t[2*k1]  +eB[ks].y*s_w1t[2*k2];
      p1b+=eB[ks].x*s_w1t[2*k1+1]+eB[ks].y*s_w1t[2*k2+1];
    }
    #pragma unroll
    for(int o=1;o<4;o<<=1){
      p0a+=__shfl_xor_sync(0xffffffffu,p0a,o); p1a+=__shfl_xor_sync(0xffffffffu,p1a,o);
      p0b+=__shfl_xor_sync(0xffffffffu,p0b,o); p1b+=__shfl_xor_sync(0xffffffffu,p1b,o);
    }
    float h0a=siluf(p0a+s_sc[0]+da*s_sc[2]+d_FA[(size_t)nda*FASTRIDE+640]+d_FB[(size_t)nsa*FASTRIDE+640]);
    float h1a=siluf(p1a+s_sc[1]+da*s_sc[3]+d_FA[(size_t)nda*FASTRIDE+641]+d_FB[(size_t)nsa*FASTRIDE+641]);
    float h0b=siluf(p0b+s_sc[0]+db*s_sc[2]+d_FA[(size_t)ndb*FASTRIDE+640]+d_FB[(size_t)nsb*FASTRIDE+640]);
    float h1b=siluf(p1b+s_sc[1]+db*s_sc[3]+d_FA[(size_t)ndb*FASTRIDE+641]+d_FB[(size_t)nsb*FASTRIDE+641]);
    #pragma unroll
    for(int nt=0;nt<4;nt++){
      int col0=nt*8+2*qc;
      c2[nt].x += h0a*s_w2t[col0]  +h1a*s_w2t[32+col0];
      c2[nt].y += h0a*s_w2t[col0+1]+h1a*s_w2t[32+col0+1];
      c2[nt].z += h0b*s_w2t[col0]  +h1b*s_w2t[32+col0];
      c2[nt].w += h0b*s_w2t[col0+1]+h1b*s_w2t[32+col0+1];
    }
  }
  float va[8], vb[8];
  #pragma unroll
  for(int nt=0;nt<4;nt++){
    int col0=nt*8+2*qc;
    va[2*nt]  =siluf(c2[nt].x+s_b2[col0]);
    va[2*nt+1]=siluf(c2[nt].y+s_b2[col0+1]);
    vb[2*nt]  =siluf(c2[nt].z+s_b2[col0]);
    vb[2*nt+1]=siluf(c2[nt].w+s_b2[col0+1]);
  }
  float sa=0.f,ssa=0.f,sb=0.f,ssb=0.f;
  #pragma unroll
  for(int i=0;i<8;i++){ sa+=va[i]; ssa+=va[i]*va[i]; sb+=vb[i]; ssb+=vb[i]*vb[i]; }
  #pragma unroll
  for(int o=1;o<4;o<<=1){
    sa+=__shfl_xor_sync(0xffffffffu,sa,o); ssa+=__shfl_xor_sync(0xffffffffu,ssa,o);
    sb+=__shfl_xor_sync(0xffffffffu,sb,o); ssb+=__shfl_xor_sync(0xffffffffu,ssb,o);
  }
  float mua=sa*(1.f/MM), vara=ssa*(1.f/MM)-mua*mua, inva=rsqrtf(vara+1e-5f);
  float mub=sb*(1.f/MM), varb=ssb*(1.f/MM)-mub*mub, invb=rsqrtf(varb+1e-5f);
  float* pa=&d_msum[(size_t)nda*MM];
  float* pb=&d_msum[(size_t)ndb*MM];
  #pragma unroll
  for(int nt=0;nt<4;nt++){
    int col0=nt*8+2*qc;
    atomicAdd(pa+col0,  (va[2*nt]  -mua)*inva*s_g[col0]  +s_bt[col0]);
    atomicAdd(pa+col0+1,(va[2*nt+1]-mua)*inva*s_g[col0+1]+s_bt[col0+1]);
    atomicAdd(pb+col0,  (vb[2*nt]  -mub)*invb*s_g[col0]  +s_bt[col0]);
    atomicAdd(pb+col0+1,(vb[2*nt+1]-mub)*invb*s_g[col0+1]+s_bt[col0+1]);
  }
}

__global__ void k_xcat(const float* __restrict__ keng,const float* __restrict__ kenb,
                       const float* __restrict__ kn1g,const float* __restrict__ kn1b,int k){
  int warp=threadIdx.x>>5, lane=threadIdx.x&31;
  int n=blockIdx.x*8+warp;
  const float* g1=kn1g+(size_t)k*128; const float* b1=kn1b+(size_t)k*128;
  float v[4],s=0.f,ss=0.f;
  #pragma unroll
  for(int i=0;i<4;i++){ float x=d_feats[(size_t)n*128+lane+32*i]; v[i]=x; s+=x; ss+=x*x; }
  #pragma unroll
  for(int o=16;o;o>>=1){ s+=__shfl_xor_sync(0xffffffffu,s,o); ss+=__shfl_xor_sync(0xffffffffu,ss,o); }
  float mu=s*(1.f/128), var=ss*(1.f/128)-mu*mu, inv=rsqrtf(var+1e-5f);
  #pragma unroll
  for(int i=0;i<4;i++){ int c=lane+32*i; d_xcat[(size_t)n*160+c]=(v[i]-mu)*inv*g1[c]+b1[c]; }
  float m=d_msum[(size_t)n*MM+lane]/fmaxf(d_deg[n],1.f);
  float s2=m, ss2=m*m;
  #pragma unroll
  for(int o=16;o;o>>=1){ s2+=__shfl_xor_sync(0xffffffffu,s2,o); ss2+=__shfl_xor_sync(0xffffffffu,ss2,o); }
  float mu2=s2*(1.f/MM), var2=ss2*(1.f/MM)-mu2*mu2, inv2=rsqrtf(var2+1e-5f);
  d_xcat[(size_t)n*160+128+lane]=(m-mu2)*inv2*keng[k*MM+lane]+kenb[k*MM+lane];
}

// node MLP: 32 nodes/block, 2 blocks/SM
__global__ void __launch_bounds__(256) k_node(const float* __restrict__ knW1,const float* __restrict__ knb1,
    const float* __restrict__ knW2,const float* __restrict__ knb2,
    const float* __restrict__ kn2g,const float* __restrict__ kn2b,int k){
  extern __shared__ float sm[];
  float* s_x=sm;            // 32*161 = 5152
  float* s_h=sm+5152;       // 32*257 = 8224
  float* s_w=sm+13376;      // max(160*64, 128*64) = 10240
  int tid=threadIdx.x;
  int n0=blockIdx.x*32;
  const float* W1=knW1+(size_t)k*160*256;
  const float* B1=knb1+(size_t)k*256;
  const float* W2=knW2+(size_t)k*256*128;
  const float* B2=knb2+(size_t)k*128;
  const float* G =kn2g+(size_t)k*128;
  const float* BT=kn2b+(size_t)k*128;
  for(int i=tid;i<32*160;i+=256){int r=i/160,c=i-r*160;int n=n0+r; s_x[r*161+c]= (n<NN)? d_xcat[(size_t)n*160+c]:0.f;}
  int r0=(tid>>4)*2, c0=(tid&15)*4;
  for(int oc=0;oc<4;oc++){
    __syncthreads();
    for(int i=tid;i<160*64;i+=256){int p=i>>6,c=i&63; s_w[i]=W1[(size_t)p*256+oc*64+c];}
    __syncthreads();
    float a4[2][4];
    #pragma unroll
    for(int i=0;i<2;i++){a4[i][0]=0;a4[i][1]=0;a4[i][2]=0;a4[i][3]=0;}
    for(int p=0;p<160;p++){
      float4 w=*(float4*)(s_w+p*64+c0);
      #pragma unroll
      for(int i=0;i<2;i++){ float a=s_x[(r0+i)*161+p];
        a4[i][0]+=a*w.x; a4[i][1]+=a*w.y; a4[i][2]+=a*w.z; a4[i][3]+=a*w.w; }
    }
    #pragma unroll
    for(int i=0;i<2;i++){
      #pragma unroll
      for(int j=0;j<4;j++){ int col=oc*64+c0+j;
        s_h[(r0+i)*257+col]=siluf(a4[i][j]+__ldg(&B1[col])); }
    }
  }
  for(int oc=0;oc<2;oc++){
    float a4[2][4];
    #pragma unroll
    for(int i=0;i<2;i++){a4[i][0]=0;a4[i][1]=0;a4[i][2]=0;a4[i][3]=0;}
    for(int rc=0;rc<2;rc++){
      __syncthreads();
      for(int i=tid;i<128*64;i+=256){int p=i>>6,c=i&63; s_w[i]=W2[(size_t)(rc*128+p)*128+oc*64+c];}
      __syncthreads();
      for(int p=0;p<128;p++){
        float4 w=*(float4*)(s_w+p*64+c0);
        #pragma unroll
        for(int i=0;i<2;i++){ float a=s_h[(r0+i)*257+rc*128+p];
          a4[i][0]+=a*w.x; a4[i][1]+=a*w.y; a4[i][2]+=a*w.z; a4[i][3]+=a*w.w; }
      }
    }
    #pragma unroll
    for(int i=0;i<2;i++){
      #pragma unroll
      for(int j=0;j<4;j++){ int col=oc*64+c0+j;
        s_x[(r0+i)*129+col]=a4[i][j]+__ldg(&B2[col]); }
    }
  }
  __syncthreads();
  int w=tid>>5, lane=tid&31;
  for(int rr=w; rr<32; rr+=8){
    int n=n0+rr;
    float v[4],s=0.f,ss=0.f;
    #pragma unroll
    for(int i=0;i<4;i++){ float x=s_x[rr*129+lane+32*i]; v[i]=x; s+=x; ss+=x*x; }
    #pragma unroll
    for(int o=16;o;o>>=1){ s+=__shfl_xor_sync(0xffffffffu,s,o); ss+=__shfl_xor_sync(0xffffffffu,ss,o); }
    float mu=s*(1.f/128), var=ss*(1.f/128)-mu*mu, inv=rsqrtf(var+1e-5f);
    if(n<NN){
      #pragma unroll
      for(int i=0;i<4;i++){ int c=lane+32*i;
        float nv=(v[i]-mu)*inv*G[c]+BT[c];
        float f=d_feats[(size_t)n*128+c]+nv;
        d_feats[(size_t)n*128+c]=f;
        d_fcat[(size_t)n*FH+(size_t)(k+1)*128+c]=f; }
    }
  }
}

__global__ void k_pool(const int* __restrict__ batch){
  int n=blockIdx.x; int c=threadIdx.x;
  int b=batch[n];
  atomicAdd(&d_gsum[b*F2+c], d_f1[(size_t)n*F2+c]);
  if(c==0) atomicAdd(&d_gcnt[b],1.f);
}

__global__ void k_final(const float* __restrict__ gW0,const float* __restrict__ gb0,
                        const float* __restrict__ gW1,const float* __restrict__ gb1,
                        const float* __restrict__ gW2,const float* __restrict__ gb2,
                        float* __restrict__ out){
  __shared__ float s_g[256], s_h[256], s_red[8];
  int b=blockIdx.x, t=threadIdx.x;
  float cnt=fmaxf(d_gcnt[b],1.f);
  s_g[t]=d_gsum[b*F2+t]/cnt;
  __syncthreads();
  float a=gb0[t];
  #pragma unroll 8
  for(int p=0;p<256;p++) a+=s_g[p]*gW0[p*256+t];
  s_h[t]=siluf(a);
  __syncthreads();
  a=gb1[t];
  #pragma unroll 8
  for(int p=0;p<256;p++) a+=s_h[p]*gW1[p*256+t];
  float h=siluf(a);
  float v=h*gW2[t];
  #pragma unroll
  for(int o=16;o;o>>=1) v+=__shfl_xor_sync(0xffffffffu,v,o);
  if((t&31)==0) s_red[t>>5]=v;
  __syncthreads();
  if(t==0){ float tot=0.f;
    #pragma unroll
    for(int i=0;i<8;i++) tot+=s_red[i];
    out[b]=tot+gb2[0]; }
}

extern "C" void kernel_launch(void* const* d_in, const int* in_sizes, int n_in,
                              void* d_out, int out_size){
  const float* coords =(const float*)d_in[0];
  const int*   atomids=(const int*)d_in[1];
  const int*   eidx   =(const int*)d_in[2];
  const int*   batch  =(const int*)d_in[3];
  int s = (in_sizes[4]==11*DD) ? 4 : 5;
  const float* emb =(const float*)d_in[s+0];
  const float* keW1=(const float*)d_in[s+1];
  const float* keb1=(const float*)d_in[s+2];
  const float* keW2=(const float*)d_in[s+3];
  const float* keb2=(const float*)d_in[s+4];
  const float* keng=(const float*)d_in[s+5];
  const float* kenb=(const float*)d_in[s+6];
  const float* kn1g=(const float*)d_in[s+7];
  const float* kn1b=(const float*)d_in[s+8];
  const float* knW1=(const float*)d_in[s+9];
  const float* knb1=(const float*)d_in[s+10];
  const float* knW2=(const float*)d_in[s+11];
  const float* knb2=(const float*)d_in[s+12];
  const float* kn2g=(const float*)d_in[s+13];
  const float* kn2b=(const float*)d_in[s+14];
  const float* fW0 =(const float*)d_in[s+15];
  const float* fb0 =(const float*)d_in[s+16];
  const float* fW1 =(const float*)d_in[s+17];
  const float* fb1 =(const float*)d_in[s+18];
  const float* fW2 =(const float*)d_in[s+19];
  const float* fb2 =(const float*)d_in[s+20];
  const float* gW0 =(const float*)d_in[s+21];
  const float* gb0 =(const float*)d_in[s+22];
  const float* gW1 =(const float*)d_in[s+23];
  const float* gb1 =(const float*)d_in[s+24];
  const float* gW2 =(const float*)d_in[s+25];
  const float* gb2 =(const float*)d_in[s+26];
  float* out=(float*)d_out;

  const int EDGE_SM = 23592*4;                 // 94368
  const int NODE_SM = (5152+8224+10240)*4;     // 94464
  const int FNN_SM  = (128*RS + 2*64*RS)*4;    // 73728
  const int EA_SM   = 256*RS*4;                // 73728
  cudaFuncSetAttribute(k_edge,    cudaFuncAttributeMaxDynamicSharedMemorySize, EDGE_SM);
  cudaFuncSetAttribute(k_node,    cudaFuncAttributeMaxDynamicSharedMemorySize, NODE_SM);
  cudaFuncSetAttribute(k_fab_mma, cudaFuncAttributeMaxDynamicSharedMemorySize, FNN_SM);
  cudaFuncSetAttribute(k_fnn_mma, cudaFuncAttributeMaxDynamicSharedMemorySize, FNN_SM);
  cudaFuncSetAttribute(k_ea,      cudaFuncAttributeMaxDynamicSharedMemorySize, EA_SM);

  k_zero_init<<<65,256>>>();
  k_feats<<<NN,128>>>(emb,atomids);
  k_deg<<<EE/256,256>>>(eidx);
  k_ea<<<EE/256,256,EA_SM>>>(coords,eidx);
  k_wprep<<<1320,256>>>(keW1,keW2);
  k_wprep_fab<<<3840,256>>>(keW1);
  k_wprep_fnn<<<1280,256>>>(fW0,fW1,fW2);
  for(int k=0;k<KK;k++){
    k_fab_mma<<<dim3(6,79,2),256,FNN_SM>>>(k);
    k_edge<<<EE/128,256,EDGE_SM>>>(eidx,keW1,keb1,keW2,keb2,keng,kenb,k);
    k_xcat<<<NN/8,256>>>(keng,kenb,kn1g,kn1b,k);
    k_node<<<313,256,NODE_SM>>>(knW1,knb1,knW2,knb2,kn2g,kn2b,k);
  }
  k_fnn_mma<<<dim3(2,79),256,FNN_SM>>>(fb0, 0);
  k_fnn_mma<<<dim3(2,79),256,FNN_SM>>>(fb1, 1);
  k_fnn_mma<<<dim3(2,79),256,FNN_SM>>>(fb2, 2);
  k_pool<<<NN,256>>>(batch);
  k_final<<<BB,256>>>(gW0,gb0,gW1,gb1,gW2,gb2,out);
}

// round 16
// speedup vs baseline: 1.3349x; 1.0626x over previous
#include <cuda_runtime.h>
#include <stdint.h>
#include <math.h>

#define NN 10000
#define EE 160000
#define BB 64
#define DD 128
#define MM 32
#define EINN 321
#define H1 642
#define KK 5
#define FH 768
#define F2 256
#define FASTRIDE 644

#define PERM(k) (((k)&3)*18 + ((k)>>2))
#define RS 72

__device__ float d_feats[NN*DD];
__device__ float d_eap[EE*RS];
__device__ float d_dcol[EE];
__device__ float d_deg[NN];
__device__ int   d_hist[NN];
__device__ int   d_base[NN];
__device__ int   d_cur[NN];
__device__ int   d_srcs[EE];
__device__ int   d_dsts[EE];
__device__ float d_FA[NN*FASTRIDE + 256];
__device__ float d_FB[NN*FASTRIDE + 256];
__device__ float d_msum[NN*MM];
__device__ float d_xcat[NN*160];
__device__ float d_fcat[NN*FH];
__device__ float d_f1[NN*F2];
__device__ float d_f2[NN*F2];
__device__ float d_gsum[BB*F2];
__device__ float d_gcnt[BB];
__device__ float d_w1p[KK*11*64*RS];
__device__ float d_w2p[KK*11*32*RS];
__device__ float d_wfabp[KK*2*12*2*64*RS];
__device__ float d_wf0p[4*12*64*RS];
__device__ float d_wf1p[4*4*64*RS];
__device__ float d_wf2p[4*4*64*RS];

__device__ __forceinline__ float siluf(float x){
  return __fdividef(x, 1.f+__expf(-x));
}
__device__ __forceinline__ float tf32r(float x){
  float r; asm("cvt.rna.tf32.f32 %0,%1;" : "=f"(r) : "f"(x)); return r;
}
__device__ __forceinline__ void mma8(float4 &c, unsigned a0,unsigned a1,unsigned a2,unsigned a3,
                                     unsigned b0,unsigned b1){
  asm("mma.sync.aligned.m16n8k8.row.col.f32.tf32.tf32.f32 "
      "{%0,%1,%2,%3},{%4,%5,%6,%7},{%8,%9},{%0,%1,%2,%3};"
      : "+f"(c.x),"+f"(c.y),"+f"(c.z),"+f"(c.w)
      : "r"(a0),"r"(a1),"r"(a2),"r"(a3),"r"(b0),"r"(b1));
}
__device__ __forceinline__ uint32_t s2u(const void* p){
  uint32_t a; asm("{ .reg .u64 t; cvta.to.shared.u64 t, %1; cvt.u32.u64 %0, t; }" : "=r"(a) : "l"(p)); return a;
}
__device__ __forceinline__ void cpa(uint32_t s, const void* g){
  asm volatile("cp.async.cg.shared.global [%0], [%1], 16;"::"r"(s),"l"(g):"memory");
}
#define CPA_COMMIT() asm volatile("cp.async.commit_group;":::"memory")
#define CPA_WAIT0()  asm volatile("cp.async.wait_group 0;":::"memory")

__global__ void k_zero_init(){
  int i = blockIdx.x*256+threadIdx.x;
  if(i<NN){ d_deg[i]=0.f; d_hist[i]=0; d_cur[i]=0; }
  if(i<BB*F2) d_gsum[i]=0.f;
  if(i<BB) d_gcnt[i]=0.f;
}
__global__ void k_hist(const int* __restrict__ eidx){
  int e=blockIdx.x*256+threadIdx.x;
  int dst=eidx[EE+e];
  atomicAdd(&d_hist[dst],1);
  atomicAdd(&d_deg[dst],1.f);
}
// exclusive prefix sum over NN bins: 1 block, 1024 threads, 10 bins/thread
__global__ void k_scan(){
  __shared__ int part[1024];
  int tid=threadIdx.x;
  int base=tid*10;
  int loc[10]; int s=0;
  #pragma unroll
  for(int i=0;i<10;i++){ int v=(base+i<NN)? d_hist[base+i] : 0; loc[i]=s; s+=v; }
  part[tid]=s;
  __syncthreads();
  for(int off=1;off<1024;off<<=1){
    int v=0;
    if(tid>=off) v=part[tid-off];
    __syncthreads();
    if(tid>=off) part[tid]+=v;
    __syncthreads();
  }
  int pre = (tid>0)? part[tid-1] : 0;
  #pragma unroll
  for(int i=0;i<10;i++){ if(base+i<NN) d_base[base+i]=pre+loc[i]; }
}
__global__ void k_scatter(const int* __restrict__ eidx){
  int e=blockIdx.x*256+threadIdx.x;
  int dst=eidx[EE+e];
  int p=d_base[dst]+atomicAdd(&d_cur[dst],1);
  d_srcs[p]=eidx[e];
  d_dsts[p]=dst;
}
__global__ void k_feats(const float* __restrict__ emb, const int* __restrict__ atomids){
  int n=blockIdx.x; int c=threadIdx.x;
  float v=emb[atomids[n]*DD+c];
  d_feats[n*DD+c]=v;
  d_fcat[(size_t)n*FH+c]=v;
}
// edge attrs in sorted order: compute into smem, coalesced copy out
__global__ void __launch_bounds__(256,2) k_ea(const float* __restrict__ coords){
  extern __shared__ float s[];
  int tid=threadIdx.x;
  int e=blockIdx.x*256+tid;
  int si=d_srcs[e], t2=d_dsts[e];
  float dx=coords[3*si]-coords[3*t2];
  float dy=coords[3*si+1]-coords[3*t2+1];
  float dz=coords[3*si+2]-coords[3*t2+2];
  float d=dx*dx+dy*dy+dz*dz;
  float* o=&s[tid*RS];
  #pragma unroll
  for(int i=0;i<32;i++){
    float sc=__uint_as_float((unsigned)(127-i)<<23);   // 2^-i
    float x=d*sc;
    float sv,cv; __sincosf(x,&sv,&cv);
    o[PERM(i)]=tf32r(sv); o[PERM(32+i)]=tf32r(cv);
  }
  d_dcol[e]=d;
  __syncthreads();
  float4* dst=(float4*)(d_eap + (size_t)blockIdx.x*256*RS);
  const float4* src=(const float4*)s;
  #pragma unroll
  for(int t=0;t<18;t++) dst[tid+256*t]=src[tid+256*t];
}

__global__ void k_wprep(const float* __restrict__ keW1, const float* __restrict__ keW2){
  int i = blockIdx.x*256+threadIdx.x;
  const int W1TOT = KK*11*64*64;
  const int W2TOT = KK*11*32*64;
  if(i < W1TOT){
    int kk=i&63; int n=(i>>6)&63; int ch=(i>>12)%11; int k=i/(64*64*11);
    int j=ch*64+n;
    float v = (j<H1)? tf32r(keW1[(size_t)k*EINN*H1 + (size_t)(256+kk)*H1 + j]) : 0.f;
    d_w1p[(size_t)(((k*11+ch)*64)+n)*RS + PERM(kk)] = v;
  } else if(i < W1TOT+W2TOT){
    int m=i-W1TOT;
    int kk=m&63; int n=(m>>6)&31; int ch=(m>>11)%11; int k=m/(32*64*11);
    int j=ch*64+kk;
    float v = (j<H1)? tf32r(keW2[(size_t)k*H1*MM + (size_t)j*MM + n]) : 0.f;
    d_w2p[(size_t)(((k*11+ch)*32)+n)*RS + PERM(kk)] = v;
  }
}
__global__ void k_wprep_fab(const float* __restrict__ keW1){
  int i = blockIdx.x*256+threadIdx.x;
  int kk=i&63; int i2=i>>6;
  int n=i2&63; i2>>=6;
  int kc=i2&1; i2>>=1;
  int cc=i2%12; i2/=12;
  int part=i2&1; int k=i2>>1;
  int p = part*128 + kc*64 + kk;
  int col = cc*64 + n;
  float v = (col<H1)? tf32r(keW1[(size_t)k*EINN*H1 + (size_t)p*H1 + col]) : 0.f;
  d_wfabp[(size_t)((((k*2+part)*12+cc)*2+kc)*64 + n)*RS + PERM(kk)] = v;
}
__global__ void k_wprep_fnn(const float* __restrict__ fW0,
                            const float* __restrict__ fW1,
                            const float* __restrict__ fW2){
  int i = blockIdx.x*256+threadIdx.x;
  if(i < 196608){
    int kk=i&63; int n=(i>>6)&63; int r=i>>12;
    int kc=r%12, cc=r/12;
    d_wf0p[(size_t)((cc*12+kc)*64+n)*RS + PERM(kk)] =
      tf32r(fW0[(size_t)(kc*64+kk)*F2 + cc*64+n]);
  } else if(i < 262144){
    int j=i-196608;
    int kk=j&63; int n=(j>>6)&63; int r=j>>12;
    int kc=r&3, cc=r>>2;
    d_wf1p[(size_t)((cc*4+kc)*64+n)*RS + PERM(kk)] =
      tf32r(fW1[(size_t)(kc*64+kk)*F2 + cc*64+n]);
  } else {
    int j=i-262144;
    int kk=j&63; int n=(j>>6)&63; int r=j>>12;
    int kc=r&3, cc=r>>2;
    d_wf2p[(size_t)((cc*4+kc)*64+n)*RS + PERM(kk)] =
      tf32r(fW2[(size_t)(kc*64+kk)*F2 + cc*64+n]);
  }
}

// generic 128-row x 128-col tf32 MMA GEMM body
__device__ __forceinline__ void gemm128(const float* Wp, const float* in, int INST, int KC,
                                        int insilu, int n0, int cc0, float4* c1, float* sm){
  float* s_a = sm;
  float* s_b = sm + 128*RS;
  int tid=threadIdx.x;
  int w=tid>>5, l=tid&31, qr=l>>2, qc=l&3;
  int ra=w*16+qr, rb=ra+8, aoff=qc*18;
  for(int kc=0;kc<KC;kc++){
    __syncthreads();
    #pragma unroll
    for(int t=0;t<8;t++){
      int lin=tid+t*256;
      int r=lin>>4, c4=(lin&15)*4;
      int n=n0+r;
      float4 v = (n<NN)? *(const float4*)(in + (size_t)n*INST + kc*64 + c4) : make_float4(0,0,0,0);
      if(insilu){ v.x=siluf(v.x); v.y=siluf(v.y); v.z=siluf(v.z); v.w=siluf(v.w); }
      float* dst = s_a + r*RS + (c4>>2);
      dst[0]=tf32r(v.x); dst[18]=tf32r(v.y); dst[36]=tf32r(v.z); dst[54]=tf32r(v.w);
    }
    {
      const float4* s0=(const float4*)(Wp + (size_t)(cc0*KC+kc)*(64*RS));
      const float4* s1=(const float4*)(Wp + (size_t)((cc0+1)*KC+kc)*(64*RS));
      float4* d0=(float4*)s_b;
      float4* d1=(float4*)(s_b+64*RS);
      #pragma unroll
      for(int t=0;t<5;t++){ int i=tid+t*256; if(i<1152){ d0[i]=s0[i]; d1[i]=s1[i]; } }
    }
    __syncthreads();
    #pragma unroll
    for(int ks=0;ks<8;ks++){
      float2 A0=*(float2*)(s_a+ra*RS+aoff+2*ks);
      float2 A1=*(float2*)(s_a+rb*RS+aoff+2*ks);
      unsigned a0=__float_as_uint(A0.x), a2=__float_as_uint(A0.y);
      unsigned a1=__float_as_uint(A1.x), a3=__float_as_uint(A1.y);
      #pragma unroll
      for(int nt=0;nt<16;nt++){
        float* sb = s_b + (nt>>3)*(64*RS);
        float2 Bv=*(float2*)(sb+((nt&7)*8+qr)*RS+aoff+2*ks);
        mma8(c1[nt],a0,a1,a2,a3,__float_as_uint(Bv.x),__float_as_uint(Bv.y));
      }
    }
  }
}

// FA/FB via gemm128: grid (6,79,2); also zeroes d_msum
__global__ void __launch_bounds__(256,2) k_fab_mma(int k){
  extern __shared__ float sm[];
  int tid=threadIdx.x;
  for(int gi=(blockIdx.x+6*(blockIdx.y+79*(int)blockIdx.z))*256+tid; gi<NN*MM; gi+=948*256)
    d_msum[gi]=0.f;
  int part=blockIdx.z;
  int n0=blockIdx.y*128, cc0=blockIdx.x*2;
  const float* Wp = d_wfabp + (size_t)(k*2+part)*(12*2*64*RS);
  float4 c1[16];
  #pragma unroll
  for(int t=0;t<16;t++) c1[t]=make_float4(0,0,0,0);
  gemm128(Wp, d_feats, 128, 2, 0, n0, cc0, c1, sm);
  float* OUT = part? d_FB : d_FA;
  int w=tid>>5, l=tid&31, qr=l>>2, qc=l&3;
  int na=n0+w*16+qr, nb2=na+8;
  #pragma unroll
  for(int nt=0;nt<16;nt++){
    int col = cc0*64 + nt*8 + 2*qc;
    if(col<642){
      if(na<NN)  *(float2*)(OUT+(size_t)na*FASTRIDE+col)=make_float2(c1[nt].x,c1[nt].y);
      if(nb2<NN) *(float2*)(OUT+(size_t)nb2*FASTRIDE+col)=make_float2(c1[nt].z,c1[nt].w);
    }
  }
}

__global__ void __launch_bounds__(256,2) k_fnn_mma(const float* __restrict__ bias, int stage){
  const float* Wp = (stage==0)? d_wf0p : ((stage==1)? d_wf1p : d_wf2p);
  const float* in = (stage==0)? d_fcat : ((stage==1)? d_f1 : d_f2);
  float* out      = (stage==1)? d_f2 : d_f1;
  int KC          = (stage==0)? 12 : 4;
  extern __shared__ float sm[];
  int n0 = blockIdx.y*128, cc0 = blockIdx.x*2;
  float4 c1[16];
  #pragma unroll
  for(int t=0;t<16;t++) c1[t]=make_float4(0,0,0,0);
  gemm128(Wp, in, KC*64, KC, stage==0, n0, cc0, c1, sm);
  int tid=threadIdx.x, w=tid>>5, l=tid&31, qr=l>>2, qc=l&3;
  int na=n0+w*16+qr, nb2=na+8;
  #pragma unroll
  for(int nt=0;nt<16;nt++){
    int col = cc0*64 + nt*8 + 2*qc;
    float b0=__ldg(&bias[col]), b1=__ldg(&bias[col+1]);
    if(na<NN)  *(float2*)(out+(size_t)na*F2+col)=make_float2(siluf(c1[nt].x+b0),siluf(c1[nt].y+b1));
    if(nb2<NN) *(float2*)(out+(size_t)nb2*F2+col)=make_float2(siluf(c1[nt].z+b0),siluf(c1[nt].w+b1));
  }
}

// ---------- edge MLP: 10 MMA chunks + scalar tail for cols 640/641 ----------
__global__ void __launch_bounds__(256,2) k_edge(
   const float* __restrict__ keW1,const float* __restrict__ keb1,
   const float* __restrict__ keW2r,const float* __restrict__ keb2,
   const float* __restrict__ keng,const float* __restrict__ kenb,int k){
  extern __shared__ float sm[];
  float* s_h  = sm;                    // 128*72
  float* s_w1 = sm + 9216;             // 2 x 4608
  float* s_w2 = sm + 18432;            // 2 x 2304
  float* s_w1d= sm + 23040;            // 2 x 64
  float* s_b1 = sm + 23168;            // 2 x 64
  float* s_b2 = sm + 23296;
  float* s_g  = sm + 23328;
  float* s_bt = sm + 23360;
  float* s_w1t= sm + 23392;            // 128
  float* s_w2t= sm + 23520;            // 64
  float* s_sc = sm + 23584;            // 4
  int tid=threadIdx.x, w=tid>>5, l=tid&31, qr=l>>2, qc=l&3;
  int e0=blockIdx.x*128;
  int ra=w*16+qr, rb=ra+8, aoff=qc*18;
  uint32_t sbu=s2u(sm);
  const float* W1c = keW1 + (size_t)k*EINN*H1 + (size_t)256*H1;
  const float* B1  = keb1 + (size_t)k*H1;
  float2 eA[8], eB[8];
  {
    const float* pA=d_eap+(size_t)(e0+ra)*RS+aoff;
    const float* pB=d_eap+(size_t)(e0+rb)*RS+aoff;
    #pragma unroll
    for(int ks=0;ks<8;ks++){ eA[ks]=*(const float2*)(pA+2*ks); eB[ks]=*(const float2*)(pB+2*ks); }
  }
  int nda=d_dsts[e0+ra], nsa=d_srcs[e0+ra];
  int ndb=d_dsts[e0+rb], nsb=d_srcs[e0+rb];
  float da=d_dcol[e0+ra], db=d_dcol[e0+rb];
  if(tid<32){ s_b2[tid]=keb2[k*MM+tid]; s_g[tid]=keng[k*MM+tid]; s_bt[tid]=kenb[k*MM+tid]; }
  if(tid<128){ int kk=tid>>1, j=tid&1; s_w1t[tid]=W1c[(size_t)kk*H1+640+j]; }
  else if(tid<192){ int m=tid-128; int j=m>>5, n=m&31;
    s_w2t[m]=keW2r[(size_t)k*H1*MM + (size_t)(640+j)*MM + n]; }
  else if(tid<196){ int m=tid-192;
    s_sc[m] = (m<2)? B1[640+m] : W1c[(size_t)64*H1+640+(m-2)]; }

  auto stage=[&](int ch,int buf){
    const float4* w1s=(const float4*)(d_w1p + (size_t)((k*11+ch)*64)*RS);
    uint32_t w1a = sbu + (9216+buf*4608)*4;
    #pragma unroll
    for(int i=0;i<4;i++) cpa(w1a+(tid+256*i)*16, w1s+tid+256*i);
    if(tid<128) cpa(w1a+(1024+tid)*16, w1s+1024+tid);
    const float4* w2s=(const float4*)(d_w2p + (size_t)((k*11+ch)*32)*RS);
    uint32_t w2a = sbu + (18432+buf*2304)*4;
    #pragma unroll
    for(int i=0;i<2;i++) cpa(w2a+(tid+256*i)*16, w2s+tid+256*i);
    if(tid<64){
      cpa(w2a+(512+tid)*16, w2s+512+tid);
      int j=ch*64+tid;
      s_b1[buf*64+tid]=B1[j];
      s_w1d[buf*64+tid]=W1c[(size_t)64*H1+j];
    }
  };
  stage(0,0); CPA_COMMIT();

  float4 c2[4];
  #pragma unroll
  for(int t=0;t<4;t++) c2[t]=make_float4(0.f,0.f,0.f,0.f);

  for(int ch=0; ch<10; ch++){
    int buf=ch&1;
    CPA_WAIT0();
    __syncthreads();
    if(ch<9){ stage(ch+1,1-buf); CPA_COMMIT(); }
    float* w1b = s_w1 + buf*4608;
    float* w2b = s_w2 + buf*2304;
    float* b1b = s_b1 + buf*64;
    float* wdb = s_w1d + buf*64;
    int jc0=ch*64;
    float4 c1[8];
    #pragma unroll
    for(int t=0;t<8;t++) c1[t]=make_float4(0.f,0.f,0.f,0.f);
    #pragma unroll
    for(int ks=0;ks<8;ks++){
      unsigned a0=__float_as_uint(eA[ks].x), a2=__float_as_uint(eA[ks].y);
      unsigned a1=__float_as_uint(eB[ks].x), a3=__float_as_uint(eB[ks].y);
      #pragma unroll
      for(int nt=0;nt<8;nt++){
        float2 Bv=*(float2*)(w1b+(nt*8+qr)*RS+aoff+2*ks);
        mma8(c1[nt],a0,a1,a2,a3,__float_as_uint(Bv.x),__float_as_uint(Bv.y));
      }
    }
    {
      const float* FAa=d_FA+(size_t)nda*FASTRIDE+jc0;
      const float* FBa=d_FB+(size_t)nsa*FASTRIDE+jc0;
      const float* FAb=d_FA+(size_t)ndb*FASTRIDE+jc0;
      const float* FBb=d_FB+(size_t)nsb*FASTRIDE+jc0;
      #pragma unroll
      for(int nt=0;nt<8;nt++){
        int col0=nt*8+2*qc;
        float2 faa=*(const float2*)(FAa+col0);
        float2 fba=*(const float2*)(FBa+col0);
        float2 fab=*(const float2*)(FAb+col0);
        float2 fbb=*(const float2*)(FBb+col0);
        float b0=b1b[col0], b1f=b1b[col0+1];
        float w0=wdb[col0], w1v=wdb[col0+1];
        int p0=((col0&3)*18) + (col0>>2);
        s_h[ra*RS+p0]   =tf32r(siluf(c1[nt].x+b0 +da*w0 +faa.x+fba.x));
        s_h[ra*RS+p0+18]=tf32r(siluf(c1[nt].y+b1f+da*w1v+faa.y+fba.y));
        s_h[rb*RS+p0]   =tf32r(siluf(c1[nt].z+b0 +db*w0 +fab.x+fbb.x));
        s_h[rb*RS+p0+18]=tf32r(siluf(c1[nt].w+b1f+db*w1v+fab.y+fbb.y));
      }
    }
    __syncwarp();
    #pragma unroll
    for(int ks=0;ks<8;ks++){
      float2 A0=*(float2*)(s_h+ra*RS+aoff+2*ks);
      float2 A1=*(float2*)(s_h+rb*RS+aoff+2*ks);
      unsigned a0=__float_as_uint(A0.x), a2=__float_as_uint(A0.y);
      unsigned a1=__float_as_uint(A1.x), a3=__float_as_uint(A1.y);
      #pragma unroll
      for(int nt=0;nt<4;nt++){
        float2 Bv=*(float2*)(w2b+(nt*8+qr)*RS+aoff+2*ks);
        mma8(c2[nt],a0,a1,a2,a3,__float_as_uint(Bv.x),__float_as_uint(Bv.y));
      }
    }
  }
  // scalar tail: H1 cols 640, 641
  {
    float p0a=0,p1a=0,p0b=0,p1b=0;
    #pragma unroll
    for(int ks=0;ks<8;ks++){
      int k1=8*ks+qc, k2=k1+4;
      p0a+=eA[ks].x*s_w1t[2*k1]  +eA[ks].y*s_w1t[2*k2];
      p1a+=eA[ks].x*s_w1t[2*k1+1]+eA[ks].y*s_w1t[2*k2+1];
      p0b+=eB[ks].x*s_w1t[2*k1]  +eB[ks].y*s_w1t[2*k2];
      p1b+=eB[ks].x*s_w1t[2*k1+1]+eB[ks].y*s_w1t[2*k2+1];
    }
    #pragma unroll
    for(int o=1;o<4;o<<=1){
      p0a+=__shfl_xor_sync(0xffffffffu,p0a,o); p1a+=__shfl_xor_sync(0xffffffffu,p1a,o);
      p0b+=__shfl_xor_sync(0xffffffffu,p0b,o); p1b+=__shfl_xor_sync(0xffffffffu,p1b,o);
    }
    float h0a=siluf(p0a+s_sc[0]+da*s_sc[2]+d_FA[(size_t)nda*FASTRIDE+640]+d_FB[(size_t)nsa*FASTRIDE+640]);
    float h1a=siluf(p1a+s_sc[1]+da*s_sc[3]+d_FA[(size_t)nda*FASTRIDE+641]+d_FB[(size_t)nsa*FASTRIDE+641]);
    float h0b=siluf(p0b+s_sc[0]+db*s_sc[2]+d_FA[(size_t)ndb*FASTRIDE+640]+d_FB[(size_t)nsb*FASTRIDE+640]);
    float h1b=siluf(p1b+s_sc[1]+db*s_sc[3]+d_FA[(size_t)ndb*FASTRIDE+641]+d_FB[(size_t)nsb*FASTRIDE+641]);
    #pragma unroll
    for(int nt=0;nt<4;nt++){
      int col0=nt*8+2*qc;
      c2[nt].x += h0a*s_w2t[col0]  +h1a*s_w2t[32+col0];
      c2[nt].y += h0a*s_w2t[col0+1]+h1a*s_w2t[32+col0+1];
      c2[nt].z += h0b*s_w2t[col0]  +h1b*s_w2t[32+col0];
      c2[nt].w += h0b*s_w2t[col0+1]+h1b*s_w2t[32+col0+1];
    }
  }
  float va[8], vb[8];
  #pragma unroll
  for(int nt=0;nt<4;nt++){
    int col0=nt*8+2*qc;
    va[2*nt]  =siluf(c2[nt].x+s_b2[col0]);
    va[2*nt+1]=siluf(c2[nt].y+s_b2[col0+1]);
    vb[2*nt]  =siluf(c2[nt].z+s_b2[col0]);
    vb[2*nt+1]=siluf(c2[nt].w+s_b2[col0+1]);
  }
  float sa=0.f,ssa=0.f,sb=0.f,ssb=0.f;
  #pragma unroll
  for(int i=0;i<8;i++){ sa+=va[i]; ssa+=va[i]*va[i]; sb+=vb[i]; ssb+=vb[i]*vb[i]; }
  #pragma unroll
  for(int o=1;o<4;o<<=1){
    sa+=__shfl_xor_sync(0xffffffffu,sa,o); ssa+=__shfl_xor_sync(0xffffffffu,ssa,o);
    sb+=__shfl_xor_sync(0xffffffffu,sb,o); ssb+=__shfl_xor_sync(0xffffffffu,ssb,o);
  }
  float mua=sa*(1.f/MM), vara=ssa*(1.f/MM)-mua*mua, inva=rsqrtf(vara+1e-5f);
  float mub=sb*(1.f/MM), varb=ssb*(1.f/MM)-mub*mub, invb=rsqrtf(varb+1e-5f);
  float* pa=&d_msum[(size_t)nda*MM];
  float* pb=&d_msum[(size_t)ndb*MM];
  #pragma unroll
  for(int nt=0;nt<4;nt++){
    int col0=nt*8+2*qc;
    atomicAdd(pa+col0,  (va[2*nt]  -mua)*inva*s_g[col0]  +s_bt[col0]);
    atomicAdd(pa+col0+1,(va[2*nt+1]-mua)*inva*s_g[col0+1]+s_bt[col0+1]);
    atomicAdd(pb+col0,  (vb[2*nt]  -mub)*invb*s_g[col0]  +s_bt[col0]);
    atomicAdd(pb+col0+1,(vb[2*nt+1]-mub)*invb*s_g[col0+1]+s_bt[col0+1]);
  }
}

__global__ void k_xcat(const float* __restrict__ keng,const float* __restrict__ kenb,
                       const float* __restrict__ kn1g,const float* __restrict__ kn1b,int k){
  int warp=threadIdx.x>>5, lane=threadIdx.x&31;
  int n=blockIdx.x*8+warp;
  const float* g1=kn1g+(size_t)k*128; const float* b1=kn1b+(size_t)k*128;
  float v[4],s=0.f,ss=0.f;
  #pragma unroll
  for(int i=0;i<4;i++){ float x=d_feats[(size_t)n*128+lane+32*i]; v[i]=x; s+=x; ss+=x*x; }
  #pragma unroll
  for(int o=16;o;o>>=1){ s+=__shfl_xor_sync(0xffffffffu,s,o); ss+=__shfl_xor_sync(0xffffffffu,ss,o); }
  float mu=s*(1.f/128), var=ss*(1.f/128)-mu*mu, inv=rsqrtf(var+1e-5f);
  #pragma unroll
  for(int i=0;i<4;i++){ int c=lane+32*i; d_xcat[(size_t)n*160+c]=(v[i]-mu)*inv*g1[c]+b1[c]; }
  float m=d_msum[(size_t)n*MM+lane]/fmaxf(d_deg[n],1.f);
  float s2=m, ss2=m*m;
  #pragma unroll
  for(int o=16;o;o>>=1){ s2+=__shfl_xor_sync(0xffffffffu,s2,o); ss2+=__shfl_xor_sync(0xffffffffu,ss2,o); }
  float mu2=s2*(1.f/MM), var2=ss2*(1.f/MM)-mu2*mu2, inv2=rsqrtf(var2+1e-5f);
  d_xcat[(size_t)n*160+128+lane]=(m-mu2)*inv2*keng[k*MM+lane]+kenb[k*MM+lane];
}

__global__ void __launch_bounds__(256) k_node(const float* __restrict__ knW1,const float* __restrict__ knb1,
    const float* __restrict__ knW2,const float* __restrict__ knb2,
    const float* __restrict__ kn2g,const float* __restrict__ kn2b,int k){
  extern __shared__ float sm[];
  float* s_x=sm;
  float* s_h=s_x+10304;
  float* s_w=s_h+16448;
  int tid=threadIdx.x;
  int n0=blockIdx.x*64;
  const float* W1=knW1+(size_t)k*160*256;
  const float* B1=knb1+(size_t)k*256;
  const float* W2=knW2+(size_t)k*256*128;
  const float* B2=knb2+(size_t)k*128;
  const float* G =kn2g+(size_t)k*128;
  const float* BT=kn2b+(size_t)k*128;
  for(int i=tid;i<64*160;i+=256){int r=i/160,c=i-r*160;int n=n0+r; s_x[r*161+c]= (n<NN)? d_xcat[(size_t)n*160+c]:0.f;}
  int r0=(tid>>4)*4, c0=(tid&15)*4;
  for(int oc=0;oc<4;oc++){
    __syncthreads();
    for(int i=tid;i<160*64;i+=256){int p=i>>6,c=i&63; s_w[i]=W1[(size_t)p*256+oc*64+c];}
    __syncthreads();
    float a4[4][4];
    #pragma unroll
    for(int i=0;i<4;i++){a4[i][0]=0;a4[i][1]=0;a4[i][2]=0;a4[i][3]=0;}
    for(int p=0;p<160;p++){
      float4 w=*(float4*)(s_w+p*64+c0);
      #pragma unroll
      for(int i=0;i<4;i++){ float a=s_x[(r0+i)*161+p];
        a4[i][0]+=a*w.x; a4[i][1]+=a*w.y; a4[i][2]+=a*w.z; a4[i][3]+=a*w.w; }
    }
    #pragma unroll
    for(int i=0;i<4;i++){
      #pragma unroll
      for(int j=0;j<4;j++){ int col=oc*64+c0+j;
        s_h[(r0+i)*257+col]=siluf(a4[i][j]+__ldg(&B1[col])); }
    }
  }
  __syncthreads();
  for(int oc=0;oc<2;oc++){
    if(oc) __syncthreads();
    for(int i=tid;i<256*64;i+=256){int p=i>>6,c=i&63; s_w[i]=W2[(size_t)p*128+oc*64+c];}
    __syncthreads();
    float a4[4][4];
    #pragma unroll
    for(int i=0;i<4;i++){a4[i][0]=0;a4[i][1]=0;a4[i][2]=0;a4[i][3]=0;}
    for(int p=0;p<256;p++){
      float4 w=*(float4*)(s_w+p*64+c0);
      #pragma unroll
      for(int i=0;i<4;i++){ float a=s_h[(r0+i)*257+p];
        a4[i][0]+=a*w.x; a4[i][1]+=a*w.y; a4[i][2]+=a*w.z; a4[i][3]+=a*w.w; }
    }
    #pragma unroll
    for(int i=0;i<4;i++){
      #pragma unroll
      for(int j=0;j<4;j++){ int col=oc*64+c0+j;
        s_x[(r0+i)*129+col]=a4[i][j]+__ldg(&B2[col]); }
    }
  }
  __syncthreads();
  int w=tid>>5, lane=tid&31;
  for(int rr=w; rr<64; rr+=8){
    int n=n0+rr;
    float v[4],s=0.f,ss=0.f;
    #pragma unroll
    for(int i=0;i<4;i++){ float x=s_x[rr*129+lane+32*i]; v[i]=x; s+=x; ss+=x*x; }
    #pragma unroll
    for(int o=16;o;o>>=1){ s+=__shfl_xor_sync(0xffffffffu,s,o); ss+=__shfl_xor_sync(0xffffffffu,ss,o); }
    float mu=s*(1.f/128), var=ss*(1.f/128)-mu*mu, inv=rsqrtf(var+1e-5f);
    if(n<NN){
      #pragma unroll
      for(int i=0;i<4;i++){ int c=lane+32*i;
        float nv=(v[i]-mu)*inv*G[c]+BT[c];
        float f=d_feats[(size_t)n*128+c]+nv;
        d_feats[(size_t)n*128+c]=f;
        d_fcat[(size_t)n*FH+(size_t)(k+1)*128+c]=f; }
    }
  }
}

__global__ void k_pool(const int* __restrict__ batch){
  int n=blockIdx.x; int c=threadIdx.x;
  int b=batch[n];
  atomicAdd(&d_gsum[b*F2+c], d_f1[(size_t)n*F2+c]);
  if(c==0) atomicAdd(&d_gcnt[b],1.f);
}

__global__ void k_final(const float* __restrict__ gW0,const float* __restrict__ gb0,
                        const float* __restrict__ gW1,const float* __restrict__ gb1,
                        const float* __restrict__ gW2,const float* __restrict__ gb2,
                        float* __restrict__ out){
  __shared__ float s_g[256], s_h[256], s_red[8];
  int b=blockIdx.x, t=threadIdx.x;
  float cnt=fmaxf(d_gcnt[b],1.f);
  s_g[t]=d_gsum[b*F2+t]/cnt;
  __syncthreads();
  float a=gb0[t];
  #pragma unroll 8
  for(int p=0;p<256;p++) a+=s_g[p]*gW0[p*256+t];
  s_h[t]=siluf(a);
  __syncthreads();
  a=gb1[t];
  #pragma unroll 8
  for(int p=0;p<256;p++) a+=s_h[p]*gW1[p*256+t];
  float h=siluf(a);
  float v=h*gW2[t];
  #pragma unroll
  for(int o=16;o;o>>=1) v+=__shfl_xor_sync(0xffffffffu,v,o);
  if((t&31)==0) s_red[t>>5]=v;
  __syncthreads();
  if(t==0){ float tot=0.f;
    #pragma unroll
    for(int i=0;i<8;i++) tot+=s_red[i];
    out[b]=tot+gb2[0]; }
}

extern "C" void kernel_launch(void* const* d_in, const int* in_sizes, int n_in,
                              void* d_out, int out_size){
  const float* coords =(const float*)d_in[0];
  const int*   atomids=(const int*)d_in[1];
  const int*   eidx   =(const int*)d_in[2];
  const int*   batch  =(const int*)d_in[3];
  int s = (in_sizes[4]==11*DD) ? 4 : 5;
  const float* emb =(const float*)d_in[s+0];
  const float* keW1=(const float*)d_in[s+1];
  const float* keb1=(const float*)d_in[s+2];
  const float* keW2=(const float*)d_in[s+3];
  const float* keb2=(const float*)d_in[s+4];
  const float* keng=(const float*)d_in[s+5];
  const float* kenb=(const float*)d_in[s+6];
  const float* kn1g=(const float*)d_in[s+7];
  const float* kn1b=(const float*)d_in[s+8];
  const float* knW1=(const float*)d_in[s+9];
  const float* knb1=(const float*)d_in[s+10];
  const float* knW2=(const float*)d_in[s+11];
  const float* knb2=(const float*)d_in[s+12];
  const float* kn2g=(const float*)d_in[s+13];
  const float* kn2b=(const float*)d_in[s+14];
  const float* fW0 =(const float*)d_in[s+15];
  const float* fb0 =(const float*)d_in[s+16];
  const float* fW1 =(const float*)d_in[s+17];
  const float* fb1 =(const float*)d_in[s+18];
  const float* fW2 =(const float*)d_in[s+19];
  const float* fb2 =(const float*)d_in[s+20];
  const float* gW0 =(const float*)d_in[s+21];
  const float* gb0 =(const float*)d_in[s+22];
  const float* gW1 =(const float*)d_in[s+23];
  const float* gb1 =(const float*)d_in[s+24];
  const float* gW2 =(const float*)d_in[s+25];
  const float* gb2 =(const float*)d_in[s+26];
  float* out=(float*)d_out;

  const int EDGE_SM = 23592*4;                 // 94368
  const int NODE_SM = (10304+16448+16384)*4;   // 172544
  const int FNN_SM  = (128*RS + 2*64*RS)*4;    // 73728
  const int EA_SM   = 256*RS*4;                // 73728
  cudaFuncSetAttribute(k_edge,    cudaFuncAttributeMaxDynamicSharedMemorySize, EDGE_SM);
  cudaFuncSetAttribute(k_node,    cudaFuncAttributeMaxDynamicSharedMemorySize, NODE_SM);
  cudaFuncSetAttribute(k_fab_mma, cudaFuncAttributeMaxDynamicSharedMemorySize, FNN_SM);
  cudaFuncSetAttribute(k_fnn_mma, cudaFuncAttributeMaxDynamicSharedMemorySize, FNN_SM);
  cudaFuncSetAttribute(k_ea,      cudaFuncAttributeMaxDynamicSharedMemorySize, EA_SM);

  k_zero_init<<<65,256>>>();
  k_hist<<<EE/256,256>>>(eidx);
  k_scan<<<1,1024>>>();
  k_scatter<<<EE/256,256>>>(eidx);
  k_feats<<<NN,128>>>(emb,atomids);
  k_ea<<<EE/256,256,EA_SM>>>(coords);
  k_wprep<<<1320,256>>>(keW1,keW2);
  k_wprep_fab<<<3840,256>>>(keW1);
  k_wprep_fnn<<<1280,256>>>(fW0,fW1,fW2);
  for(int k=0;k<KK;k++){
    k_fab_mma<<<dim3(6,79,2),256,FNN_SM>>>(k);
    k_edge<<<EE/128,256,EDGE_SM>>>(keW1,keb1,keW2,keb2,keng,kenb,k);
    k_xcat<<<NN/8,256>>>(keng,kenb,kn1g,kn1b,k);
    k_node<<<157,256,NODE_SM>>>(knW1,knb1,knW2,knb2,kn2g,kn2b,k);
  }
  k_fnn_mma<<<dim3(2,79),256,FNN_SM>>>(fb0, 0);
  k_fnn_mma<<<dim3(2,79),256,FNN_SM>>>(fb1, 1);
  k_fnn_mma<<<dim3(2,79),256,FNN_SM>>>(fb2, 2);
  k_pool<<<NN,256>>>(batch);
  k_final<<<BB,256>>>(gW0,gb0,gW1,gb1,gW2,gb2,out);
}

// round 17
// speedup vs baseline: 1.3455x; 1.0080x over previous
#include <cuda_runtime.h>
#include <stdint.h>
#include <math.h>

#define NN 10000
#define EE 160000
#define BB 64
#define DD 128
#define MM 32
#define EINN 321
#define H1 642
#define KK 5
#define FH 768
#define F2 256
#define FASTRIDE 644

#define PERM(k) (((k)&3)*18 + ((k)>>2))
#define RS 72

__device__ float d_feats[NN*DD];
__device__ float d_eap[EE*RS];
__device__ float d_dcol[EE];
__device__ int   d_hist[NN];
__device__ int   d_base[NN];
__device__ int   d_cur[NN];
__device__ int   d_srcs[EE];
__device__ int   d_dsts[EE];
__device__ float d_mij[(size_t)EE*MM];
__device__ float d_FA[NN*FASTRIDE + 256];
__device__ float d_FB[NN*FASTRIDE + 256];
__device__ float d_xcat[NN*160];
__device__ float d_fcat[NN*FH];
__device__ float d_f1[NN*F2];
__device__ float d_f2[NN*F2];
__device__ float d_gsum[BB*F2];
__device__ float d_gcnt[BB];
__device__ float d_w1p[KK*11*64*RS];
__device__ float d_w2p[KK*11*32*RS];
__device__ float d_wfabp[KK*2*12*2*64*RS];
__device__ float d_wf0p[4*12*64*RS];
__device__ float d_wf1p[4*4*64*RS];
__device__ float d_wf2p[4*4*64*RS];

__device__ __forceinline__ float siluf(float x){
  return __fdividef(x, 1.f+__expf(-x));
}
__device__ __forceinline__ float tf32r(float x){
  float r; asm("cvt.rna.tf32.f32 %0,%1;" : "=f"(r) : "f"(x)); return r;
}
__device__ __forceinline__ void mma8(float4 &c, unsigned a0,unsigned a1,unsigned a2,unsigned a3,
                                     unsigned b0,unsigned b1){
  asm("mma.sync.aligned.m16n8k8.row.col.f32.tf32.tf32.f32 "
      "{%0,%1,%2,%3},{%4,%5,%6,%7},{%8,%9},{%0,%1,%2,%3};"
      : "+f"(c.x),"+f"(c.y),"+f"(c.z),"+f"(c.w)
      : "r"(a0),"r"(a1),"r"(a2),"r"(a3),"r"(b0),"r"(b1));
}
__device__ __forceinline__ uint32_t s2u(const void* p){
  uint32_t a; asm("{ .reg .u64 t; cvta.to.shared.u64 t, %1; cvt.u32.u64 %0, t; }" : "=r"(a) : "l"(p)); return a;
}
__device__ __forceinline__ void cpa(uint32_t s, const void* g){
  asm volatile("cp.async.cg.shared.global [%0], [%1], 16;"::"r"(s),"l"(g):"memory");
}
#define CPA_COMMIT() asm volatile("cp.async.commit_group;":::"memory")
#define CPA_WAIT0()  asm volatile("cp.async.wait_group 0;":::"memory")

__global__ void k_zero_init(){
  int i = blockIdx.x*256+threadIdx.x;
  if(i<NN){ d_hist[i]=0; d_cur[i]=0; }
  if(i<BB*F2) d_gsum[i]=0.f;
  if(i<BB) d_gcnt[i]=0.f;
}
__global__ void k_hist(const int* __restrict__ eidx){
  int e=blockIdx.x*256+threadIdx.x;
  atomicAdd(&d_hist[eidx[EE+e]],1);
}
// exclusive prefix sum over NN bins: 1 block, 1024 threads, 10 bins/thread
__global__ void k_scan(){
  __shared__ int part[1024];
  int tid=threadIdx.x;
  int base=tid*10;
  int loc[10]; int s=0;
  #pragma unroll
  for(int i=0;i<10;i++){ int v=(base+i<NN)? d_hist[base+i] : 0; loc[i]=s; s+=v; }
  part[tid]=s;
  __syncthreads();
  for(int off=1;off<1024;off<<=1){
    int v=0;
    if(tid>=off) v=part[tid-off];
    __syncthreads();
    if(tid>=off) part[tid]+=v;
    __syncthreads();
  }
  int pre = (tid>0)? part[tid-1] : 0;
  #pragma unroll
  for(int i=0;i<10;i++){ if(base+i<NN) d_base[base+i]=pre+loc[i]; }
}
__global__ void k_scatter(const int* __restrict__ eidx){
  int e=blockIdx.x*256+threadIdx.x;
  int dst=eidx[EE+e];
  int p=d_base[dst]+atomicAdd(&d_cur[dst],1);
  d_srcs[p]=eidx[e];
  d_dsts[p]=dst;
}
__global__ void k_feats(const float* __restrict__ emb, const int* __restrict__ atomids){
  int n=blockIdx.x; int c=threadIdx.x;
  float v=emb[atomids[n]*DD+c];
  d_feats[n*DD+c]=v;
  d_fcat[(size_t)n*FH+c]=v;
}
// edge attrs in sorted order: compute into smem, coalesced copy out
__global__ void __launch_bounds__(256,2) k_ea(const float* __restrict__ coords){
  extern __shared__ float s[];
  int tid=threadIdx.x;
  int e=blockIdx.x*256+tid;
  int si=d_srcs[e], t2=d_dsts[e];
  float dx=coords[3*si]-coords[3*t2];
  float dy=coords[3*si+1]-coords[3*t2+1];
  float dz=coords[3*si+2]-coords[3*t2+2];
  float d=dx*dx+dy*dy+dz*dz;
  float* o=&s[tid*RS];
  #pragma unroll
  for(int i=0;i<32;i++){
    float sc=__uint_as_float((unsigned)(127-i)<<23);   // 2^-i
    float x=d*sc;
    float sv,cv; __sincosf(x,&sv,&cv);
    o[PERM(i)]=tf32r(sv); o[PERM(32+i)]=tf32r(cv);
  }
  d_dcol[e]=d;
  __syncthreads();
  float4* dst=(float4*)(d_eap + (size_t)blockIdx.x*256*RS);
  const float4* src=(const float4*)s;
  #pragma unroll
  for(int t=0;t<18;t++) dst[tid+256*t]=src[tid+256*t];
}

__global__ void k_wprep(const float* __restrict__ keW1, const float* __restrict__ keW2){
  int i = blockIdx.x*256+threadIdx.x;
  const int W1TOT = KK*11*64*64;
  const int W2TOT = KK*11*32*64;
  if(i < W1TOT){
    int kk=i&63; int n=(i>>6)&63; int ch=(i>>12)%11; int k=i/(64*64*11);
    int j=ch*64+n;
    float v = (j<H1)? tf32r(keW1[(size_t)k*EINN*H1 + (size_t)(256+kk)*H1 + j]) : 0.f;
    d_w1p[(size_t)(((k*11+ch)*64)+n)*RS + PERM(kk)] = v;
  } else if(i < W1TOT+W2TOT){
    int m=i-W1TOT;
    int kk=m&63; int n=(m>>6)&31; int ch=(m>>11)%11; int k=m/(32*64*11);
    int j=ch*64+kk;
    float v = (j<H1)? tf32r(keW2[(size_t)k*H1*MM + (size_t)j*MM + n]) : 0.f;
    d_w2p[(size_t)(((k*11+ch)*32)+n)*RS + PERM(kk)] = v;
  }
}
__global__ void k_wprep_fab(const float* __restrict__ keW1){
  int i = blockIdx.x*256+threadIdx.x;
  int kk=i&63; int i2=i>>6;
  int n=i2&63; i2>>=6;
  int kc=i2&1; i2>>=1;
  int cc=i2%12; i2/=12;
  int part=i2&1; int k=i2>>1;
  int p = part*128 + kc*64 + kk;
  int col = cc*64 + n;
  float v = (col<H1)? tf32r(keW1[(size_t)k*EINN*H1 + (size_t)p*H1 + col]) : 0.f;
  d_wfabp[(size_t)((((k*2+part)*12+cc)*2+kc)*64 + n)*RS + PERM(kk)] = v;
}
__global__ void k_wprep_fnn(const float* __restrict__ fW0,
                            const float* __restrict__ fW1,
                            const float* __restrict__ fW2){
  int i = blockIdx.x*256+threadIdx.x;
  if(i < 196608){
    int kk=i&63; int n=(i>>6)&63; int r=i>>12;
    int kc=r%12, cc=r/12;
    d_wf0p[(size_t)((cc*12+kc)*64+n)*RS + PERM(kk)] =
      tf32r(fW0[(size_t)(kc*64+kk)*F2 + cc*64+n]);
  } else if(i < 262144){
    int j=i-196608;
    int kk=j&63; int n=(j>>6)&63; int r=j>>12;
    int kc=r&3, cc=r>>2;
    d_wf1p[(size_t)((cc*4+kc)*64+n)*RS + PERM(kk)] =
      tf32r(fW1[(size_t)(kc*64+kk)*F2 + cc*64+n]);
  } else {
    int j=i-262144;
    int kk=j&63; int n=(j>>6)&63; int r=j>>12;
    int kc=r&3, cc=r>>2;
    d_wf2p[(size_t)((cc*4+kc)*64+n)*RS + PERM(kk)] =
      tf32r(fW2[(size_t)(kc*64+kk)*F2 + cc*64+n]);
  }
}

// generic 128-row x 128-col tf32 MMA GEMM body
__device__ __forceinline__ void gemm128(const float* Wp, const float* in, int INST, int KC,
                                        int insilu, int n0, int cc0, float4* c1, float* sm){
  float* s_a = sm;
  float* s_b = sm + 128*RS;
  int tid=threadIdx.x;
  int w=tid>>5, l=tid&31, qr=l>>2, qc=l&3;
  int ra=w*16+qr, rb=ra+8, aoff=qc*18;
  for(int kc=0;kc<KC;kc++){
    __syncthreads();
    #pragma unroll
    for(int t=0;t<8;t++){
      int lin=tid+t*256;
      int r=lin>>4, c4=(lin&15)*4;
      int n=n0+r;
      float4 v = (n<NN)? *(const float4*)(in + (size_t)n*INST + kc*64 + c4) : make_float4(0,0,0,0);
      if(insilu){ v.x=siluf(v.x); v.y=siluf(v.y); v.z=siluf(v.z); v.w=siluf(v.w); }
      float* dst = s_a + r*RS + (c4>>2);
      dst[0]=tf32r(v.x); dst[18]=tf32r(v.y); dst[36]=tf32r(v.z); dst[54]=tf32r(v.w);
    }
    {
      const float4* s0=(const float4*)(Wp + (size_t)(cc0*KC+kc)*(64*RS));
      const float4* s1=(const float4*)(Wp + (size_t)((cc0+1)*KC+kc)*(64*RS));
      float4* d0=(float4*)s_b;
      float4* d1=(float4*)(s_b+64*RS);
      #pragma unroll
      for(int t=0;t<5;t++){ int i=tid+t*256; if(i<1152){ d0[i]=s0[i]; d1[i]=s1[i]; } }
    }
    __syncthreads();
    #pragma unroll
    for(int ks=0;ks<8;ks++){
      float2 A0=*(float2*)(s_a+ra*RS+aoff+2*ks);
      float2 A1=*(float2*)(s_a+rb*RS+aoff+2*ks);
      unsigned a0=__float_as_uint(A0.x), a2=__float_as_uint(A0.y);
      unsigned a1=__float_as_uint(A1.x), a3=__float_as_uint(A1.y);
      #pragma unroll
      for(int nt=0;nt<16;nt++){
        float* sb = s_b + (nt>>3)*(64*RS);
        float2 Bv=*(float2*)(sb+((nt&7)*8+qr)*RS+aoff+2*ks);
        mma8(c1[nt],a0,a1,a2,a3,__float_as_uint(Bv.x),__float_as_uint(Bv.y));
      }
    }
  }
}

// FA/FB via gemm128: grid (6,79,2)
__global__ void __launch_bounds__(256,2) k_fab_mma(int k){
  extern __shared__ float sm[];
  int tid=threadIdx.x;
  int part=blockIdx.z;
  int n0=blockIdx.y*128, cc0=blockIdx.x*2;
  const float* Wp = d_wfabp + (size_t)(k*2+part)*(12*2*64*RS);
  float4 c1[16];
  #pragma unroll
  for(int t=0;t<16;t++) c1[t]=make_float4(0,0,0,0);
  gemm128(Wp, d_feats, 128, 2, 0, n0, cc0, c1, sm);
  float* OUT = part? d_FB : d_FA;
  int w=tid>>5, l=tid&31, qr=l>>2, qc=l&3;
  int na=n0+w*16+qr, nb2=na+8;
  #pragma unroll
  for(int nt=0;nt<16;nt++){
    int col = cc0*64 + nt*8 + 2*qc;
    if(col<642){
      if(na<NN)  *(float2*)(OUT+(size_t)na*FASTRIDE+col)=make_float2(c1[nt].x,c1[nt].y);
      if(nb2<NN) *(float2*)(OUT+(size_t)nb2*FASTRIDE+col)=make_float2(c1[nt].z,c1[nt].w);
    }
  }
}

__global__ void __launch_bounds__(256,2) k_fnn_mma(const float* __restrict__ bias, int stage){
  const float* Wp = (stage==0)? d_wf0p : ((stage==1)? d_wf1p : d_wf2p);
  const float* in = (stage==0)? d_fcat : ((stage==1)? d_f1 : d_f2);
  float* out      = (stage==1)? d_f2 : d_f1;
  int KC          = (stage==0)? 12 : 4;
  extern __shared__ float sm[];
  int n0 = blockIdx.y*128, cc0 = blockIdx.x*2;
  float4 c1[16];
  #pragma unroll
  for(int t=0;t<16;t++) c1[t]=make_float4(0,0,0,0);
  gemm128(Wp, in, KC*64, KC, stage==0, n0, cc0, c1, sm);
  int tid=threadIdx.x, w=tid>>5, l=tid&31, qr=l>>2, qc=l&3;
  int na=n0+w*16+qr, nb2=na+8;
  #pragma unroll
  for(int nt=0;nt<16;nt++){
    int col = cc0*64 + nt*8 + 2*qc;
    float b0=__ldg(&bias[col]), b1=__ldg(&bias[col+1]);
    if(na<NN)  *(float2*)(out+(size_t)na*F2+col)=make_float2(siluf(c1[nt].x+b0),siluf(c1[nt].y+b1));
    if(nb2<NN) *(float2*)(out+(size_t)nb2*F2+col)=make_float2(siluf(c1[nt].z+b0),siluf(c1[nt].w+b1));
  }
}

// ---------- edge MLP: 10 MMA chunks + scalar tail; writes per-edge m to d_mij ----------
__global__ void __launch_bounds__(256,2) k_edge(
   const float* __restrict__ keW1,const float* __restrict__ keb1,
   const float* __restrict__ keW2r,const float* __restrict__ keb2,
   const float* __restrict__ keng,const float* __restrict__ kenb,int k){
  extern __shared__ float sm[];
  float* s_h  = sm;                    // 128*72
  float* s_w1 = sm + 9216;             // 2 x 4608
  float* s_w2 = sm + 18432;            // 2 x 2304
  float* s_w1d= sm + 23040;            // 2 x 64
  float* s_b1 = sm + 23168;            // 2 x 64
  float* s_b2 = sm + 23296;
  float* s_g  = sm + 23328;
  float* s_bt = sm + 23360;
  float* s_w1t= sm + 23392;            // 128
  float* s_w2t= sm + 23520;            // 64
  float* s_sc = sm + 23584;            // 4
  int tid=threadIdx.x, w=tid>>5, l=tid&31, qr=l>>2, qc=l&3;
  int e0=blockIdx.x*128;
  int ra=w*16+qr, rb=ra+8, aoff=qc*18;
  uint32_t sbu=s2u(sm);
  const float* W1c = keW1 + (size_t)k*EINN*H1 + (size_t)256*H1;
  const float* B1  = keb1 + (size_t)k*H1;
  float2 eA[8], eB[8];
  {
    const float* pA=d_eap+(size_t)(e0+ra)*RS+aoff;
    const float* pB=d_eap+(size_t)(e0+rb)*RS+aoff;
    #pragma unroll
    for(int ks=0;ks<8;ks++){ eA[ks]=*(const float2*)(pA+2*ks); eB[ks]=*(const float2*)(pB+2*ks); }
  }
  int nda=d_dsts[e0+ra], nsa=d_srcs[e0+ra];
  int ndb=d_dsts[e0+rb], nsb=d_srcs[e0+rb];
  float da=d_dcol[e0+ra], db=d_dcol[e0+rb];
  if(tid<32){ s_b2[tid]=keb2[k*MM+tid]; s_g[tid]=keng[k*MM+tid]; s_bt[tid]=kenb[k*MM+tid]; }
  if(tid<128){ int kk=tid>>1, j=tid&1; s_w1t[tid]=W1c[(size_t)kk*H1+640+j]; }
  else if(tid<192){ int m=tid-128; int j=m>>5, n=m&31;
    s_w2t[m]=keW2r[(size_t)k*H1*MM + (size_t)(640+j)*MM + n]; }
  else if(tid<196){ int m=tid-192;
    s_sc[m] = (m<2)? B1[640+m] : W1c[(size_t)64*H1+640+(m-2)]; }

  auto stage=[&](int ch,int buf){
    const float4* w1s=(const float4*)(d_w1p + (size_t)((k*11+ch)*64)*RS);
    uint32_t w1a = sbu + (9216+buf*4608)*4;
    #pragma unroll
    for(int i=0;i<4;i++) cpa(w1a+(tid+256*i)*16, w1s+tid+256*i);
    if(tid<128) cpa(w1a+(1024+tid)*16, w1s+1024+tid);
    const float4* w2s=(const float4*)(d_w2p + (size_t)((k*11+ch)*32)*RS);
    uint32_t w2a = sbu + (18432+buf*2304)*4;
    #pragma unroll
    for(int i=0;i<2;i++) cpa(w2a+(tid+256*i)*16, w2s+tid+256*i);
    if(tid<64){
      cpa(w2a+(512+tid)*16, w2s+512+tid);
      int j=ch*64+tid;
      s_b1[buf*64+tid]=B1[j];
      s_w1d[buf*64+tid]=W1c[(size_t)64*H1+j];
    }
  };
  stage(0,0); CPA_COMMIT();

  float4 c2[4];
  #pragma unroll
  for(int t=0;t<4;t++) c2[t]=make_float4(0.f,0.f,0.f,0.f);

  for(int ch=0; ch<10; ch++){
    int buf=ch&1;
    CPA_WAIT0();
    __syncthreads();
    if(ch<9){ stage(ch+1,1-buf); CPA_COMMIT(); }
    float* w1b = s_w1 + buf*4608;
    float* w2b = s_w2 + buf*2304;
    float* b1b = s_b1 + buf*64;
    float* wdb = s_w1d + buf*64;
    int jc0=ch*64;
    float4 c1[8];
    #pragma unroll
    for(int t=0;t<8;t++) c1[t]=make_float4(0.f,0.f,0.f,0.f);
    #pragma unroll
    for(int ks=0;ks<8;ks++){
      unsigned a0=__float_as_uint(eA[ks].x), a2=__float_as_uint(eA[ks].y);
      unsigned a1=__float_as_uint(eB[ks].x), a3=__float_as_uint(eB[ks].y);
      #pragma unroll
      for(int nt=0;nt<8;nt++){
        float2 Bv=*(float2*)(w1b+(nt*8+qr)*RS+aoff+2*ks);
        mma8(c1[nt],a0,a1,a2,a3,__float_as_uint(Bv.x),__float_as_uint(Bv.y));
      }
    }
    {
      const float* FAa=d_FA+(size_t)nda*FASTRIDE+jc0;
      const float* FBa=d_FB+(size_t)nsa*FASTRIDE+jc0;
      const float* FAb=d_FA+(size_t)ndb*FASTRIDE+jc0;
      const float* FBb=d_FB+(size_t)nsb*FASTRIDE+jc0;
      #pragma unroll
      for(int nt=0;nt<8;nt++){
        int col0=nt*8+2*qc;
        float2 faa=*(const float2*)(FAa+col0);
        float2 fba=*(const float2*)(FBa+col0);
        float2 fab=*(const float2*)(FAb+col0);
        float2 fbb=*(const float2*)(FBb+col0);
        float b0=b1b[col0], b1f=b1b[col0+1];
        float w0=wdb[col0], w1v=wdb[col0+1];
        int p0=((col0&3)*18) + (col0>>2);
        s_h[ra*RS+p0]   =tf32r(siluf(c1[nt].x+b0 +da*w0 +faa.x+fba.x));
        s_h[ra*RS+p0+18]=tf32r(siluf(c1[nt].y+b1f+da*w1v+faa.y+fba.y));
        s_h[rb*RS+p0]   =tf32r(siluf(c1[nt].z+b0 +db*w0 +fab.x+fbb.x));
        s_h[rb*RS+p0+18]=tf32r(siluf(c1[nt].w+b1f+db*w1v+fab.y+fbb.y));
      }
    }
    __syncwarp();
    #pragma unroll
    for(int ks=0;ks<8;ks++){
      float2 A0=*(float2*)(s_h+ra*RS+aoff+2*ks);
      float2 A1=*(float2*)(s_h+rb*RS+aoff+2*ks);
      unsigned a0=__float_as_uint(A0.x), a2=__float_as_uint(A0.y);
      unsigned a1=__float_as_uint(A1.x), a3=__float_as_uint(A1.y);
      #pragma unroll
      for(int nt=0;nt<4;nt++){
        float2 Bv=*(float2*)(w2b+(nt*8+qr)*RS+aoff+2*ks);
        mma8(c2[nt],a0,a1,a2,a3,__float_as_uint(Bv.x),__float_as_uint(Bv.y));
      }
    }
  }
  // scalar tail: H1 cols 640, 641
  {
    float p0a=0,p1a=0,p0b=0,p1b=0;
    #pragma unroll
    for(int ks=0;ks<8;ks++){
      int k1=8*ks+qc, k2=k1+4;
      p0a+=eA[ks].x*s_w1t[2*k1]  +eA[ks].y*s_w1t[2*k2];
      p1a+=eA[ks].x*s_w1t[2*k1+1]+eA[ks].y*s_w1t[2*k2+1];
      p0b+=eB[ks].x*s_w1t[2*k1]  +eB[ks].y*s_w1t[2*k2];
      p1b+=eB[ks].x*s_w1t[2*k1+1]+eB[ks].y*s_w1t[2*k2+1];
    }
    #pragma unroll
    for(int o=1;o<4;o<<=1){
      p0a+=__shfl_xor_sync(0xffffffffu,p0a,o); p1a+=__shfl_xor_sync(0xffffffffu,p1a,o);
      p0b+=__shfl_xor_sync(0xffffffffu,p0b,o); p1b+=__shfl_xor_sync(0xffffffffu,p1b,o);
    }
    float h0a=siluf(p0a+s_sc[0]+da*s_sc[2]+d_FA[(size_t)nda*FASTRIDE+640]+d_FB[(size_t)nsa*FASTRIDE+640]);
    float h1a=siluf(p1a+s_sc[1]+da*s_sc[3]+d_FA[(size_t)nda*FASTRIDE+641]+d_FB[(size_t)nsa*FASTRIDE+641]);
    float h0b=siluf(p0b+s_sc[0]+db*s_sc[2]+d_FA[(size_t)ndb*FASTRIDE+640]+d_FB[(size_t)nsb*FASTRIDE+640]);
    float h1b=siluf(p1b+s_sc[1]+db*s_sc[3]+d_FA[(size_t)ndb*FASTRIDE+641]+d_FB[(size_t)nsb*FASTRIDE+641]);
    #pragma unroll
    for(int nt=0;nt<4;nt++){
      int col0=nt*8+2*qc;
      c2[nt].x += h0a*s_w2t[col0]  +h1a*s_w2t[32+col0];
      c2[nt].y += h0a*s_w2t[col0+1]+h1a*s_w2t[32+col0+1];
      c2[nt].z += h0b*s_w2t[col0]  +h1b*s_w2t[32+col0];
      c2[nt].w += h0b*s_w2t[col0+1]+h1b*s_w2t[32+col0+1];
    }
  }
  float va[8], vb[8];
  #pragma unroll
  for(int nt=0;nt<4;nt++){
    int col0=nt*8+2*qc;
    va[2*nt]  =siluf(c2[nt].x+s_b2[col0]);
    va[2*nt+1]=siluf(c2[nt].y+s_b2[col0+1]);
    vb[2*nt]  =siluf(c2[nt].z+s_b2[col0]);
    vb[2*nt+1]=siluf(c2[nt].w+s_b2[col0+1]);
  }
  float sa=0.f,ssa=0.f,sb=0.f,ssb=0.f;
  #pragma unroll
  for(int i=0;i<8;i++){ sa+=va[i]; ssa+=va[i]*va[i]; sb+=vb[i]; ssb+=vb[i]*vb[i]; }
  #pragma unroll
  for(int o=1;o<4;o<<=1){
    sa+=__shfl_xor_sync(0xffffffffu,sa,o); ssa+=__shfl_xor_sync(0xffffffffu,ssa,o);
    sb+=__shfl_xor_sync(0xffffffffu,sb,o); ssb+=__shfl_xor_sync(0xffffffffu,ssb,o);
  }
  float mua=sa*(1.f/MM), vara=ssa*(1.f/MM)-mua*mua, inva=rsqrtf(vara+1e-5f);
  float mub=sb*(1.f/MM), varb=ssb*(1.f/MM)-mub*mub, invb=rsqrtf(varb+1e-5f);
  float* pa=&d_mij[(size_t)(e0+ra)*MM];
  float* pb=&d_mij[(size_t)(e0+rb)*MM];
  #pragma unroll
  for(int nt=0;nt<4;nt++){
    int col0=nt*8+2*qc;
    *(float2*)(pa+col0)=make_float2((va[2*nt]  -mua)*inva*s_g[col0]  +s_bt[col0],
                                    (va[2*nt+1]-mua)*inva*s_g[col0+1]+s_bt[col0+1]);
    *(float2*)(pb+col0)=make_float2((vb[2*nt]  -mub)*invb*s_g[col0]  +s_bt[col0],
                                    (vb[2*nt+1]-mub)*invb*s_g[col0+1]+s_bt[col0+1]);
  }
}

// xcat: LN(feats) | LN(segment-mean of d_mij)
__global__ void k_xcat(const float* __restrict__ keng,const float* __restrict__ kenb,
                       const float* __restrict__ kn1g,const float* __restrict__ kn1b,int k){
  int warp=threadIdx.x>>5, lane=threadIdx.x&31;
  int n=blockIdx.x*8+warp;
  const float* g1=kn1g+(size_t)k*128; const float* b1=kn1b+(size_t)k*128;
  float v[4],s=0.f,ss=0.f;
  #pragma unroll
  for(int i=0;i<4;i++){ float x=d_feats[(size_t)n*128+lane+32*i]; v[i]=x; s+=x; ss+=x*x; }
  #pragma unroll
  for(int o=16;o;o>>=1){ s+=__shfl_xor_sync(0xffffffffu,s,o); ss+=__shfl_xor_sync(0xffffffffu,ss,o); }
  float mu=s*(1.f/128), var=ss*(1.f/128)-mu*mu, inv=rsqrtf(var+1e-5f);
  #pragma unroll
  for(int i=0;i<4;i++){ int c=lane+32*i; d_xcat[(size_t)n*160+c]=(v[i]-mu)*inv*g1[c]+b1[c]; }
  int base=d_base[n], deg=d_hist[n];
  float m=0.f;
  for(int e=base;e<base+deg;e++) m+=d_mij[(size_t)e*MM+lane];
  m/=fmaxf((float)deg,1.f);
  float s2=m, ss2=m*m;
  #pragma unroll
  for(int o=16;o;o>>=1){ s2+=__shfl_xor_sync(0xffffffffu,s2,o); ss2+=__shfl_xor_sync(0xffffffffu,ss2,o); }
  float mu2=s2*(1.f/MM), var2=ss2*(1.f/MM)-mu2*mu2, inv2=rsqrtf(var2+1e-5f);
  d_xcat[(size_t)n*160+128+lane]=(m-mu2)*inv2*keng[k*MM+lane]+kenb[k*MM+lane];
}

__global__ void __launch_bounds__(256) k_node(const float* __restrict__ knW1,const float* __restrict__ knb1,
    const float* __restrict__ knW2,const float* __restrict__ knb2,
    const float* __restrict__ kn2g,const float* __restrict__ kn2b,int k){
  extern __shared__ float sm[];
  float* s_x=sm;
  float* s_h=s_x+10304;
  float* s_w=s_h+16448;
  int tid=threadIdx.x;
  int n0=blockIdx.x*64;
  const float* W1=knW1+(size_t)k*160*256;
  const float* B1=knb1+(size_t)k*256;
  const float* W2=knW2+(size_t)k*256*128;
  const float* B2=knb2+(size_t)k*128;
  const float* G =kn2g+(size_t)k*128;
  const float* BT=kn2b+(size_t)k*128;
  for(int i=tid;i<64*160;i+=256){int r=i/160,c=i-r*160;int n=n0+r; s_x[r*161+c]= (n<NN)? d_xcat[(size_t)n*160+c]:0.f;}
  int r0=(tid>>4)*4, c0=(tid&15)*4;
  for(int oc=0;oc<4;oc++){
    __syncthreads();
    for(int i=tid;i<160*64;i+=256){int p=i>>6,c=i&63; s_w[i]=W1[(size_t)p*256+oc*64+c];}
    __syncthreads();
    float a4[4][4];
    #pragma unroll
    for(int i=0;i<4;i++){a4[i][0]=0;a4[i][1]=0;a4[i][2]=0;a4[i][3]=0;}
    for(int p=0;p<160;p++){
      float4 w=*(float4*)(s_w+p*64+c0);
      #pragma unroll
      for(int i=0;i<4;i++){ float a=s_x[(r0+i)*161+p];
        a4[i][0]+=a*w.x; a4[i][1]+=a*w.y; a4[i][2]+=a*w.z; a4[i][3]+=a*w.w; }
    }
    #pragma unroll
    for(int i=0;i<4;i++){
      #pragma unroll
      for(int j=0;j<4;j++){ int col=oc*64+c0+j;
        s_h[(r0+i)*257+col]=siluf(a4[i][j]+__ldg(&B1[col])); }
    }
  }
  __syncthreads();
  for(int oc=0;oc<2;oc++){
    if(oc) __syncthreads();
    for(int i=tid;i<256*64;i+=256){int p=i>>6,c=i&63; s_w[i]=W2[(size_t)p*128+oc*64+c];}
    __syncthreads();
    float a4[4][4];
    #pragma unroll
    for(int i=0;i<4;i++){a4[i][0]=0;a4[i][1]=0;a4[i][2]=0;a4[i][3]=0;}
    for(int p=0;p<256;p++){
      float4 w=*(float4*)(s_w+p*64+c0);
      #pragma unroll
      for(int i=0;i<4;i++){ float a=s_h[(r0+i)*257+p];
        a4[i][0]+=a*w.x; a4[i][1]+=a*w.y; a4[i][2]+=a*w.z; a4[i][3]+=a*w.w; }
    }
    #pragma unroll
    for(int i=0;i<4;i++){
      #pragma unroll
      for(int j=0;j<4;j++){ int col=oc*64+c0+j;
        s_x[(r0+i)*129+col]=a4[i][j]+__ldg(&B2[col]); }
    }
  }
  __syncthreads();
  int w=tid>>5, lane=tid&31;
  for(int rr=w; rr<64; rr+=8){
    int n=n0+rr;
    float v[4],s=0.f,ss=0.f;
    #pragma unroll
    for(int i=0;i<4;i++){ float x=s_x[rr*129+lane+32*i]; v[i]=x; s+=x; ss+=x*x; }
    #pragma unroll
    for(int o=16;o;o>>=1){ s+=__shfl_xor_sync(0xffffffffu,s,o); ss+=__shfl_xor_sync(0xffffffffu,ss,o); }
    float mu=s*(1.f/128), var=ss*(1.f/128)-mu*mu, inv=rsqrtf(var+1e-5f);
    if(n<NN){
      #pragma unroll
      for(int i=0;i<4;i++){ int c=lane+32*i;
        float nv=(v[i]-mu)*inv*G[c]+BT[c];
        float f=d_feats[(size_t)n*128+c]+nv;
        d_feats[(size_t)n*128+c]=f;
        d_fcat[(size_t)n*FH+(size_t)(k+1)*128+c]=f; }
    }
  }
}

__global__ void k_pool(const int* __restrict__ batch){
  int n=blockIdx.x; int c=threadIdx.x;
  int b=batch[n];
  atomicAdd(&d_gsum[b*F2+c], d_f1[(size_t)n*F2+c]);
  if(c==0) atomicAdd(&d_gcnt[b],1.f);
}

__global__ void k_final(const float* __restrict__ gW0,const float* __restrict__ gb0,
                        const float* __restrict__ gW1,const float* __restrict__ gb1,
                        const float* __restrict__ gW2,const float* __restrict__ gb2,
                        float* __restrict__ out){
  __shared__ float s_g[256], s_h[256], s_red[8];
  int b=blockIdx.x, t=threadIdx.x;
  float cnt=fmaxf(d_gcnt[b],1.f);
  s_g[t]=d_gsum[b*F2+t]/cnt;
  __syncthreads();
  float a=gb0[t];
  #pragma unroll 8
  for(int p=0;p<256;p++) a+=s_g[p]*gW0[p*256+t];
  s_h[t]=siluf(a);
  __syncthreads();
  a=gb1[t];
  #pragma unroll 8
  for(int p=0;p<256;p++) a+=s_h[p]*gW1[p*256+t];
  float h=siluf(a);
  float v=h*gW2[t];
  #pragma unroll
  for(int o=16;o;o>>=1) v+=__shfl_xor_sync(0xffffffffu,v,o);
  if((t&31)==0) s_red[t>>5]=v;
  __syncthreads();
  if(t==0){ float tot=0.f;
    #pragma unroll
    for(int i=0;i<8;i++) tot+=s_red[i];
    out[b]=tot+gb2[0]; }
}

extern "C" void kernel_launch(void* const* d_in, const int* in_sizes, int n_in,
                              void* d_out, int out_size){
  const float* coords =(const float*)d_in[0];
  const int*   atomids=(const int*)d_in[1];
  const int*   eidx   =(const int*)d_in[2];
  const int*   batch  =(const int*)d_in[3];
  int s = (in_sizes[4]==11*DD) ? 4 : 5;
  const float* emb =(const float*)d_in[s+0];
  const float* keW1=(const float*)d_in[s+1];
  const float* keb1=(const float*)d_in[s+2];
  const float* keW2=(const float*)d_in[s+3];
  const float* keb2=(const float*)d_in[s+4];
  const float* keng=(const float*)d_in[s+5];
  const float* kenb=(const float*)d_in[s+6];
  const float* kn1g=(const float*)d_in[s+7];
  const float* kn1b=(const float*)d_in[s+8];
  const float* knW1=(const float*)d_in[s+9];
  const float* knb1=(const float*)d_in[s+10];
  const float* knW2=(const float*)d_in[s+11];
  const float* knb2=(const float*)d_in[s+12];
  const float* kn2g=(const float*)d_in[s+13];
  const float* kn2b=(const float*)d_in[s+14];
  const float* fW0 =(const float*)d_in[s+15];
  const float* fb0 =(const float*)d_in[s+16];
  const float* fW1 =(const float*)d_in[s+17];
  const float* fb1 =(const float*)d_in[s+18];
  const float* fW2 =(const float*)d_in[s+19];
  const float* fb2 =(const float*)d_in[s+20];
  const float* gW0 =(const float*)d_in[s+21];
  const float* gb0 =(const float*)d_in[s+22];
  const float* gW1 =(const float*)d_in[s+23];
  const float* gb1 =(const float*)d_in[s+24];
  const float* gW2 =(const float*)d_in[s+25];
  const float* gb2 =(const float*)d_in[s+26];
  float* out=(float*)d_out;

  const int EDGE_SM = 23592*4;                 // 94368
  const int NODE_SM = (10304+16448+16384)*4;   // 172544
  const int FNN_SM  = (128*RS + 2*64*RS)*4;    // 73728
  const int EA_SM   = 256*RS*4;                // 73728
  cudaFuncSetAttribute(k_edge,    cudaFuncAttributeMaxDynamicSharedMemorySize, EDGE_SM);
  cudaFuncSetAttribute(k_node,    cudaFuncAttributeMaxDynamicSharedMemorySize, NODE_SM);
  cudaFuncSetAttribute(k_fab_mma, cudaFuncAttributeMaxDynamicSharedMemorySize, FNN_SM);
  cudaFuncSetAttribute(k_fnn_mma, cudaFuncAttributeMaxDynamicSharedMemorySize, FNN_SM);
  cudaFuncSetAttribute(k_ea,      cudaFuncAttributeMaxDynamicSharedMemorySize, EA_SM);

  k_zero_init<<<65,256>>>();
  k_hist<<<EE/256,256>>>(eidx);
  k_scan<<<1,1024>>>();
  k_scatter<<<EE/256,256>>>(eidx);
  k_feats<<<NN,128>>>(emb,atomids);
  k_ea<<<EE/256,256,EA_SM>>>(coords);
  k_wprep<<<1320,256>>>(keW1,keW2);
  k_wprep_fab<<<3840,256>>>(keW1);
  k_wprep_fnn<<<1280,256>>>(fW0,fW1,fW2);
  for(int k=0;k<KK;k++){
    k_fab_mma<<<dim3(6,79,2),256,FNN_SM>>>(k);
    k_edge<<<EE/128,256,EDGE_SM>>>(keW1,keb1,keW2,keb2,keng,kenb,k);
    k_xcat<<<NN/8,256>>>(keng,kenb,kn1g,kn1b,k);
    k_node<<<157,256,NODE_SM>>>(knW1,knb1,knW2,knb2,kn2g,kn2b,k);
  }
  k_fnn_mma<<<dim3(2,79),256,FNN_SM>>>(fb0, 0);
  k_fnn_mma<<<dim3(2,79),256,FNN_SM>>>(fb1, 1);
  k_fnn_mma<<<dim3(2,79),256,FNN_SM>>>(fb2, 2);
  k_pool<<<NN,256>>>(batch);
  k_final<<<BB,256>>>(gW0,gb0,gW1,gb1,gW2,gb2,out);
}